// round 1
// baseline (speedup 1.0000x reference)
#include <cuda_runtime.h>
#include <math.h>

// ---------------------------------------------------------------------------
// Problem constants (fixed by setup_inputs)
// ---------------------------------------------------------------------------
constexpr int B_  = 2;
constexpr int NQ  = 2048;
constexpr int NC  = 4096;
constexpr int CE  = 512;    // n_embd
constexpr int H_  = 8;
constexpr int D_  = 64;     // head dim
constexpr float SCALE   = 0.125f;   // 1/sqrt(64)
constexpr float FOURNU  = 0.4f;     // 4 * NU_BAR
constexpr float EPS_    = 1e-6f;

// ---------------------------------------------------------------------------
// Scratch (device globals: allocation-free)
// ---------------------------------------------------------------------------
__device__ float g_q[B_ * NQ * CE];   // 8 MB
__device__ float g_k[B_ * NC * CE];   // 16 MB
__device__ float g_v[B_ * NC * CE];   // 16 MB
__device__ float g_y[B_ * NQ * CE];   // 8 MB

// ---------------------------------------------------------------------------
// GEMM:  Y[M,512] = X[M,512] @ W[512,512]^T + bias   (torch Linear)
// 128x64 block tile, BK=16, 256 threads, 8x4 register tile.
// ---------------------------------------------------------------------------
__global__ __launch_bounds__(256)
void gemm_bias_kernel(const float* __restrict__ X, const float* __restrict__ W,
                      const float* __restrict__ bias, float* __restrict__ Y) {
    constexpr int GK = 512, BM = 128, BN = 64, BK = 16;
    __shared__ float Xs[BK][BM];   // k-major
    __shared__ float Ws[BK][BN];   // k-major

    const int tid = threadIdx.x;
    const int tx  = tid & 15;      // 0..15 -> 4 output cols
    const int ty  = tid >> 4;      // 0..15 -> 8 output rows
    const int rowBase = blockIdx.y * BM;
    const int colBase = blockIdx.x * BN;

    float acc[8][4];
    #pragma unroll
    for (int i = 0; i < 8; i++)
        #pragma unroll
        for (int j = 0; j < 4; j++) acc[i][j] = 0.f;

    for (int k0 = 0; k0 < GK; k0 += BK) {
        // X tile: 128x16 = 512 float4, 2 per thread
        #pragma unroll
        for (int t = 0; t < 2; t++) {
            int idx = tid + t * 256;           // 0..511
            int r   = idx >> 2;                // 0..127
            int c4  = (idx & 3) << 2;          // 0,4,8,12
            float4 v = *(const float4*)&X[(size_t)(rowBase + r) * GK + k0 + c4];
            Xs[c4 + 0][r] = v.x; Xs[c4 + 1][r] = v.y;
            Xs[c4 + 2][r] = v.z; Xs[c4 + 3][r] = v.w;
        }
        // W tile: 64x16 = 256 float4, 1 per thread
        {
            int r  = tid >> 2;                 // 0..63
            int c4 = (tid & 3) << 2;
            float4 v = *(const float4*)&W[(size_t)(colBase + r) * GK + k0 + c4];
            Ws[c4 + 0][r] = v.x; Ws[c4 + 1][r] = v.y;
            Ws[c4 + 2][r] = v.z; Ws[c4 + 3][r] = v.w;
        }
        __syncthreads();

        #pragma unroll
        for (int kk = 0; kk < BK; kk++) {
            float4 x0 = *(const float4*)&Xs[kk][ty * 8];
            float4 x1 = *(const float4*)&Xs[kk][ty * 8 + 4];
            float4 w0 = *(const float4*)&Ws[kk][tx * 4];
            float xr[8] = {x0.x, x0.y, x0.z, x0.w, x1.x, x1.y, x1.z, x1.w};
            float wr[4] = {w0.x, w0.y, w0.z, w0.w};
            #pragma unroll
            for (int i = 0; i < 8; i++)
                #pragma unroll
                for (int j = 0; j < 4; j++)
                    acc[i][j] = fmaf(xr[i], wr[j], acc[i][j]);
        }
        __syncthreads();
    }

    float4 bv = *(const float4*)&bias[colBase + tx * 4];
    float  br[4] = {bv.x, bv.y, bv.z, bv.w};
    #pragma unroll
    for (int i = 0; i < 8; i++) {
        int row = rowBase + ty * 8 + i;
        float4 o;
        o.x = acc[i][0] + br[0]; o.y = acc[i][1] + br[1];
        o.z = acc[i][2] + br[2]; o.w = acc[i][3] + br[3];
        *(float4*)&Y[(size_t)row * GK + colBase + tx * 4] = o;
    }
}

// ---------------------------------------------------------------------------
// Flash attention with heat-kernel bias.
// Block = (b, h, 64-query tile); 256 threads as 16x16.
// Thread (ty,tx): score phase -> S[ty*4..+4][tx*4..+4]
//                 AV phase    -> O[ty*4..+4][d = tx*4..+4]
// ---------------------------------------------------------------------------
struct AttnSmem {
    float Qst[D_][64];     // d-major (transposed), pre-scaled Q
    float Kst[D_][64];     // d-major (transposed)
    float Vs[64][D_];      // row-major
    float S[64][68];       // padded score/prob tile
    float pq[64][4];       // x, y, t
    float pc[64][4];
};

__global__ __launch_bounds__(256)
void attn_kernel(const float* __restrict__ q, const float* __restrict__ k,
                 const float* __restrict__ v,
                 const float* __restrict__ pos_c, const float* __restrict__ pos_q,
                 float* __restrict__ y) {
    extern __shared__ char smraw[];
    AttnSmem& sm = *reinterpret_cast<AttnSmem*>(smraw);

    const int b  = blockIdx.z;
    const int h  = blockIdx.y;
    const int q0 = blockIdx.x * 64;
    const int tid = threadIdx.x;
    const int tx = tid & 15;
    const int ty = tid >> 4;

    // ---- load Q tile (transposed, pre-scaled) ----
    const float* qb = q + ((size_t)(b * NQ + q0)) * CE + h * D_;
    #pragma unroll
    for (int t = 0; t < 4; t++) {
        int idx = tid + t * 256;          // 0..1023
        int r   = idx >> 4;               // 0..63
        int c4  = (idx & 15) << 2;        // 0..60
        float4 val = *(const float4*)(qb + (size_t)r * CE + c4);
        sm.Qst[c4 + 0][r] = val.x * SCALE;
        sm.Qst[c4 + 1][r] = val.y * SCALE;
        sm.Qst[c4 + 2][r] = val.z * SCALE;
        sm.Qst[c4 + 3][r] = val.w * SCALE;
    }
    if (tid < 64) {
        const float* p = pos_q + (size_t)(b * NQ + q0 + tid) * 3;
        sm.pq[tid][0] = p[0]; sm.pq[tid][1] = p[1]; sm.pq[tid][2] = p[2];
    }

    float acc[4][4];
    #pragma unroll
    for (int i = 0; i < 4; i++)
        #pragma unroll
        for (int j = 0; j < 4; j++) acc[i][j] = 0.f;
    float mrow[4], lrow[4];
    #pragma unroll
    for (int i = 0; i < 4; i++) { mrow[i] = -1e30f; lrow[i] = 0.f; }

    for (int c0 = 0; c0 < NC; c0 += 64) {
        __syncthreads();   // prior AV-phase reads of Vs/S finished
        // ---- load K (transposed), V, pos_c ----
        const float* kb = k + ((size_t)(b * NC + c0)) * CE + h * D_;
        const float* vb = v + ((size_t)(b * NC + c0)) * CE + h * D_;
        #pragma unroll
        for (int t = 0; t < 4; t++) {
            int idx = tid + t * 256;
            int r   = idx >> 4;
            int c4  = (idx & 15) << 2;
            float4 kv = *(const float4*)(kb + (size_t)r * CE + c4);
            sm.Kst[c4 + 0][r] = kv.x; sm.Kst[c4 + 1][r] = kv.y;
            sm.Kst[c4 + 2][r] = kv.z; sm.Kst[c4 + 3][r] = kv.w;
            float4 vv = *(const float4*)(vb + (size_t)r * CE + c4);
            *(float4*)&sm.Vs[r][c4] = vv;
        }
        if (tid < 64) {
            const float* p = pos_c + (size_t)(b * NC + c0 + tid) * 3;
            sm.pc[tid][0] = p[0]; sm.pc[tid][1] = p[1]; sm.pc[tid][2] = p[2];
        }
        __syncthreads();

        // ---- score phase: s = (Q*scale) . K ----
        float s[4][4];
        #pragma unroll
        for (int i = 0; i < 4; i++)
            #pragma unroll
            for (int j = 0; j < 4; j++) s[i][j] = 0.f;
        #pragma unroll 16
        for (int dd = 0; dd < D_; dd++) {
            float4 qv = *(const float4*)&sm.Qst[dd][ty * 4];
            float4 kv = *(const float4*)&sm.Kst[dd][tx * 4];
            float qr[4] = {qv.x, qv.y, qv.z, qv.w};
            float kr[4] = {kv.x, kv.y, kv.z, kv.w};
            #pragma unroll
            for (int i = 0; i < 4; i++)
                #pragma unroll
                for (int j = 0; j < 4; j++)
                    s[i][j] = fmaf(qr[i], kr[j], s[i][j]);
        }

        // ---- heat-kernel bias (ALPHA = 1) ----
        #pragma unroll
        for (int i = 0; i < 4; i++) {
            int qi = ty * 4 + i;
            float qx = sm.pq[qi][0], qy = sm.pq[qi][1], qt = sm.pq[qi][2];
            #pragma unroll
            for (int j = 0; j < 4; j++) {
                int cj = tx * 4 + j;
                float dx = qx - sm.pc[cj][0];
                float dy = qy - sm.pc[cj][1];
                float dt = qt - sm.pc[cj][2];
                float denom = FOURNU * fabsf(dt) + EPS_;
                float dist  = dx * dx + dy * dy;
                s[i][j] += __expf(-__fdividef(dist, denom));
            }
        }

        // ---- online softmax (row reductions across 16-lane groups) ----
        #pragma unroll
        for (int i = 0; i < 4; i++) {
            float mx = fmaxf(fmaxf(s[i][0], s[i][1]), fmaxf(s[i][2], s[i][3]));
            #pragma unroll
            for (int o = 8; o >= 1; o >>= 1)
                mx = fmaxf(mx, __shfl_xor_sync(0xffffffffu, mx, o));
            float mnew = fmaxf(mrow[i], mx);
            float corr = __expf(mrow[i] - mnew);
            float rsum = 0.f;
            int qi = ty * 4 + i;
            #pragma unroll
            for (int j = 0; j < 4; j++) {
                float p = __expf(s[i][j] - mnew);
                sm.S[qi][tx * 4 + j] = p;
                rsum += p;
            }
            #pragma unroll
            for (int o = 8; o >= 1; o >>= 1)
                rsum += __shfl_xor_sync(0xffffffffu, rsum, o);
            lrow[i] = lrow[i] * corr + rsum;
            mrow[i] = mnew;
            #pragma unroll
            for (int j = 0; j < 4; j++) acc[i][j] *= corr;
        }
        __syncthreads();

        // ---- AV phase: O += P @ V ----
        #pragma unroll 8
        for (int cj = 0; cj < 64; cj++) {
            float pr[4];
            #pragma unroll
            for (int i = 0; i < 4; i++) pr[i] = sm.S[ty * 4 + i][cj];
            float4 vv = *(const float4*)&sm.Vs[cj][tx * 4];
            float vr[4] = {vv.x, vv.y, vv.z, vv.w};
            #pragma unroll
            for (int i = 0; i < 4; i++)
                #pragma unroll
                for (int j = 0; j < 4; j++)
                    acc[i][j] = fmaf(pr[i], vr[j], acc[i][j]);
        }
    }

    // ---- normalize & write ----
    float* yb = y + ((size_t)(b * NQ + q0)) * CE + h * D_;
    #pragma unroll
    for (int i = 0; i < 4; i++) {
        float inv = 1.0f / lrow[i];
        float4 o;
        o.x = acc[i][0] * inv; o.y = acc[i][1] * inv;
        o.z = acc[i][2] * inv; o.w = acc[i][3] * inv;
        *(float4*)(yb + (size_t)(ty * 4 + i) * CE + tx * 4) = o;
    }
}

// ---------------------------------------------------------------------------
// Launch
// ---------------------------------------------------------------------------
extern "C" void kernel_launch(void* const* d_in, const int* in_sizes, int n_in,
                              void* d_out, int out_size) {
    (void)in_sizes; (void)n_in; (void)out_size;
    const float* x_ctx    = (const float*)d_in[0];
    const float* x_query  = (const float*)d_in[1];
    const float* pos_ctx  = (const float*)d_in[2];
    const float* pos_query= (const float*)d_in[3];
    const float* Wq = (const float*)d_in[4];
    const float* bq = (const float*)d_in[5];
    const float* Wk = (const float*)d_in[6];
    const float* bk = (const float*)d_in[7];
    const float* Wv = (const float*)d_in[8];
    const float* bv = (const float*)d_in[9];
    const float* Wo = (const float*)d_in[10];
    const float* bo = (const float*)d_in[11];
    float* out = (float*)d_out;

    float *gq, *gk, *gv, *gy;
    cudaGetSymbolAddress((void**)&gq, g_q);
    cudaGetSymbolAddress((void**)&gk, g_k);
    cudaGetSymbolAddress((void**)&gv, g_v);
    cudaGetSymbolAddress((void**)&gy, g_y);

    cudaFuncSetAttribute(attn_kernel,
                         cudaFuncAttributeMaxDynamicSharedMemorySize,
                         (int)sizeof(AttnSmem));

    dim3 thr(256);
    gemm_bias_kernel<<<dim3(CE / 64, (B_ * NQ) / 128), thr>>>(x_query, Wq, bq, gq);
    gemm_bias_kernel<<<dim3(CE / 64, (B_ * NC) / 128), thr>>>(x_ctx,   Wk, bk, gk);
    gemm_bias_kernel<<<dim3(CE / 64, (B_ * NC) / 128), thr>>>(x_ctx,   Wv, bv, gv);
    attn_kernel<<<dim3(NQ / 64, H_, B_), thr, sizeof(AttnSmem)>>>(
        gq, gk, gv, pos_ctx, pos_query, gy);
    gemm_bias_kernel<<<dim3(CE / 64, (B_ * NQ) / 128), thr>>>(gy, Wo, bo, out);
}

// round 3
// speedup vs baseline: 1.3764x; 1.3764x over previous
#include <cuda_runtime.h>
#include <cstdint>
#include <math.h>

// ---------------------------------------------------------------------------
// Problem constants
// ---------------------------------------------------------------------------
constexpr int B_  = 2;
constexpr int NQ  = 2048;
constexpr int NC  = 4096;
constexpr int CE  = 512;
constexpr int H_  = 8;
constexpr int D_  = 64;
constexpr float SCALE  = 0.125f;
constexpr float FOURNU = 0.4f;
constexpr float EPS_   = 1e-6f;

// ---------------------------------------------------------------------------
// Scratch (device globals: allocation-free)
// ---------------------------------------------------------------------------
__device__ float g_q [B_ * NQ * CE];             // 8 MB   (row-major proj out)
__device__ float g_k [B_ * NC * CE];             // 16 MB
__device__ float g_v [B_ * NC * CE];             // 16 MB
__device__ float g_qT[B_ * NQ * CE];             // 8 MB   [b][h][d][q]
__device__ float g_kT[B_ * NC * CE];             // 16 MB  [b][h][d][c]
__device__ float g_y [B_ * NQ * CE];             // 8 MB
__device__ float g_heat[(size_t)B_ * NQ * NC];   // 67 MB  [b][q][c]

// ---------------------------------------------------------------------------
// tf32 helpers
// ---------------------------------------------------------------------------
__device__ __forceinline__ uint32_t f2tf32(float f) {
    uint32_t r;
    asm("cvt.rna.tf32.f32 %0, %1;" : "=r"(r) : "f"(f));
    return r;
}
__device__ __forceinline__ void split_tf32(float f, uint32_t& hi, uint32_t& lo) {
    hi = f2tf32(f);
    lo = f2tf32(f - __uint_as_float(hi));
}
#define MMA_TF32(d, a, b) \
    asm volatile("mma.sync.aligned.m16n8k8.row.col.f32.tf32.tf32.f32 " \
        "{%0,%1,%2,%3}, {%4,%5,%6,%7}, {%8,%9}, {%0,%1,%2,%3};" \
        : "+f"((d)[0]), "+f"((d)[1]), "+f"((d)[2]), "+f"((d)[3]) \
        : "r"((a)[0]), "r"((a)[1]), "r"((a)[2]), "r"((a)[3]), \
          "r"((b)[0]), "r"((b)[1]))

// ---------------------------------------------------------------------------
// Heat-kernel bias precompute (head-independent)
// ---------------------------------------------------------------------------
__global__ __launch_bounds__(256)
void heat_precompute(const float* __restrict__ pos_c, const float* __restrict__ pos_q,
                     float* __restrict__ heat) {
    const int b  = blockIdx.y;
    const int qi = blockIdx.x;
    const float* pq = pos_q + (size_t)(b * NQ + qi) * 3;
    const float qx = pq[0], qy = pq[1], qt = pq[2];
    float* hrow = heat + ((size_t)b * NQ + qi) * NC;
    for (int ci = threadIdx.x; ci < NC; ci += 256) {
        const float* pc = pos_c + (size_t)(b * NC + ci) * 3;
        float dx = qx - pc[0];
        float dy = qy - pc[1];
        float dt = qt - pc[2];
        float denom = FOURNU * fabsf(dt) + EPS_;
        float dist  = dx * dx + dy * dy;
        hrow[ci] = __expf(-__fdividef(dist, denom));
    }
}

// ---------------------------------------------------------------------------
// Per-head transpose: in[b*Nrows + r][512] (col h*64+d)  ->  out[(b*H+h)*64+d][Nrows]
// ---------------------------------------------------------------------------
__global__ __launch_bounds__(256)
void transpose_head(const float* __restrict__ in, float* __restrict__ out, int Nrows) {
    __shared__ float ts[64][65];
    const int b  = blockIdx.z;
    const int h  = blockIdx.y;
    const int r0 = blockIdx.x * 64;
    const int tid = threadIdx.x;
    #pragma unroll
    for (int t = 0; t < 4; ++t) {
        int idx = tid + t * 256;
        int r   = idx >> 4;
        int d4  = (idx & 15) << 2;
        float4 v = *(const float4*)&in[(size_t)(b * Nrows + r0 + r) * 512 + h * 64 + d4];
        ts[d4 + 0][r] = v.x; ts[d4 + 1][r] = v.y;
        ts[d4 + 2][r] = v.z; ts[d4 + 3][r] = v.w;
    }
    __syncthreads();
    #pragma unroll
    for (int t = 0; t < 4; ++t) {
        int idx = tid + t * 256;
        int d   = idx >> 4;
        int r4  = (idx & 15) << 2;
        float4 o = make_float4(ts[d][r4], ts[d][r4 + 1], ts[d][r4 + 2], ts[d][r4 + 3]);
        *(float4*)&out[((size_t)(b * H_ + h) * 64 + d) * Nrows + r0 + r4] = o;
    }
}

// ---------------------------------------------------------------------------
// GEMM via mma.sync tf32 x3-split:  Y[M,512] = X[M,512] @ W[512,512]^T + bias
// CTA 128x128, BK=32, 256 threads (8 warps as 4M x 2N, warp tile 32x64).
// ---------------------------------------------------------------------------
__global__ __launch_bounds__(256, 1)
void gemm_tc(const float* __restrict__ X, const float* __restrict__ W,
             const float* __restrict__ bias, float* __restrict__ Y) {
    __shared__ float As[32 * 132];   // [k][m]
    __shared__ float Bs[32 * 132];   // [k][n]

    const int tid  = threadIdx.x;
    const int lane = tid & 31;
    const int wid  = tid >> 5;
    const int grp  = lane >> 2;
    const int tig  = lane & 3;
    const int wm   = (wid >> 1) * 32;
    const int wn   = (wid & 1) * 64;
    const int rowBase = blockIdx.y * 128;
    const int colBase = blockIdx.x * 128;

    float acc[2][8][4];
    #pragma unroll
    for (int mt = 0; mt < 2; ++mt)
        #pragma unroll
        for (int nt = 0; nt < 8; ++nt)
            #pragma unroll
            for (int r = 0; r < 4; ++r) acc[mt][nt][r] = 0.f;

    float4 xs[4], ws[4];
    // preload chunk 0
    #pragma unroll
    for (int t = 0; t < 4; ++t) {
        int idx = tid + t * 256;
        int r   = idx >> 3;
        int k4  = (idx & 7) << 2;
        xs[t] = *(const float4*)&X[(size_t)(rowBase + r) * 512 + k4];
        ws[t] = *(const float4*)&W[(size_t)(colBase + r) * 512 + k4];
    }

    for (int c = 0; c < 16; ++c) {
        __syncthreads();
        #pragma unroll
        for (int t = 0; t < 4; ++t) {
            int idx = tid + t * 256;
            int r   = idx >> 3;
            int k4  = (idx & 7) << 2;
            As[(k4 + 0) * 132 + r] = xs[t].x;
            As[(k4 + 1) * 132 + r] = xs[t].y;
            As[(k4 + 2) * 132 + r] = xs[t].z;
            As[(k4 + 3) * 132 + r] = xs[t].w;
            Bs[(k4 + 0) * 132 + r] = ws[t].x;
            Bs[(k4 + 1) * 132 + r] = ws[t].y;
            Bs[(k4 + 2) * 132 + r] = ws[t].z;
            Bs[(k4 + 3) * 132 + r] = ws[t].w;
        }
        __syncthreads();
        if (c < 15) {
            int k0 = (c + 1) * 32;
            #pragma unroll
            for (int t = 0; t < 4; ++t) {
                int idx = tid + t * 256;
                int r   = idx >> 3;
                int k4  = (idx & 7) << 2;
                xs[t] = *(const float4*)&X[(size_t)(rowBase + r) * 512 + k0 + k4];
                ws[t] = *(const float4*)&W[(size_t)(colBase + r) * 512 + k0 + k4];
            }
        }
        #pragma unroll
        for (int ks = 0; ks < 4; ++ks) {
            const int k8 = ks * 8;
            uint32_t ah[2][4], al[2][4];
            #pragma unroll
            for (int mt = 0; mt < 2; ++mt) {
                int r0 = wm + mt * 16 + grp;
                split_tf32(As[(k8 + tig)     * 132 + r0],     ah[mt][0], al[mt][0]);
                split_tf32(As[(k8 + tig)     * 132 + r0 + 8], ah[mt][1], al[mt][1]);
                split_tf32(As[(k8 + tig + 4) * 132 + r0],     ah[mt][2], al[mt][2]);
                split_tf32(As[(k8 + tig + 4) * 132 + r0 + 8], ah[mt][3], al[mt][3]);
            }
            uint32_t bh[8][2], bl[8][2];
            #pragma unroll
            for (int nt = 0; nt < 8; ++nt) {
                int n = wn + nt * 8 + grp;
                split_tf32(Bs[(k8 + tig)     * 132 + n], bh[nt][0], bl[nt][0]);
                split_tf32(Bs[(k8 + tig + 4) * 132 + n], bh[nt][1], bl[nt][1]);
            }
            #pragma unroll
            for (int mt = 0; mt < 2; ++mt)
                #pragma unroll
                for (int nt = 0; nt < 8; ++nt) {
                    MMA_TF32(acc[mt][nt], ah[mt], bh[nt]);
                    MMA_TF32(acc[mt][nt], ah[mt], bl[nt]);
                    MMA_TF32(acc[mt][nt], al[mt], bh[nt]);
                }
        }
    }

    #pragma unroll
    for (int nt = 0; nt < 8; ++nt) {
        int col = colBase + wn + nt * 8 + tig * 2;
        float b0 = __ldg(&bias[col]);
        float b1 = __ldg(&bias[col + 1]);
        #pragma unroll
        for (int mt = 0; mt < 2; ++mt) {
            int row = rowBase + wm + mt * 16 + grp;
            float2 o0 = make_float2(acc[mt][nt][0] + b0, acc[mt][nt][1] + b1);
            float2 o1 = make_float2(acc[mt][nt][2] + b0, acc[mt][nt][3] + b1);
            *(float2*)&Y[(size_t)row       * 512 + col] = o0;
            *(float2*)&Y[(size_t)(row + 8) * 512 + col] = o1;
        }
    }
}

// ---------------------------------------------------------------------------
// Flash attention, fp32 FFMA, 128q x 128c tiles, 512 threads.
// Q^T/K^T inputs (d-major) -> all smem accesses conflict-free.
// Thread (ty in [0,32), tx in [0,16)):
//   score rows ty*4..+4, cols {tx*4..+4, 64+tx*4..+4}
//   AV    rows ty*4..+4, d-cols tx*4..+4
// ---------------------------------------------------------------------------
constexpr int AQ = 0;                 // Qs[64][128]
constexpr int AK = AQ + 64 * 128;     // Ks[64][128]
constexpr int AV = AK + 64 * 128;     // Vs[128][68]
constexpr int AS = AV + 128 * 68;     // S[128][132]
constexpr int AF = AS + 128 * 132;
constexpr int ATTN_SMEM = AF * 4;     // 167936 B

__global__ __launch_bounds__(512, 1)
void attn_kernel(const float* __restrict__ qT, const float* __restrict__ kT,
                 const float* __restrict__ v, const float* __restrict__ heat,
                 float* __restrict__ y) {
    extern __shared__ float sm[];
    float* Qs = sm + AQ;
    float* Ks = sm + AK;
    float* Vs = sm + AV;
    float* S  = sm + AS;

    const int b  = blockIdx.z;
    const int h  = blockIdx.y;
    const int q0 = blockIdx.x * 128;
    const int tid = threadIdx.x;
    const int tx = tid & 15;
    const int ty = tid >> 4;

    // Q tile (d-major, pre-scaled)
    const float* qTb = qT + ((size_t)(b * H_ + h) * 64) * NQ + q0;
    #pragma unroll
    for (int t = 0; t < 4; ++t) {
        int idx = tid + t * 512;
        int d   = idx >> 5;
        int c4  = (idx & 31) << 2;
        float4 val = *(const float4*)(qTb + (size_t)d * NQ + c4);
        val.x *= SCALE; val.y *= SCALE; val.z *= SCALE; val.w *= SCALE;
        *(float4*)&Qs[d * 128 + c4] = val;
    }

    float acc[4][4];
    float mrow[4], lrow[4];
    #pragma unroll
    for (int i = 0; i < 4; ++i) {
        mrow[i] = -1e30f; lrow[i] = 0.f;
        #pragma unroll
        for (int j = 0; j < 4; ++j) acc[i][j] = 0.f;
    }

    const float* kTb = kT + ((size_t)(b * H_ + h) * 64) * NC;
    const float* vb0 = v + ((size_t)b * NC) * CE + h * 64;
    const float* hbase = heat + ((size_t)b * NQ + q0) * NC;

    for (int c0 = 0; c0 < NC; c0 += 128) {
        __syncthreads();
        // K tile (d-major) + V tile (row-major)
        #pragma unroll
        for (int t = 0; t < 4; ++t) {
            int idx = tid + t * 512;
            int d   = idx >> 5;
            int c4  = (idx & 31) << 2;
            *(float4*)&Ks[d * 128 + c4] =
                *(const float4*)(kTb + (size_t)d * NC + c0 + c4);
            int r   = idx >> 4;
            int d4  = (idx & 15) << 2;
            *(float4*)&Vs[r * 68 + d4] =
                *(const float4*)(vb0 + (size_t)(c0 + r) * CE + d4);
        }
        __syncthreads();

        // ---- score: s[4][8] ----
        float s[4][8];
        #pragma unroll
        for (int i = 0; i < 4; ++i)
            #pragma unroll
            for (int j = 0; j < 8; ++j) s[i][j] = 0.f;
        #pragma unroll 8
        for (int dd = 0; dd < 64; ++dd) {
            float4 qv = *(const float4*)&Qs[dd * 128 + ty * 4];
            float4 ka = *(const float4*)&Ks[dd * 128 + tx * 4];
            float4 kb = *(const float4*)&Ks[dd * 128 + 64 + tx * 4];
            float qr[4] = {qv.x, qv.y, qv.z, qv.w};
            float kr[8] = {ka.x, ka.y, ka.z, ka.w, kb.x, kb.y, kb.z, kb.w};
            #pragma unroll
            for (int i = 0; i < 4; ++i)
                #pragma unroll
                for (int j = 0; j < 8; ++j)
                    s[i][j] = fmaf(qr[i], kr[j], s[i][j]);
        }

        // ---- heat bias ----
        #pragma unroll
        for (int i = 0; i < 4; ++i) {
            const float* hr = hbase + (size_t)(ty * 4 + i) * NC + c0;
            float4 h0 = *(const float4*)(hr + tx * 4);
            float4 h1 = *(const float4*)(hr + 64 + tx * 4);
            s[i][0] += h0.x; s[i][1] += h0.y; s[i][2] += h0.z; s[i][3] += h0.w;
            s[i][4] += h1.x; s[i][5] += h1.y; s[i][6] += h1.z; s[i][7] += h1.w;
        }

        // ---- online softmax (rows owned by 16-lane tx groups) ----
        #pragma unroll
        for (int i = 0; i < 4; ++i) {
            float mx = s[i][0];
            #pragma unroll
            for (int j = 1; j < 8; ++j) mx = fmaxf(mx, s[i][j]);
            #pragma unroll
            for (int o = 8; o >= 1; o >>= 1)
                mx = fmaxf(mx, __shfl_xor_sync(0xffffffffu, mx, o));
            float mnew = fmaxf(mrow[i], mx);
            float corr = __expf(mrow[i] - mnew);
            float p[8];
            float rsum = 0.f;
            #pragma unroll
            for (int j = 0; j < 8; ++j) { p[j] = __expf(s[i][j] - mnew); rsum += p[j]; }
            float* srow = &S[(ty * 4 + i) * 132];
            *(float4*)(srow + tx * 4)      = make_float4(p[0], p[1], p[2], p[3]);
            *(float4*)(srow + 64 + tx * 4) = make_float4(p[4], p[5], p[6], p[7]);
            #pragma unroll
            for (int o = 8; o >= 1; o >>= 1)
                rsum += __shfl_xor_sync(0xffffffffu, rsum, o);
            lrow[i] = lrow[i] * corr + rsum;
            mrow[i] = mnew;
            #pragma unroll
            for (int j = 0; j < 4; ++j) acc[i][j] *= corr;
        }
        __syncthreads();

        // ---- AV: O += P @ V ----
        #pragma unroll 4
        for (int cj = 0; cj < 128; cj += 4) {
            float4 v0 = *(const float4*)&Vs[(cj + 0) * 68 + tx * 4];
            float4 v1 = *(const float4*)&Vs[(cj + 1) * 68 + tx * 4];
            float4 v2 = *(const float4*)&Vs[(cj + 2) * 68 + tx * 4];
            float4 v3 = *(const float4*)&Vs[(cj + 3) * 68 + tx * 4];
            #pragma unroll
            for (int i = 0; i < 4; ++i) {
                float4 p4 = *(const float4*)&S[(ty * 4 + i) * 132 + cj];
                acc[i][0] = fmaf(p4.x, v0.x, acc[i][0]);
                acc[i][1] = fmaf(p4.x, v0.y, acc[i][1]);
                acc[i][2] = fmaf(p4.x, v0.z, acc[i][2]);
                acc[i][3] = fmaf(p4.x, v0.w, acc[i][3]);
                acc[i][0] = fmaf(p4.y, v1.x, acc[i][0]);
                acc[i][1] = fmaf(p4.y, v1.y, acc[i][1]);
                acc[i][2] = fmaf(p4.y, v1.z, acc[i][2]);
                acc[i][3] = fmaf(p4.y, v1.w, acc[i][3]);
                acc[i][0] = fmaf(p4.z, v2.x, acc[i][0]);
                acc[i][1] = fmaf(p4.z, v2.y, acc[i][1]);
                acc[i][2] = fmaf(p4.z, v2.z, acc[i][2]);
                acc[i][3] = fmaf(p4.z, v2.w, acc[i][3]);
                acc[i][0] = fmaf(p4.w, v3.x, acc[i][0]);
                acc[i][1] = fmaf(p4.w, v3.y, acc[i][1]);
                acc[i][2] = fmaf(p4.w, v3.z, acc[i][2]);
                acc[i][3] = fmaf(p4.w, v3.w, acc[i][3]);
            }
        }
    }

    float* yb = y + ((size_t)(b * NQ + q0)) * CE + h * 64;
    #pragma unroll
    for (int i = 0; i < 4; ++i) {
        float inv = 1.0f / lrow[i];
        float4 o;
        o.x = acc[i][0] * inv; o.y = acc[i][1] * inv;
        o.z = acc[i][2] * inv; o.w = acc[i][3] * inv;
        *(float4*)(yb + (size_t)(ty * 4 + i) * CE + tx * 4) = o;
    }
}

// ---------------------------------------------------------------------------
// Launch
// ---------------------------------------------------------------------------
extern "C" void kernel_launch(void* const* d_in, const int* in_sizes, int n_in,
                              void* d_out, int out_size) {
    (void)in_sizes; (void)n_in; (void)out_size;
    const float* x_ctx     = (const float*)d_in[0];
    const float* x_query   = (const float*)d_in[1];
    const float* pos_ctx   = (const float*)d_in[2];
    const float* pos_query = (const float*)d_in[3];
    const float* Wq = (const float*)d_in[4];
    const float* bq = (const float*)d_in[5];
    const float* Wk = (const float*)d_in[6];
    const float* bk = (const float*)d_in[7];
    const float* Wv = (const float*)d_in[8];
    const float* bv = (const float*)d_in[9];
    const float* Wo = (const float*)d_in[10];
    const float* bo = (const float*)d_in[11];
    float* out = (float*)d_out;

    float *gq, *gk, *gv, *gqT, *gkT, *gy, *gh;
    cudaGetSymbolAddress((void**)&gq,  g_q);
    cudaGetSymbolAddress((void**)&gk,  g_k);
    cudaGetSymbolAddress((void**)&gv,  g_v);
    cudaGetSymbolAddress((void**)&gqT, g_qT);
    cudaGetSymbolAddress((void**)&gkT, g_kT);
    cudaGetSymbolAddress((void**)&gy,  g_y);
    cudaGetSymbolAddress((void**)&gh,  g_heat);

    cudaFuncSetAttribute(attn_kernel,
                         cudaFuncAttributeMaxDynamicSharedMemorySize, ATTN_SMEM);

    heat_precompute<<<dim3(NQ, B_), 256>>>(pos_ctx, pos_query, gh);

    gemm_tc<<<dim3(4, (B_ * NQ) / 128), 256>>>(x_query, Wq, bq, gq);
    gemm_tc<<<dim3(4, (B_ * NC) / 128), 256>>>(x_ctx,   Wk, bk, gk);
    gemm_tc<<<dim3(4, (B_ * NC) / 128), 256>>>(x_ctx,   Wv, bv, gv);

    transpose_head<<<dim3(NQ / 64, H_, B_), 256>>>(gq, gqT, NQ);
    transpose_head<<<dim3(NC / 64, H_, B_), 256>>>(gk, gkT, NC);

    attn_kernel<<<dim3(NQ / 128, H_, B_), 512, ATTN_SMEM>>>(gqT, gkT, gv, gh, gy);

    gemm_tc<<<dim3(4, (B_ * NQ) / 128), 256>>>(gy, Wo, bo, out);
}

// round 4
// speedup vs baseline: 2.1587x; 1.5684x over previous
#include <cuda_runtime.h>
#include <cuda_bf16.h>
#include <cstdint>
#include <math.h>

// ---------------------------------------------------------------------------
// Problem constants
// ---------------------------------------------------------------------------
constexpr int B_  = 2;
constexpr int NQ  = 2048;
constexpr int NC  = 4096;
constexpr int CE  = 512;
constexpr int H_  = 8;
constexpr float SCALE  = 0.125f;
constexpr float FOURNU = 0.4f;
constexpr float EPS_   = 1e-6f;

// ---------------------------------------------------------------------------
// Scratch
// ---------------------------------------------------------------------------
__device__ float g_q [B_ * NQ * CE];
__device__ float g_k [B_ * NC * CE];
__device__ float g_v [B_ * NC * CE];
__device__ float g_y [B_ * NQ * CE];
__device__ float g_heat[(size_t)B_ * NQ * NC];            // 67 MB
__device__ __nv_bfloat16 g_qh[B_ * NQ * CE];              // 4 MB (scaled)
__device__ __nv_bfloat16 g_ql[B_ * NQ * CE];
__device__ __nv_bfloat16 g_kh[B_ * NC * CE];              // 8 MB
__device__ __nv_bfloat16 g_kl[B_ * NC * CE];
__device__ __nv_bfloat16 g_vth[B_ * NC * CE];             // 8 MB, [b][h][d][c]
__device__ __nv_bfloat16 g_vtl[B_ * NC * CE];

// ---------------------------------------------------------------------------
// helpers
// ---------------------------------------------------------------------------
__device__ __forceinline__ uint32_t f2tf32(float f) {
    uint32_t r;
    asm("cvt.rna.tf32.f32 %0, %1;" : "=r"(r) : "f"(f));
    return r;
}
__device__ __forceinline__ void split_tf32(float f, uint32_t& hi, uint32_t& lo) {
    hi = f2tf32(f);
    lo = f2tf32(f - __uint_as_float(hi));
}
#define MMA_TF32(d, a, b) \
    asm volatile("mma.sync.aligned.m16n8k8.row.col.f32.tf32.tf32.f32 " \
        "{%0,%1,%2,%3}, {%4,%5,%6,%7}, {%8,%9}, {%0,%1,%2,%3};" \
        : "+f"((d)[0]), "+f"((d)[1]), "+f"((d)[2]), "+f"((d)[3]) \
        : "r"((a)[0]), "r"((a)[1]), "r"((a)[2]), "r"((a)[3]), \
          "r"((b)[0]), "r"((b)[1]))

#define MMA_BF16(d, a0, a1, a2, a3, b0, b1) \
    asm volatile("mma.sync.aligned.m16n8k16.row.col.f32.bf16.bf16.f32 " \
        "{%0,%1,%2,%3}, {%4,%5,%6,%7}, {%8,%9}, {%0,%1,%2,%3};" \
        : "+f"((d)[0]), "+f"((d)[1]), "+f"((d)[2]), "+f"((d)[3]) \
        : "r"(a0), "r"(a1), "r"(a2), "r"(a3), "r"(b0), "r"(b1))

__device__ __forceinline__ uint32_t b2u(__nv_bfloat162 x) {
    return *reinterpret_cast<uint32_t*>(&x);
}

// ---------------------------------------------------------------------------
// Heat-kernel bias precompute (head-independent)
// ---------------------------------------------------------------------------
__global__ __launch_bounds__(256)
void heat_precompute(const float* __restrict__ pos_c, const float* __restrict__ pos_q,
                     float* __restrict__ heat) {
    const int b  = blockIdx.y;
    const int qi = blockIdx.x;
    const float* pq = pos_q + (size_t)(b * NQ + qi) * 3;
    const float qx = pq[0], qy = pq[1], qt = pq[2];
    float* hrow = heat + ((size_t)b * NQ + qi) * NC;
    for (int ci = threadIdx.x; ci < NC; ci += 256) {
        const float* pc = pos_c + (size_t)(b * NC + ci) * 3;
        float dx = qx - pc[0];
        float dy = qy - pc[1];
        float dt = qt - pc[2];
        float denom = FOURNU * fabsf(dt) + EPS_;
        float dist  = dx * dx + dy * dy;
        hrow[ci] = __expf(-__fdividef(dist, denom));
    }
}

// ---------------------------------------------------------------------------
// bf16 hi/lo split (elementwise, optional scale)
// ---------------------------------------------------------------------------
__global__ __launch_bounds__(256)
void split_bf16(const float* __restrict__ in, __nv_bfloat16* __restrict__ oh,
                __nv_bfloat16* __restrict__ ol, float scale) {
    int i = blockIdx.x * 256 + threadIdx.x;
    float4 v = ((const float4*)in)[i];
    v.x *= scale; v.y *= scale; v.z *= scale; v.w *= scale;
    __nv_bfloat162 hA = __floats2bfloat162_rn(v.x, v.y);
    __nv_bfloat162 hB = __floats2bfloat162_rn(v.z, v.w);
    __nv_bfloat162 lA = __floats2bfloat162_rn(v.x - __bfloat162float(hA.x),
                                              v.y - __bfloat162float(hA.y));
    __nv_bfloat162 lB = __floats2bfloat162_rn(v.z - __bfloat162float(hB.x),
                                              v.w - __bfloat162float(hB.y));
    *(uint2*)&oh[(size_t)i * 4] = make_uint2(b2u(hA), b2u(hB));
    *(uint2*)&ol[(size_t)i * 4] = make_uint2(b2u(lA), b2u(lB));
}

// ---------------------------------------------------------------------------
// V: per-head transpose + bf16 split.  g_v[b][c][h*64+d] -> out[b][h][d][c]
// ---------------------------------------------------------------------------
__global__ __launch_bounds__(256)
void split_v_T(const float* __restrict__ v, __nv_bfloat16* __restrict__ oh,
               __nv_bfloat16* __restrict__ ol) {
    __shared__ float ts[64][65];
    const int b  = blockIdx.z;
    const int h  = blockIdx.y;
    const int c0 = blockIdx.x * 64;
    const int tid = threadIdx.x;
    #pragma unroll
    for (int t = 0; t < 4; ++t) {
        int idx = tid + t * 256;
        int r   = idx >> 4;
        int d4  = (idx & 15) << 2;
        float4 vv = *(const float4*)&v[(size_t)(b * NC + c0 + r) * 512 + h * 64 + d4];
        ts[d4 + 0][r] = vv.x; ts[d4 + 1][r] = vv.y;
        ts[d4 + 2][r] = vv.z; ts[d4 + 3][r] = vv.w;
    }
    __syncthreads();
    #pragma unroll
    for (int t = 0; t < 4; ++t) {
        int idx = tid + t * 256;
        int d   = idx >> 4;
        int r4  = (idx & 15) << 2;
        float x0 = ts[d][r4], x1 = ts[d][r4 + 1], x2 = ts[d][r4 + 2], x3 = ts[d][r4 + 3];
        __nv_bfloat162 hA = __floats2bfloat162_rn(x0, x1);
        __nv_bfloat162 hB = __floats2bfloat162_rn(x2, x3);
        __nv_bfloat162 lA = __floats2bfloat162_rn(x0 - __bfloat162float(hA.x),
                                                  x1 - __bfloat162float(hA.y));
        __nv_bfloat162 lB = __floats2bfloat162_rn(x2 - __bfloat162float(hB.x),
                                                  x3 - __bfloat162float(hB.y));
        size_t o = ((size_t)(b * H_ + h) * 64 + d) * NC + c0 + r4;
        *(uint2*)&oh[o] = make_uint2(b2u(hA), b2u(hB));
        *(uint2*)&ol[o] = make_uint2(b2u(lA), b2u(lB));
    }
}

// ---------------------------------------------------------------------------
// GEMM via mma.sync tf32 x3-split (unchanged from R3, passing)
// ---------------------------------------------------------------------------
__global__ __launch_bounds__(256, 1)
void gemm_tc(const float* __restrict__ X, const float* __restrict__ W,
             const float* __restrict__ bias, float* __restrict__ Y) {
    __shared__ float As[32 * 132];
    __shared__ float Bs[32 * 132];

    const int tid  = threadIdx.x;
    const int lane = tid & 31;
    const int wid  = tid >> 5;
    const int grp  = lane >> 2;
    const int tig  = lane & 3;
    const int wm   = (wid >> 1) * 32;
    const int wn   = (wid & 1) * 64;
    const int rowBase = blockIdx.y * 128;
    const int colBase = blockIdx.x * 128;

    float acc[2][8][4];
    #pragma unroll
    for (int mt = 0; mt < 2; ++mt)
        #pragma unroll
        for (int nt = 0; nt < 8; ++nt)
            #pragma unroll
            for (int r = 0; r < 4; ++r) acc[mt][nt][r] = 0.f;

    float4 xs[4], ws[4];
    #pragma unroll
    for (int t = 0; t < 4; ++t) {
        int idx = tid + t * 256;
        int r   = idx >> 3;
        int k4  = (idx & 7) << 2;
        xs[t] = *(const float4*)&X[(size_t)(rowBase + r) * 512 + k4];
        ws[t] = *(const float4*)&W[(size_t)(colBase + r) * 512 + k4];
    }

    for (int c = 0; c < 16; ++c) {
        __syncthreads();
        #pragma unroll
        for (int t = 0; t < 4; ++t) {
            int idx = tid + t * 256;
            int r   = idx >> 3;
            int k4  = (idx & 7) << 2;
            As[(k4 + 0) * 132 + r] = xs[t].x;
            As[(k4 + 1) * 132 + r] = xs[t].y;
            As[(k4 + 2) * 132 + r] = xs[t].z;
            As[(k4 + 3) * 132 + r] = xs[t].w;
            Bs[(k4 + 0) * 132 + r] = ws[t].x;
            Bs[(k4 + 1) * 132 + r] = ws[t].y;
            Bs[(k4 + 2) * 132 + r] = ws[t].z;
            Bs[(k4 + 3) * 132 + r] = ws[t].w;
        }
        __syncthreads();
        if (c < 15) {
            int k0 = (c + 1) * 32;
            #pragma unroll
            for (int t = 0; t < 4; ++t) {
                int idx = tid + t * 256;
                int r   = idx >> 3;
                int k4  = (idx & 7) << 2;
                xs[t] = *(const float4*)&X[(size_t)(rowBase + r) * 512 + k0 + k4];
                ws[t] = *(const float4*)&W[(size_t)(colBase + r) * 512 + k0 + k4];
            }
        }
        #pragma unroll
        for (int ks = 0; ks < 4; ++ks) {
            const int k8 = ks * 8;
            uint32_t ah[2][4], al[2][4];
            #pragma unroll
            for (int mt = 0; mt < 2; ++mt) {
                int r0 = wm + mt * 16 + grp;
                split_tf32(As[(k8 + tig)     * 132 + r0],     ah[mt][0], al[mt][0]);
                split_tf32(As[(k8 + tig)     * 132 + r0 + 8], ah[mt][1], al[mt][1]);
                split_tf32(As[(k8 + tig + 4) * 132 + r0],     ah[mt][2], al[mt][2]);
                split_tf32(As[(k8 + tig + 4) * 132 + r0 + 8], ah[mt][3], al[mt][3]);
            }
            uint32_t bh[8][2], bl[8][2];
            #pragma unroll
            for (int nt = 0; nt < 8; ++nt) {
                int n = wn + nt * 8 + grp;
                split_tf32(Bs[(k8 + tig)     * 132 + n], bh[nt][0], bl[nt][0]);
                split_tf32(Bs[(k8 + tig + 4) * 132 + n], bh[nt][1], bl[nt][1]);
            }
            #pragma unroll
            for (int mt = 0; mt < 2; ++mt)
                #pragma unroll
                for (int nt = 0; nt < 8; ++nt) {
                    MMA_TF32(acc[mt][nt], ah[mt], bh[nt]);
                    MMA_TF32(acc[mt][nt], ah[mt], bl[nt]);
                    MMA_TF32(acc[mt][nt], al[mt], bh[nt]);
                }
        }
    }

    #pragma unroll
    for (int nt = 0; nt < 8; ++nt) {
        int col = colBase + wn + nt * 8 + tig * 2;
        float b0 = __ldg(&bias[col]);
        float b1 = __ldg(&bias[col + 1]);
        #pragma unroll
        for (int mt = 0; mt < 2; ++mt) {
            int row = rowBase + wm + mt * 16 + grp;
            float2 o0 = make_float2(acc[mt][nt][0] + b0, acc[mt][nt][1] + b1);
            float2 o1 = make_float2(acc[mt][nt][2] + b0, acc[mt][nt][3] + b1);
            *(float2*)&Y[(size_t)row       * 512 + col] = o0;
            *(float2*)&Y[(size_t)(row + 8) * 512 + col] = o1;
        }
    }
}

// ---------------------------------------------------------------------------
// Tensor-core flash attention.  128q x 64c tiles, 8 warps (16 q-rows each).
// bf16 hi/lo 3-split MMAs for QK and PV.  No online max (logits bounded).
// Smem bytes:
//   Kh 0..9216, Kl 9216..18432, Vh 18432..27648, Vl 27648..36864
//   P per warp: 36864 + w*4608  (Ph 2304 | Pl 2304); row stride 144 B (72 bf16)
// ---------------------------------------------------------------------------
constexpr int ATTN_SMEM_B = 73728;

__global__ __launch_bounds__(256)
void attn_tc(const __nv_bfloat16* __restrict__ qh, const __nv_bfloat16* __restrict__ ql,
             const __nv_bfloat16* __restrict__ kh, const __nv_bfloat16* __restrict__ kl,
             const __nv_bfloat16* __restrict__ vth, const __nv_bfloat16* __restrict__ vtl,
             const float* __restrict__ heat, float* __restrict__ y) {
    extern __shared__ char smem[];

    const int b   = blockIdx.z;
    const int h   = blockIdx.y;
    const int q0  = blockIdx.x * 128;
    const int tid = threadIdx.x;
    const int w    = tid >> 5;
    const int lane = tid & 31;
    const int grp  = lane >> 2;
    const int tig  = lane & 3;

    // ---- Q fragments in registers (fixed for whole kernel) ----
    const int qrow0 = b * NQ + q0 + w * 16 + grp;
    uint32_t qfh[4][4], qfl[4][4];
    #pragma unroll
    for (int ks = 0; ks < 4; ++ks) {
        int cb = h * 64 + ks * 16 + tig * 2;
        qfh[ks][0] = *(const uint32_t*)(qh + (size_t)qrow0 * 512 + cb);
        qfh[ks][1] = *(const uint32_t*)(qh + (size_t)(qrow0 + 8) * 512 + cb);
        qfh[ks][2] = *(const uint32_t*)(qh + (size_t)qrow0 * 512 + cb + 8);
        qfh[ks][3] = *(const uint32_t*)(qh + (size_t)(qrow0 + 8) * 512 + cb + 8);
        qfl[ks][0] = *(const uint32_t*)(ql + (size_t)qrow0 * 512 + cb);
        qfl[ks][1] = *(const uint32_t*)(ql + (size_t)(qrow0 + 8) * 512 + cb);
        qfl[ks][2] = *(const uint32_t*)(ql + (size_t)qrow0 * 512 + cb + 8);
        qfl[ks][3] = *(const uint32_t*)(ql + (size_t)(qrow0 + 8) * 512 + cb + 8);
    }

    float acc[8][4];
    #pragma unroll
    for (int nt = 0; nt < 8; ++nt)
        #pragma unroll
        for (int r = 0; r < 4; ++r) acc[nt][r] = 0.f;
    float l0 = 0.f, l1 = 0.f;

    char* PhB = smem + 36864 + w * 4608;
    char* PlB = PhB + 2304;
    const float* hb0 = heat + (size_t)qrow0 * NC;
    const float* hb1 = hb0 + (size_t)8 * NC;

    for (int c0 = 0; c0 < NC; c0 += 64) {
        __syncthreads();
        // ---- stage K / V^T tiles (hi/lo), row stride 144 B ----
        #pragma unroll
        for (int j = 0; j < 2; ++j) {
            int idx = tid + j * 256;
            int r   = idx >> 3;
            int c8  = idx & 7;
            size_t ksrc = (size_t)(b * NC + c0 + r) * 512 + h * 64 + c8 * 8;
            *(uint4*)(smem +         r * 144 + c8 * 16) = *(const uint4*)(kh  + ksrc);
            *(uint4*)(smem +  9216 + r * 144 + c8 * 16) = *(const uint4*)(kl  + ksrc);
            size_t vsrc = ((size_t)(b * H_ + h) * 64 + r) * NC + c0 + c8 * 8;
            *(uint4*)(smem + 18432 + r * 144 + c8 * 16) = *(const uint4*)(vth + vsrc);
            *(uint4*)(smem + 27648 + r * 144 + c8 * 16) = *(const uint4*)(vtl + vsrc);
        }
        __syncthreads();

        // ---- QK: s[nt][4] ----
        float s[8][4];
        #pragma unroll
        for (int nt = 0; nt < 8; ++nt) {
            #pragma unroll
            for (int r = 0; r < 4; ++r) s[nt][r] = 0.f;
            #pragma unroll
            for (int ks = 0; ks < 4; ++ks) {
                int roff = (nt * 8 + grp) * 144 + ks * 32 + tig * 4;
                uint32_t bh0 = *(uint32_t*)(smem + roff);
                uint32_t bh1 = *(uint32_t*)(smem + roff + 16);
                uint32_t bl0 = *(uint32_t*)(smem + 9216 + roff);
                uint32_t bl1 = *(uint32_t*)(smem + 9216 + roff + 16);
                MMA_BF16(s[nt], qfh[ks][0], qfh[ks][1], qfh[ks][2], qfh[ks][3], bh0, bh1);
                MMA_BF16(s[nt], qfh[ks][0], qfh[ks][1], qfh[ks][2], qfh[ks][3], bl0, bl1);
                MMA_BF16(s[nt], qfl[ks][0], qfl[ks][1], qfl[ks][2], qfl[ks][3], bh0, bh1);
            }
        }

        // ---- bias + exp + store P (hi/lo) ----
        #pragma unroll
        for (int nt = 0; nt < 8; ++nt) {
            int cc = nt * 8 + tig * 2;
            float2 h0 = *(const float2*)(hb0 + c0 + cc);
            float2 h1 = *(const float2*)(hb1 + c0 + cc);
            float e00 = __expf(s[nt][0] + h0.x);
            float e01 = __expf(s[nt][1] + h0.y);
            float e10 = __expf(s[nt][2] + h1.x);
            float e11 = __expf(s[nt][3] + h1.y);
            l0 += e00 + e01;
            l1 += e10 + e11;
            __nv_bfloat162 p0 = __floats2bfloat162_rn(e00, e01);
            __nv_bfloat162 p1 = __floats2bfloat162_rn(e10, e11);
            __nv_bfloat162 q0v = __floats2bfloat162_rn(e00 - __bfloat162float(p0.x),
                                                       e01 - __bfloat162float(p0.y));
            __nv_bfloat162 q1v = __floats2bfloat162_rn(e10 - __bfloat162float(p1.x),
                                                       e11 - __bfloat162float(p1.y));
            *(uint32_t*)(PhB + grp * 144 + cc * 2)       = b2u(p0);
            *(uint32_t*)(PhB + (grp + 8) * 144 + cc * 2) = b2u(p1);
            *(uint32_t*)(PlB + grp * 144 + cc * 2)       = b2u(q0v);
            *(uint32_t*)(PlB + (grp + 8) * 144 + cc * 2) = b2u(q1v);
        }
        __syncwarp();

        // ---- AV: acc += P @ V^T' ----
        #pragma unroll
        for (int ks = 0; ks < 4; ++ks) {
            int aoff = grp * 144 + ks * 32 + tig * 4;
            uint32_t ah0 = *(uint32_t*)(PhB + aoff);
            uint32_t ah1 = *(uint32_t*)(PhB + aoff + 8 * 144);
            uint32_t ah2 = *(uint32_t*)(PhB + aoff + 16);
            uint32_t ah3 = *(uint32_t*)(PhB + aoff + 8 * 144 + 16);
            uint32_t al0 = *(uint32_t*)(PlB + aoff);
            uint32_t al1 = *(uint32_t*)(PlB + aoff + 8 * 144);
            uint32_t al2 = *(uint32_t*)(PlB + aoff + 16);
            uint32_t al3 = *(uint32_t*)(PlB + aoff + 8 * 144 + 16);
            #pragma unroll
            for (int nt = 0; nt < 8; ++nt) {
                int boff = 18432 + (nt * 8 + grp) * 144 + ks * 32 + tig * 4;
                uint32_t bh0 = *(uint32_t*)(smem + boff);
                uint32_t bh1 = *(uint32_t*)(smem + boff + 16);
                uint32_t bl0 = *(uint32_t*)(smem + boff + 9216);
                uint32_t bl1 = *(uint32_t*)(smem + boff + 9216 + 16);
                MMA_BF16(acc[nt], ah0, ah1, ah2, ah3, bh0, bh1);
                MMA_BF16(acc[nt], ah0, ah1, ah2, ah3, bl0, bl1);
                MMA_BF16(acc[nt], al0, al1, al2, al3, bh0, bh1);
            }
        }
    }

    // ---- final row sums + write ----
    l0 += __shfl_xor_sync(0xffffffffu, l0, 1);
    l0 += __shfl_xor_sync(0xffffffffu, l0, 2);
    l1 += __shfl_xor_sync(0xffffffffu, l1, 1);
    l1 += __shfl_xor_sync(0xffffffffu, l1, 2);
    float i0 = 1.0f / l0;
    float i1 = 1.0f / l1;

    size_t yr0 = (size_t)qrow0 * 512 + h * 64;
    #pragma unroll
    for (int nt = 0; nt < 8; ++nt) {
        int cc = nt * 8 + tig * 2;
        *(float2*)(y + yr0 + cc)            = make_float2(acc[nt][0] * i0, acc[nt][1] * i0);
        *(float2*)(y + yr0 + 8 * 512 + cc)  = make_float2(acc[nt][2] * i1, acc[nt][3] * i1);
    }
}

// ---------------------------------------------------------------------------
// Launch
// ---------------------------------------------------------------------------
extern "C" void kernel_launch(void* const* d_in, const int* in_sizes, int n_in,
                              void* d_out, int out_size) {
    (void)in_sizes; (void)n_in; (void)out_size;
    const float* x_ctx     = (const float*)d_in[0];
    const float* x_query   = (const float*)d_in[1];
    const float* pos_ctx   = (const float*)d_in[2];
    const float* pos_query = (const float*)d_in[3];
    const float* Wq = (const float*)d_in[4];
    const float* bq = (const float*)d_in[5];
    const float* Wk = (const float*)d_in[6];
    const float* bk = (const float*)d_in[7];
    const float* Wv = (const float*)d_in[8];
    const float* bv = (const float*)d_in[9];
    const float* Wo = (const float*)d_in[10];
    const float* bo = (const float*)d_in[11];
    float* out = (float*)d_out;

    float *gq, *gk, *gv, *gy, *gh;
    __nv_bfloat16 *gqh, *gql, *gkh, *gkl, *gvth, *gvtl;
    cudaGetSymbolAddress((void**)&gq,  g_q);
    cudaGetSymbolAddress((void**)&gk,  g_k);
    cudaGetSymbolAddress((void**)&gv,  g_v);
    cudaGetSymbolAddress((void**)&gy,  g_y);
    cudaGetSymbolAddress((void**)&gh,  g_heat);
    cudaGetSymbolAddress((void**)&gqh, g_qh);
    cudaGetSymbolAddress((void**)&gql, g_ql);
    cudaGetSymbolAddress((void**)&gkh, g_kh);
    cudaGetSymbolAddress((void**)&gkl, g_kl);
    cudaGetSymbolAddress((void**)&gvth, g_vth);
    cudaGetSymbolAddress((void**)&gvtl, g_vtl);

    cudaFuncSetAttribute(attn_tc,
                         cudaFuncAttributeMaxDynamicSharedMemorySize, ATTN_SMEM_B);

    heat_precompute<<<dim3(NQ, B_), 256>>>(pos_ctx, pos_query, gh);

    gemm_tc<<<dim3(4, (B_ * NQ) / 128), 256>>>(x_query, Wq, bq, gq);
    gemm_tc<<<dim3(4, (B_ * NC) / 128), 256>>>(x_ctx,   Wk, bk, gk);
    gemm_tc<<<dim3(4, (B_ * NC) / 128), 256>>>(x_ctx,   Wv, bv, gv);

    split_bf16<<<(B_ * NQ * CE) / 1024, 256>>>(gq, gqh, gql, SCALE);
    split_bf16<<<(B_ * NC * CE) / 1024, 256>>>(gk, gkh, gkl, 1.0f);
    split_v_T<<<dim3(NC / 64, H_, B_), 256>>>(gv, gvth, gvtl);

    attn_tc<<<dim3(NQ / 128, H_, B_), 256, ATTN_SMEM_B>>>(
        gqh, gql, gkh, gkl, gvth, gvtl, gh, gy);

    gemm_tc<<<dim3(4, (B_ * NQ) / 128), 256>>>(gy, Wo, bo, out);
}

// round 6
// speedup vs baseline: 2.3168x; 1.0733x over previous
#include <cuda_runtime.h>
#include <cuda_bf16.h>
#include <cstdint>
#include <math.h>

// ---------------------------------------------------------------------------
// Problem constants
// ---------------------------------------------------------------------------
constexpr int B_  = 2;
constexpr int NQ  = 2048;
constexpr int NC  = 4096;
constexpr int CE  = 512;
constexpr int H_  = 8;
constexpr float SCALE  = 0.125f;
constexpr float FOURNU = 0.4f;
constexpr float EPS_   = 1e-6f;

// ---------------------------------------------------------------------------
// Scratch
// ---------------------------------------------------------------------------
__device__ float g_v [B_ * NC * CE];
__device__ float g_heat[(size_t)B_ * NQ * NC];            // 67 MB
__device__ __nv_bfloat16 g_xqh[B_ * NQ * CE];             // x_query hi/lo
__device__ __nv_bfloat16 g_xql[B_ * NQ * CE];
__device__ __nv_bfloat16 g_xch[B_ * NC * CE];             // x_ctx hi/lo
__device__ __nv_bfloat16 g_xcl[B_ * NC * CE];
__device__ __nv_bfloat16 g_wh[4 * CE * CE];               // Wq,Wk,Wv,Wo hi
__device__ __nv_bfloat16 g_wl[4 * CE * CE];
__device__ __nv_bfloat16 g_qh[B_ * NQ * CE];              // scaled q hi/lo
__device__ __nv_bfloat16 g_ql[B_ * NQ * CE];
__device__ __nv_bfloat16 g_kh[B_ * NC * CE];
__device__ __nv_bfloat16 g_kl[B_ * NC * CE];
__device__ __nv_bfloat16 g_vth[B_ * NC * CE];             // [b][h][d][c]
__device__ __nv_bfloat16 g_vtl[B_ * NC * CE];
__device__ __nv_bfloat16 g_yh[B_ * NQ * CE];              // attn out hi/lo
__device__ __nv_bfloat16 g_yl[B_ * NQ * CE];

// ---------------------------------------------------------------------------
// helpers
// ---------------------------------------------------------------------------
#define MMA_BF16(d, a0, a1, a2, a3, b0, b1) \
    asm volatile("mma.sync.aligned.m16n8k16.row.col.f32.bf16.bf16.f32 " \
        "{%0,%1,%2,%3}, {%4,%5,%6,%7}, {%8,%9}, {%0,%1,%2,%3};" \
        : "+f"((d)[0]), "+f"((d)[1]), "+f"((d)[2]), "+f"((d)[3]) \
        : "r"(a0), "r"(a1), "r"(a2), "r"(a3), "r"(b0), "r"(b1))

#define CP16(dst, src) \
    asm volatile("cp.async.cg.shared.global [%0], [%1], 16;" \
                 :: "r"(dst), "l"(src))
#define CP_COMMIT() asm volatile("cp.async.commit_group;")

__device__ __forceinline__ uint32_t b2u(__nv_bfloat162 x) {
    return *reinterpret_cast<uint32_t*>(&x);
}
__device__ __forceinline__ uint32_t smem_u32(const void* p) {
    uint32_t a;
    asm("{ .reg .u64 t; cvta.to.shared.u64 t, %1; cvt.u32.u64 %0, t; }"
        : "=r"(a) : "l"(p));
    return a;
}

// ---------------------------------------------------------------------------
// Heat-kernel bias precompute (head-independent)
// ---------------------------------------------------------------------------
__global__ __launch_bounds__(256)
void heat_precompute(const float* __restrict__ pos_c, const float* __restrict__ pos_q,
                     float* __restrict__ heat) {
    const int b  = blockIdx.y;
    const int qi = blockIdx.x;
    const float* pq = pos_q + (size_t)(b * NQ + qi) * 3;
    const float qx = pq[0], qy = pq[1], qt = pq[2];
    float* hrow = heat + ((size_t)b * NQ + qi) * NC;
    for (int ci = threadIdx.x; ci < NC; ci += 256) {
        const float* pc = pos_c + (size_t)(b * NC + ci) * 3;
        float dx = qx - pc[0];
        float dy = qy - pc[1];
        float dt = qt - pc[2];
        float denom = FOURNU * fabsf(dt) + EPS_;
        float dist  = dx * dx + dy * dy;
        hrow[ci] = __expf(-__fdividef(dist, denom));
    }
}

// ---------------------------------------------------------------------------
// bf16 hi/lo split (elementwise)
// ---------------------------------------------------------------------------
__global__ __launch_bounds__(256)
void split_bf16(const float* __restrict__ in, __nv_bfloat16* __restrict__ oh,
                __nv_bfloat16* __restrict__ ol) {
    int i = blockIdx.x * 256 + threadIdx.x;
    float4 v = ((const float4*)in)[i];
    __nv_bfloat162 hA = __floats2bfloat162_rn(v.x, v.y);
    __nv_bfloat162 hB = __floats2bfloat162_rn(v.z, v.w);
    __nv_bfloat162 lA = __floats2bfloat162_rn(v.x - __bfloat162float(hA.x),
                                              v.y - __bfloat162float(hA.y));
    __nv_bfloat162 lB = __floats2bfloat162_rn(v.z - __bfloat162float(hB.x),
                                              v.w - __bfloat162float(hB.y));
    *(uint2*)&oh[(size_t)i * 4] = make_uint2(b2u(hA), b2u(hB));
    *(uint2*)&ol[(size_t)i * 4] = make_uint2(b2u(lA), b2u(lB));
}

// ---------------------------------------------------------------------------
// V: per-head transpose + bf16 split.  g_v[b][c][h*64+d] -> out[b][h][d][c]
// ---------------------------------------------------------------------------
__global__ __launch_bounds__(256)
void split_v_T(const float* __restrict__ v, __nv_bfloat16* __restrict__ oh,
               __nv_bfloat16* __restrict__ ol) {
    __shared__ float ts[64][65];
    const int b  = blockIdx.z;
    const int h  = blockIdx.y;
    const int c0 = blockIdx.x * 64;
    const int tid = threadIdx.x;
    #pragma unroll
    for (int t = 0; t < 4; ++t) {
        int idx = tid + t * 256;
        int r   = idx >> 4;
        int d4  = (idx & 15) << 2;
        float4 vv = *(const float4*)&v[(size_t)(b * NC + c0 + r) * 512 + h * 64 + d4];
        ts[d4 + 0][r] = vv.x; ts[d4 + 1][r] = vv.y;
        ts[d4 + 2][r] = vv.z; ts[d4 + 3][r] = vv.w;
    }
    __syncthreads();
    #pragma unroll
    for (int t = 0; t < 4; ++t) {
        int idx = tid + t * 256;
        int d   = idx >> 4;
        int r4  = (idx & 15) << 2;
        float x0 = ts[d][r4], x1 = ts[d][r4 + 1], x2 = ts[d][r4 + 2], x3 = ts[d][r4 + 3];
        __nv_bfloat162 hA = __floats2bfloat162_rn(x0, x1);
        __nv_bfloat162 hB = __floats2bfloat162_rn(x2, x3);
        __nv_bfloat162 lA = __floats2bfloat162_rn(x0 - __bfloat162float(hA.x),
                                                  x1 - __bfloat162float(hA.y));
        __nv_bfloat162 lB = __floats2bfloat162_rn(x2 - __bfloat162float(hB.x),
                                                  x3 - __bfloat162float(hB.y));
        size_t o = ((size_t)(b * H_ + h) * 64 + d) * NC + c0 + r4;
        *(uint2*)&oh[o] = make_uint2(b2u(hA), b2u(hB));
        *(uint2*)&ol[o] = make_uint2(b2u(lA), b2u(lB));
    }
}

// ---------------------------------------------------------------------------
// bf16 3-pass GEMM:  Y[M,512] = A[M,512] @ B[512,512]^T + bias
// A,B pre-split hi/lo bf16.  CTA 128x128, BK=32, 8 warps (4M x 2N, 32x64 each).
// mode 0: write fp32 to Yf.   mode 1: write (acc+bias)*scale as bf16 hi/lo.
// ---------------------------------------------------------------------------
__global__ __launch_bounds__(256, 1)
void gemm_bf16(const __nv_bfloat16* __restrict__ Ah, const __nv_bfloat16* __restrict__ Al,
               const __nv_bfloat16* __restrict__ Bh, const __nv_bfloat16* __restrict__ Bl,
               const float* __restrict__ bias, float* __restrict__ Yf,
               __nv_bfloat16* __restrict__ Ybh, __nv_bfloat16* __restrict__ Ybl,
               int mode, float scale) {
    __shared__ __nv_bfloat16 sA[2][128 * 40];
    __shared__ __nv_bfloat16 sB[2][128 * 40];

    const int tid  = threadIdx.x;
    const int lane = tid & 31;
    const int wid  = tid >> 5;
    const int grp  = lane >> 2;
    const int tig  = lane & 3;
    const int wm   = (wid >> 1) * 32;
    const int wn   = (wid & 1) * 64;
    const int rowBase = blockIdx.y * 128;
    const int colBase = blockIdx.x * 128;

    float acc[2][8][4];
    #pragma unroll
    for (int mt = 0; mt < 2; ++mt)
        #pragma unroll
        for (int nt = 0; nt < 8; ++nt)
            #pragma unroll
            for (int r = 0; r < 4; ++r) acc[mt][nt][r] = 0.f;

    uint4 pa[2][2], pb[2][2];
    #pragma unroll
    for (int t = 0; t < 2; ++t) {
        int u  = tid + t * 256;
        int r  = u >> 2;
        int cu = u & 3;
        size_t ga = (size_t)(rowBase + r) * 512 + cu * 8;
        size_t gb = (size_t)(colBase + r) * 512 + cu * 8;
        pa[0][t] = *(const uint4*)&Ah[ga];
        pa[1][t] = *(const uint4*)&Al[ga];
        pb[0][t] = *(const uint4*)&Bh[gb];
        pb[1][t] = *(const uint4*)&Bl[gb];
    }

    for (int c = 0; c < 16; ++c) {
        __syncthreads();
        #pragma unroll
        for (int t = 0; t < 2; ++t) {
            int u  = tid + t * 256;
            int r  = u >> 2;
            int cu = u & 3;
            int so = r * 40 + cu * 8;
            *(uint4*)&sA[0][so] = pa[0][t];
            *(uint4*)&sA[1][so] = pa[1][t];
            *(uint4*)&sB[0][so] = pb[0][t];
            *(uint4*)&sB[1][so] = pb[1][t];
        }
        __syncthreads();
        if (c < 15) {
            int k0 = (c + 1) * 32;
            #pragma unroll
            for (int t = 0; t < 2; ++t) {
                int u  = tid + t * 256;
                int r  = u >> 2;
                int cu = u & 3;
                size_t ga = (size_t)(rowBase + r) * 512 + k0 + cu * 8;
                size_t gb = (size_t)(colBase + r) * 512 + k0 + cu * 8;
                pa[0][t] = *(const uint4*)&Ah[ga];
                pa[1][t] = *(const uint4*)&Al[ga];
                pb[0][t] = *(const uint4*)&Bh[gb];
                pb[1][t] = *(const uint4*)&Bl[gb];
            }
        }
        #pragma unroll
        for (int sub = 0; sub < 2; ++sub) {
            const int kb = sub * 16 + tig * 2;
            uint32_t ah[2][4], al[2][4];
            #pragma unroll
            for (int mt = 0; mt < 2; ++mt) {
                int r0 = wm + mt * 16 + grp;
                ah[mt][0] = *(uint32_t*)&sA[0][r0 * 40 + kb];
                ah[mt][1] = *(uint32_t*)&sA[0][(r0 + 8) * 40 + kb];
                ah[mt][2] = *(uint32_t*)&sA[0][r0 * 40 + kb + 8];
                ah[mt][3] = *(uint32_t*)&sA[0][(r0 + 8) * 40 + kb + 8];
                al[mt][0] = *(uint32_t*)&sA[1][r0 * 40 + kb];
                al[mt][1] = *(uint32_t*)&sA[1][(r0 + 8) * 40 + kb];
                al[mt][2] = *(uint32_t*)&sA[1][r0 * 40 + kb + 8];
                al[mt][3] = *(uint32_t*)&sA[1][(r0 + 8) * 40 + kb + 8];
            }
            uint32_t bh[8][2], bl[8][2];
            #pragma unroll
            for (int nt = 0; nt < 8; ++nt) {
                int n = wn + nt * 8 + grp;
                bh[nt][0] = *(uint32_t*)&sB[0][n * 40 + kb];
                bh[nt][1] = *(uint32_t*)&sB[0][n * 40 + kb + 8];
                bl[nt][0] = *(uint32_t*)&sB[1][n * 40 + kb];
                bl[nt][1] = *(uint32_t*)&sB[1][n * 40 + kb + 8];
            }
            #pragma unroll
            for (int mt = 0; mt < 2; ++mt)
                #pragma unroll
                for (int nt = 0; nt < 8; ++nt) {
                    MMA_BF16(acc[mt][nt], ah[mt][0], ah[mt][1], ah[mt][2], ah[mt][3],
                             bh[nt][0], bh[nt][1]);
                    MMA_BF16(acc[mt][nt], ah[mt][0], ah[mt][1], ah[mt][2], ah[mt][3],
                             bl[nt][0], bl[nt][1]);
                    MMA_BF16(acc[mt][nt], al[mt][0], al[mt][1], al[mt][2], al[mt][3],
                             bh[nt][0], bh[nt][1]);
                }
        }
    }

    #pragma unroll
    for (int nt = 0; nt < 8; ++nt) {
        int col = colBase + wn + nt * 8 + tig * 2;
        float b0 = __ldg(&bias[col]);
        float b1 = __ldg(&bias[col + 1]);
        #pragma unroll
        for (int mt = 0; mt < 2; ++mt) {
            int row = rowBase + wm + mt * 16 + grp;
            float v00 = acc[mt][nt][0] + b0, v01 = acc[mt][nt][1] + b1;
            float v10 = acc[mt][nt][2] + b0, v11 = acc[mt][nt][3] + b1;
            if (mode == 0) {
                *(float2*)&Yf[(size_t)row       * 512 + col] = make_float2(v00, v01);
                *(float2*)&Yf[(size_t)(row + 8) * 512 + col] = make_float2(v10, v11);
            } else {
                v00 *= scale; v01 *= scale; v10 *= scale; v11 *= scale;
                __nv_bfloat162 h0 = __floats2bfloat162_rn(v00, v01);
                __nv_bfloat162 h1 = __floats2bfloat162_rn(v10, v11);
                __nv_bfloat162 l0 = __floats2bfloat162_rn(v00 - __bfloat162float(h0.x),
                                                          v01 - __bfloat162float(h0.y));
                __nv_bfloat162 l1 = __floats2bfloat162_rn(v10 - __bfloat162float(h1.x),
                                                          v11 - __bfloat162float(h1.y));
                *(uint32_t*)&Ybh[(size_t)row       * 512 + col] = b2u(h0);
                *(uint32_t*)&Ybh[(size_t)(row + 8) * 512 + col] = b2u(h1);
                *(uint32_t*)&Ybl[(size_t)row       * 512 + col] = b2u(l0);
                *(uint32_t*)&Ybl[(size_t)(row + 8) * 512 + col] = b2u(l1);
            }
        }
    }
}

// ---------------------------------------------------------------------------
// Tensor-core flash attention, cp.async double-buffered.
// 128q x 64c tiles, 8 warps (16 q-rows each).  QK 3-pass, AV 3-pass (P hi/lo —
// P MUST be hi/lo: softmax peaking defeats error averaging, R5 lesson).
// Smem (bytes): tile buf[2] @ 0 / 36864  {Kh 0 | Kl 9216 | Vh 18432 | Vl 27648},
//               P per warp @ 73728 + w*4608  (Ph 2304 | Pl 2304).  Total 110592.
// ---------------------------------------------------------------------------
constexpr int ATTN_SMEM_B = 110592;

__global__ __launch_bounds__(256)
void attn_tc(const __nv_bfloat16* __restrict__ qh, const __nv_bfloat16* __restrict__ ql,
             const __nv_bfloat16* __restrict__ kh, const __nv_bfloat16* __restrict__ kl,
             const __nv_bfloat16* __restrict__ vth, const __nv_bfloat16* __restrict__ vtl,
             const float* __restrict__ heat,
             __nv_bfloat16* __restrict__ yh, __nv_bfloat16* __restrict__ yl) {
    extern __shared__ char smem[];
    const uint32_t sb = smem_u32(smem);

    const int b   = blockIdx.z;
    const int h   = blockIdx.y;
    const int q0  = blockIdx.x * 128;
    const int tid = threadIdx.x;
    const int w    = tid >> 5;
    const int lane = tid & 31;
    const int grp  = lane >> 2;
    const int tig  = lane & 3;

    const int sr  = tid >> 3;
    const int sc8 = tid & 7;

    auto issue_tile = [&](uint32_t bb, int c0) {
        #pragma unroll
        for (int j = 0; j < 2; ++j) {
            int r = sr + j * 32;
            size_t ksrc = (size_t)(b * NC + c0 + r) * 512 + h * 64 + sc8 * 8;
            size_t vsrc = ((size_t)(b * H_ + h) * 64 + r) * NC + c0 + sc8 * 8;
            uint32_t d0 = bb + r * 144 + sc8 * 16;
            CP16(d0,         kh  + ksrc);
            CP16(d0 +  9216, kl  + ksrc);
            CP16(d0 + 18432, vth + vsrc);
            CP16(d0 + 27648, vtl + vsrc);
        }
        CP_COMMIT();
    };

    // ---- Q fragments in registers ----
    const int qrow0 = b * NQ + q0 + w * 16 + grp;
    uint32_t qfh[4][4], qfl[4][4];
    #pragma unroll
    for (int ks = 0; ks < 4; ++ks) {
        int cb = h * 64 + ks * 16 + tig * 2;
        qfh[ks][0] = *(const uint32_t*)(qh + (size_t)qrow0 * 512 + cb);
        qfh[ks][1] = *(const uint32_t*)(qh + (size_t)(qrow0 + 8) * 512 + cb);
        qfh[ks][2] = *(const uint32_t*)(qh + (size_t)qrow0 * 512 + cb + 8);
        qfh[ks][3] = *(const uint32_t*)(qh + (size_t)(qrow0 + 8) * 512 + cb + 8);
        qfl[ks][0] = *(const uint32_t*)(ql + (size_t)qrow0 * 512 + cb);
        qfl[ks][1] = *(const uint32_t*)(ql + (size_t)(qrow0 + 8) * 512 + cb);
        qfl[ks][2] = *(const uint32_t*)(ql + (size_t)qrow0 * 512 + cb + 8);
        qfl[ks][3] = *(const uint32_t*)(ql + (size_t)(qrow0 + 8) * 512 + cb + 8);
    }

    float acc[8][4];
    #pragma unroll
    for (int nt = 0; nt < 8; ++nt)
        #pragma unroll
        for (int r = 0; r < 4; ++r) acc[nt][r] = 0.f;
    float l0 = 0.f, l1 = 0.f;

    char* PhB = smem + 73728 + w * 4608;
    char* PlB = PhB + 2304;
    const float* hb0 = heat + (size_t)qrow0 * NC;
    const float* hb1 = hb0 + (size_t)8 * NC;

    issue_tile(sb, 0);

    for (int it = 0; it < 64; ++it) {
        const int cur = it & 1;
        const char* bufc = smem + cur * 36864;
        if (it < 63) issue_tile(sb + (cur ^ 1) * 36864, (it + 1) * 64);
        if (it < 63) asm volatile("cp.async.wait_group 1;" ::: "memory");
        else         asm volatile("cp.async.wait_group 0;" ::: "memory");
        __syncthreads();

        // ---- QK (3-pass) ----
        float s[8][4];
        #pragma unroll
        for (int nt = 0; nt < 8; ++nt) {
            #pragma unroll
            for (int r = 0; r < 4; ++r) s[nt][r] = 0.f;
            #pragma unroll
            for (int ks = 0; ks < 4; ++ks) {
                int roff = (nt * 8 + grp) * 144 + ks * 32 + tig * 4;
                uint32_t bh0 = *(uint32_t*)(bufc + roff);
                uint32_t bh1 = *(uint32_t*)(bufc + roff + 16);
                uint32_t bl0 = *(uint32_t*)(bufc + 9216 + roff);
                uint32_t bl1 = *(uint32_t*)(bufc + 9216 + roff + 16);
                MMA_BF16(s[nt], qfh[ks][0], qfh[ks][1], qfh[ks][2], qfh[ks][3], bh0, bh1);
                MMA_BF16(s[nt], qfh[ks][0], qfh[ks][1], qfh[ks][2], qfh[ks][3], bl0, bl1);
                MMA_BF16(s[nt], qfl[ks][0], qfl[ks][1], qfl[ks][2], qfl[ks][3], bh0, bh1);
            }
        }

        // ---- bias + exp + store P (hi/lo) ----
        const int c0 = it * 64;
        #pragma unroll
        for (int nt = 0; nt < 8; ++nt) {
            int cc = nt * 8 + tig * 2;
            float2 h0 = *(const float2*)(hb0 + c0 + cc);
            float2 h1 = *(const float2*)(hb1 + c0 + cc);
            float e00 = __expf(s[nt][0] + h0.x);
            float e01 = __expf(s[nt][1] + h0.y);
            float e10 = __expf(s[nt][2] + h1.x);
            float e11 = __expf(s[nt][3] + h1.y);
            l0 += e00 + e01;
            l1 += e10 + e11;
            __nv_bfloat162 p0 = __floats2bfloat162_rn(e00, e01);
            __nv_bfloat162 p1 = __floats2bfloat162_rn(e10, e11);
            __nv_bfloat162 q0v = __floats2bfloat162_rn(e00 - __bfloat162float(p0.x),
                                                       e01 - __bfloat162float(p0.y));
            __nv_bfloat162 q1v = __floats2bfloat162_rn(e10 - __bfloat162float(p1.x),
                                                       e11 - __bfloat162float(p1.y));
            *(uint32_t*)(PhB + grp * 144 + cc * 2)       = b2u(p0);
            *(uint32_t*)(PhB + (grp + 8) * 144 + cc * 2) = b2u(p1);
            *(uint32_t*)(PlB + grp * 144 + cc * 2)       = b2u(q0v);
            *(uint32_t*)(PlB + (grp + 8) * 144 + cc * 2) = b2u(q1v);
        }
        __syncwarp();

        // ---- AV (3-pass: Ph*Vh + Ph*Vl + Pl*Vh) ----
        #pragma unroll
        for (int ks = 0; ks < 4; ++ks) {
            int aoff = grp * 144 + ks * 32 + tig * 4;
            uint32_t a0 = *(uint32_t*)(PhB + aoff);
            uint32_t a1 = *(uint32_t*)(PhB + aoff + 8 * 144);
            uint32_t a2 = *(uint32_t*)(PhB + aoff + 16);
            uint32_t a3 = *(uint32_t*)(PhB + aoff + 8 * 144 + 16);
            uint32_t c0r = *(uint32_t*)(PlB + aoff);
            uint32_t c1r = *(uint32_t*)(PlB + aoff + 8 * 144);
            uint32_t c2r = *(uint32_t*)(PlB + aoff + 16);
            uint32_t c3r = *(uint32_t*)(PlB + aoff + 8 * 144 + 16);
            #pragma unroll
            for (int nt = 0; nt < 8; ++nt) {
                int boff = 18432 + (nt * 8 + grp) * 144 + ks * 32 + tig * 4;
                uint32_t bh0 = *(uint32_t*)(bufc + boff);
                uint32_t bh1 = *(uint32_t*)(bufc + boff + 16);
                uint32_t bl0 = *(uint32_t*)(bufc + boff + 9216);
                uint32_t bl1 = *(uint32_t*)(bufc + boff + 9216 + 16);
                MMA_BF16(acc[nt], a0, a1, a2, a3, bh0, bh1);
                MMA_BF16(acc[nt], a0, a1, a2, a3, bl0, bl1);
                MMA_BF16(acc[nt], c0r, c1r, c2r, c3r, bh0, bh1);
            }
        }
        __syncthreads();
    }

    // ---- final row sums + bf16 hi/lo write ----
    l0 += __shfl_xor_sync(0xffffffffu, l0, 1);
    l0 += __shfl_xor_sync(0xffffffffu, l0, 2);
    l1 += __shfl_xor_sync(0xffffffffu, l1, 1);
    l1 += __shfl_xor_sync(0xffffffffu, l1, 2);
    float i0 = 1.0f / l0;
    float i1 = 1.0f / l1;

    size_t yr0 = (size_t)qrow0 * 512 + h * 64;
    size_t yr1 = yr0 + (size_t)8 * 512;
    #pragma unroll
    for (int nt = 0; nt < 8; ++nt) {
        int cc = nt * 8 + tig * 2;
        float v00 = acc[nt][0] * i0, v01 = acc[nt][1] * i0;
        float v10 = acc[nt][2] * i1, v11 = acc[nt][3] * i1;
        __nv_bfloat162 h0 = __floats2bfloat162_rn(v00, v01);
        __nv_bfloat162 h1 = __floats2bfloat162_rn(v10, v11);
        __nv_bfloat162 l0v = __floats2bfloat162_rn(v00 - __bfloat162float(h0.x),
                                                   v01 - __bfloat162float(h0.y));
        __nv_bfloat162 l1v = __floats2bfloat162_rn(v10 - __bfloat162float(h1.x),
                                                   v11 - __bfloat162float(h1.y));
        *(uint32_t*)&yh[yr0 + cc] = b2u(h0);
        *(uint32_t*)&yh[yr1 + cc] = b2u(h1);
        *(uint32_t*)&yl[yr0 + cc] = b2u(l0v);
        *(uint32_t*)&yl[yr1 + cc] = b2u(l1v);
    }
}

// ---------------------------------------------------------------------------
// Launch
// ---------------------------------------------------------------------------
extern "C" void kernel_launch(void* const* d_in, const int* in_sizes, int n_in,
                              void* d_out, int out_size) {
    (void)in_sizes; (void)n_in; (void)out_size;
    const float* x_ctx     = (const float*)d_in[0];
    const float* x_query   = (const float*)d_in[1];
    const float* pos_ctx   = (const float*)d_in[2];
    const float* pos_query = (const float*)d_in[3];
    const float* Wq = (const float*)d_in[4];
    const float* bq = (const float*)d_in[5];
    const float* Wk = (const float*)d_in[6];
    const float* bk = (const float*)d_in[7];
    const float* Wv = (const float*)d_in[8];
    const float* bv = (const float*)d_in[9];
    const float* Wo = (const float*)d_in[10];
    const float* bo = (const float*)d_in[11];
    float* out = (float*)d_out;

    float *gv, *gh;
    __nv_bfloat16 *gxqh, *gxql, *gxch, *gxcl, *gwh, *gwl;
    __nv_bfloat16 *gqh, *gql, *gkh, *gkl, *gvth, *gvtl, *gyh, *gyl;
    cudaGetSymbolAddress((void**)&gv,   g_v);
    cudaGetSymbolAddress((void**)&gh,   g_heat);
    cudaGetSymbolAddress((void**)&gxqh, g_xqh);
    cudaGetSymbolAddress((void**)&gxql, g_xql);
    cudaGetSymbolAddress((void**)&gxch, g_xch);
    cudaGetSymbolAddress((void**)&gxcl, g_xcl);
    cudaGetSymbolAddress((void**)&gwh,  g_wh);
    cudaGetSymbolAddress((void**)&gwl,  g_wl);
    cudaGetSymbolAddress((void**)&gqh,  g_qh);
    cudaGetSymbolAddress((void**)&gql,  g_ql);
    cudaGetSymbolAddress((void**)&gkh,  g_kh);
    cudaGetSymbolAddress((void**)&gkl,  g_kl);
    cudaGetSymbolAddress((void**)&gvth, g_vth);
    cudaGetSymbolAddress((void**)&gvtl, g_vtl);
    cudaGetSymbolAddress((void**)&gyh,  g_yh);
    cudaGetSymbolAddress((void**)&gyl,  g_yl);

    cudaFuncSetAttribute(attn_tc,
                         cudaFuncAttributeMaxDynamicSharedMemorySize, ATTN_SMEM_B);

    heat_precompute<<<dim3(NQ, B_), 256>>>(pos_ctx, pos_query, gh);

    // operand splits
    split_bf16<<<(B_ * NQ * CE) / 1024, 256>>>(x_query, gxqh, gxql);
    split_bf16<<<(B_ * NC * CE) / 1024, 256>>>(x_ctx,   gxch, gxcl);
    split_bf16<<<(CE * CE) / 1024, 256>>>(Wq, gwh,               gwl);
    split_bf16<<<(CE * CE) / 1024, 256>>>(Wk, gwh + CE * CE,     gwl + CE * CE);
    split_bf16<<<(CE * CE) / 1024, 256>>>(Wv, gwh + 2 * CE * CE, gwl + 2 * CE * CE);
    split_bf16<<<(CE * CE) / 1024, 256>>>(Wo, gwh + 3 * CE * CE, gwl + 3 * CE * CE);

    // projections: q/k -> bf16 hi/lo directly; v -> fp32 (for transpose)
    gemm_bf16<<<dim3(4, (B_ * NQ) / 128), 256>>>(
        gxqh, gxql, gwh, gwl, bq, nullptr, gqh, gql, 1, SCALE);
    gemm_bf16<<<dim3(4, (B_ * NC) / 128), 256>>>(
        gxch, gxcl, gwh + CE * CE, gwl + CE * CE, bk, nullptr, gkh, gkl, 1, 1.0f);
    gemm_bf16<<<dim3(4, (B_ * NC) / 128), 256>>>(
        gxch, gxcl, gwh + 2 * CE * CE, gwl + 2 * CE * CE, bv, gv, nullptr, nullptr, 0, 1.0f);

    split_v_T<<<dim3(NC / 64, H_, B_), 256>>>(gv, gvth, gvtl);

    attn_tc<<<dim3(NQ / 128, H_, B_), 256, ATTN_SMEM_B>>>(
        gqh, gql, gkh, gkl, gvth, gvtl, gh, gyh, gyl);

    gemm_bf16<<<dim3(4, (B_ * NQ) / 128), 256>>>(
        gyh, gyl, gwh + 3 * CE * CE, gwl + 3 * CE * CE, bo, out, nullptr, nullptr, 0, 1.0f);
}

// round 7
// speedup vs baseline: 3.0282x; 1.3070x over previous
#include <cuda_runtime.h>
#include <cuda_bf16.h>
#include <cstdint>
#include <math.h>

// ---------------------------------------------------------------------------
// Problem constants
// ---------------------------------------------------------------------------
constexpr int B_  = 2;
constexpr int NQ  = 2048;
constexpr int NC  = 4096;
constexpr int CE  = 512;
constexpr int H_  = 8;
constexpr float SCALE  = 0.125f;
constexpr float FOURNU = 0.4f;
constexpr float EPS_   = 1e-6f;

// Pair-interleave permutation within a 16-element k-chunk:
// physical pair slots hold logical pairs in order [0,4,1,5,2,6,3,7].
// Lane tig then reads physical bytes [tig*8, tig*8+8) = logical elements
// {2t,2t+1, 8+2t,8+2t+1} = exactly fragment regs {b0,b1} / {a0,a2}.
__host__ __device__ constexpr int perm16(int e) {
    int lp = e >> 1, o = e & 1;
    int slot = (lp < 4) ? (lp * 2) : ((lp - 4) * 2 + 1);
    return slot * 2 + o;
}

// ---------------------------------------------------------------------------
// Scratch
// ---------------------------------------------------------------------------
__device__ float g_v [B_ * NC * CE];
__device__ float g_heat[(size_t)B_ * NQ * NC];            // 67 MB
__device__ __nv_bfloat16 g_xqh[B_ * NQ * CE];
__device__ __nv_bfloat16 g_xql[B_ * NQ * CE];
__device__ __nv_bfloat16 g_xch[B_ * NC * CE];
__device__ __nv_bfloat16 g_xcl[B_ * NC * CE];
__device__ __nv_bfloat16 g_wh[4 * CE * CE];
__device__ __nv_bfloat16 g_wl[4 * CE * CE];
__device__ __nv_bfloat16 g_qh[B_ * NQ * CE];              // scaled, d-permuted
__device__ __nv_bfloat16 g_ql[B_ * NQ * CE];
__device__ __nv_bfloat16 g_kh[B_ * NC * CE];              // d-permuted
__device__ __nv_bfloat16 g_kl[B_ * NC * CE];
__device__ __nv_bfloat16 g_vth[B_ * NC * CE];             // [b][h][d][c], c-permuted
__device__ __nv_bfloat16 g_vtl[B_ * NC * CE];
__device__ __nv_bfloat16 g_yh[B_ * NQ * CE];              // attn out (logical layout)
__device__ __nv_bfloat16 g_yl[B_ * NQ * CE];

// ---------------------------------------------------------------------------
// helpers
// ---------------------------------------------------------------------------
#define MMA_BF16(d, a0, a1, a2, a3, b0, b1) \
    asm volatile("mma.sync.aligned.m16n8k16.row.col.f32.bf16.bf16.f32 " \
        "{%0,%1,%2,%3}, {%4,%5,%6,%7}, {%8,%9}, {%0,%1,%2,%3};" \
        : "+f"((d)[0]), "+f"((d)[1]), "+f"((d)[2]), "+f"((d)[3]) \
        : "r"(a0), "r"(a1), "r"(a2), "r"(a3), "r"(b0), "r"(b1))

#define CP16(dst, src) \
    asm volatile("cp.async.cg.shared.global [%0], [%1], 16;" \
                 :: "r"(dst), "l"(src))
#define CP_COMMIT() asm volatile("cp.async.commit_group;")

__device__ __forceinline__ uint32_t b2u(__nv_bfloat162 x) {
    return *reinterpret_cast<uint32_t*>(&x);
}
__device__ __forceinline__ uint32_t smem_u32(const void* p) {
    uint32_t a;
    asm("{ .reg .u64 t; cvta.to.shared.u64 t, %1; cvt.u32.u64 %0, t; }"
        : "=r"(a) : "l"(p));
    return a;
}

// ---------------------------------------------------------------------------
// Heat-kernel bias precompute (head-independent)
// ---------------------------------------------------------------------------
__global__ __launch_bounds__(256)
void heat_precompute(const float* __restrict__ pos_c, const float* __restrict__ pos_q,
                     float* __restrict__ heat) {
    const int b  = blockIdx.y;
    const int qi = blockIdx.x;
    const float* pq = pos_q + (size_t)(b * NQ + qi) * 3;
    const float qx = pq[0], qy = pq[1], qt = pq[2];
    float* hrow = heat + ((size_t)b * NQ + qi) * NC;
    for (int ci = threadIdx.x; ci < NC; ci += 256) {
        const float* pc = pos_c + (size_t)(b * NC + ci) * 3;
        float dx = qx - pc[0];
        float dy = qy - pc[1];
        float dt = qt - pc[2];
        float denom = FOURNU * fabsf(dt) + EPS_;
        float dist  = dx * dx + dy * dy;
        hrow[ci] = __expf(-__fdividef(dist, denom));
    }
}

// ---------------------------------------------------------------------------
// bf16 hi/lo split (elementwise)
// ---------------------------------------------------------------------------
__global__ __launch_bounds__(256)
void split_bf16(const float* __restrict__ in, __nv_bfloat16* __restrict__ oh,
                __nv_bfloat16* __restrict__ ol) {
    int i = blockIdx.x * 256 + threadIdx.x;
    float4 v = ((const float4*)in)[i];
    __nv_bfloat162 hA = __floats2bfloat162_rn(v.x, v.y);
    __nv_bfloat162 hB = __floats2bfloat162_rn(v.z, v.w);
    __nv_bfloat162 lA = __floats2bfloat162_rn(v.x - __bfloat162float(hA.x),
                                              v.y - __bfloat162float(hA.y));
    __nv_bfloat162 lB = __floats2bfloat162_rn(v.z - __bfloat162float(hB.x),
                                              v.w - __bfloat162float(hB.y));
    *(uint2*)&oh[(size_t)i * 4] = make_uint2(b2u(hA), b2u(hB));
    *(uint2*)&ol[(size_t)i * 4] = make_uint2(b2u(lA), b2u(lB));
}

// ---------------------------------------------------------------------------
// V: per-head transpose + bf16 split + c-pair-interleave.
// g_v[b][c][h*64+d] -> out[b][h][d][perm(c)]
// ---------------------------------------------------------------------------
__global__ __launch_bounds__(256)
void split_v_T(const float* __restrict__ v, __nv_bfloat16* __restrict__ oh,
               __nv_bfloat16* __restrict__ ol) {
    __shared__ float ts[64][65];
    const int b  = blockIdx.z;
    const int h  = blockIdx.y;
    const int c0 = blockIdx.x * 64;
    const int tid = threadIdx.x;
    #pragma unroll
    for (int t = 0; t < 4; ++t) {
        int idx = tid + t * 256;
        int r   = idx >> 4;
        int d4  = (idx & 15) << 2;
        float4 vv = *(const float4*)&v[(size_t)(b * NC + c0 + r) * 512 + h * 64 + d4];
        ts[d4 + 0][r] = vv.x; ts[d4 + 1][r] = vv.y;
        ts[d4 + 2][r] = vv.z; ts[d4 + 3][r] = vv.w;
    }
    __syncthreads();
    #pragma unroll
    for (int t = 0; t < 4; ++t) {
        int idx = tid + t * 256;
        int d   = idx >> 4;
        int r4  = (idx & 15) << 2;          // logical c offset within tile, 0..60
        size_t orow = ((size_t)(b * H_ + h) * 64 + d) * NC + c0;
        #pragma unroll
        for (int pp = 0; pp < 2; ++pp) {    // two logical pairs
            int cl = r4 + pp * 2;           // even logical position
            float x0 = ts[d][cl], x1 = ts[d][cl + 1];
            __nv_bfloat162 hh = __floats2bfloat162_rn(x0, x1);
            __nv_bfloat162 ll = __floats2bfloat162_rn(x0 - __bfloat162float(hh.x),
                                                      x1 - __bfloat162float(hh.y));
            int cp = (cl & ~15) + perm16(cl & 15);
            *(uint32_t*)&oh[orow + cp] = b2u(hh);
            *(uint32_t*)&ol[orow + cp] = b2u(ll);
        }
    }
}

// ---------------------------------------------------------------------------
// bf16 3-pass GEMM.  mode 0: fp32 out.  mode 1: bf16 hi/lo out with
// (acc+bias)*scale and pair-interleaved column permutation (for Q/K).
// ---------------------------------------------------------------------------
__global__ __launch_bounds__(256, 1)
void gemm_bf16(const __nv_bfloat16* __restrict__ Ah, const __nv_bfloat16* __restrict__ Al,
               const __nv_bfloat16* __restrict__ Bh, const __nv_bfloat16* __restrict__ Bl,
               const float* __restrict__ bias, float* __restrict__ Yf,
               __nv_bfloat16* __restrict__ Ybh, __nv_bfloat16* __restrict__ Ybl,
               int mode, float scale) {
    __shared__ __nv_bfloat16 sA[2][128 * 40];
    __shared__ __nv_bfloat16 sB[2][128 * 40];

    const int tid  = threadIdx.x;
    const int lane = tid & 31;
    const int wid  = tid >> 5;
    const int grp  = lane >> 2;
    const int tig  = lane & 3;
    const int wm   = (wid >> 1) * 32;
    const int wn   = (wid & 1) * 64;
    const int rowBase = blockIdx.y * 128;
    const int colBase = blockIdx.x * 128;

    float acc[2][8][4];
    #pragma unroll
    for (int mt = 0; mt < 2; ++mt)
        #pragma unroll
        for (int nt = 0; nt < 8; ++nt)
            #pragma unroll
            for (int r = 0; r < 4; ++r) acc[mt][nt][r] = 0.f;

    uint4 pa[2][2], pb[2][2];
    #pragma unroll
    for (int t = 0; t < 2; ++t) {
        int u  = tid + t * 256;
        int r  = u >> 2;
        int cu = u & 3;
        size_t ga = (size_t)(rowBase + r) * 512 + cu * 8;
        size_t gb = (size_t)(colBase + r) * 512 + cu * 8;
        pa[0][t] = *(const uint4*)&Ah[ga];
        pa[1][t] = *(const uint4*)&Al[ga];
        pb[0][t] = *(const uint4*)&Bh[gb];
        pb[1][t] = *(const uint4*)&Bl[gb];
    }

    for (int c = 0; c < 16; ++c) {
        __syncthreads();
        #pragma unroll
        for (int t = 0; t < 2; ++t) {
            int u  = tid + t * 256;
            int r  = u >> 2;
            int cu = u & 3;
            int so = r * 40 + cu * 8;
            *(uint4*)&sA[0][so] = pa[0][t];
            *(uint4*)&sA[1][so] = pa[1][t];
            *(uint4*)&sB[0][so] = pb[0][t];
            *(uint4*)&sB[1][so] = pb[1][t];
        }
        __syncthreads();
        if (c < 15) {
            int k0 = (c + 1) * 32;
            #pragma unroll
            for (int t = 0; t < 2; ++t) {
                int u  = tid + t * 256;
                int r  = u >> 2;
                int cu = u & 3;
                size_t ga = (size_t)(rowBase + r) * 512 + k0 + cu * 8;
                size_t gb = (size_t)(colBase + r) * 512 + k0 + cu * 8;
                pa[0][t] = *(const uint4*)&Ah[ga];
                pa[1][t] = *(const uint4*)&Al[ga];
                pb[0][t] = *(const uint4*)&Bh[gb];
                pb[1][t] = *(const uint4*)&Bl[gb];
            }
        }
        #pragma unroll
        for (int sub = 0; sub < 2; ++sub) {
            const int kb = sub * 16 + tig * 2;
            uint32_t ah[2][4], al[2][4];
            #pragma unroll
            for (int mt = 0; mt < 2; ++mt) {
                int r0 = wm + mt * 16 + grp;
                ah[mt][0] = *(uint32_t*)&sA[0][r0 * 40 + kb];
                ah[mt][1] = *(uint32_t*)&sA[0][(r0 + 8) * 40 + kb];
                ah[mt][2] = *(uint32_t*)&sA[0][r0 * 40 + kb + 8];
                ah[mt][3] = *(uint32_t*)&sA[0][(r0 + 8) * 40 + kb + 8];
                al[mt][0] = *(uint32_t*)&sA[1][r0 * 40 + kb];
                al[mt][1] = *(uint32_t*)&sA[1][(r0 + 8) * 40 + kb];
                al[mt][2] = *(uint32_t*)&sA[1][r0 * 40 + kb + 8];
                al[mt][3] = *(uint32_t*)&sA[1][(r0 + 8) * 40 + kb + 8];
            }
            uint32_t bh[8][2], bl[8][2];
            #pragma unroll
            for (int nt = 0; nt < 8; ++nt) {
                int n = wn + nt * 8 + grp;
                bh[nt][0] = *(uint32_t*)&sB[0][n * 40 + kb];
                bh[nt][1] = *(uint32_t*)&sB[0][n * 40 + kb + 8];
                bl[nt][0] = *(uint32_t*)&sB[1][n * 40 + kb];
                bl[nt][1] = *(uint32_t*)&sB[1][n * 40 + kb + 8];
            }
            #pragma unroll
            for (int mt = 0; mt < 2; ++mt)
                #pragma unroll
                for (int nt = 0; nt < 8; ++nt) {
                    MMA_BF16(acc[mt][nt], ah[mt][0], ah[mt][1], ah[mt][2], ah[mt][3],
                             bh[nt][0], bh[nt][1]);
                    MMA_BF16(acc[mt][nt], ah[mt][0], ah[mt][1], ah[mt][2], ah[mt][3],
                             bl[nt][0], bl[nt][1]);
                    MMA_BF16(acc[mt][nt], al[mt][0], al[mt][1], al[mt][2], al[mt][3],
                             bh[nt][0], bh[nt][1]);
                }
        }
    }

    #pragma unroll
    for (int nt = 0; nt < 8; ++nt) {
        int col = colBase + wn + nt * 8 + tig * 2;
        float b0 = __ldg(&bias[col]);
        float b1 = __ldg(&bias[col + 1]);
        #pragma unroll
        for (int mt = 0; mt < 2; ++mt) {
            int row = rowBase + wm + mt * 16 + grp;
            float v00 = acc[mt][nt][0] + b0, v01 = acc[mt][nt][1] + b1;
            float v10 = acc[mt][nt][2] + b0, v11 = acc[mt][nt][3] + b1;
            if (mode == 0) {
                *(float2*)&Yf[(size_t)row       * 512 + col] = make_float2(v00, v01);
                *(float2*)&Yf[(size_t)(row + 8) * 512 + col] = make_float2(v10, v11);
            } else {
                v00 *= scale; v01 *= scale; v10 *= scale; v11 *= scale;
                __nv_bfloat162 h0 = __floats2bfloat162_rn(v00, v01);
                __nv_bfloat162 h1 = __floats2bfloat162_rn(v10, v11);
                __nv_bfloat162 l0 = __floats2bfloat162_rn(v00 - __bfloat162float(h0.x),
                                                          v01 - __bfloat162float(h0.y));
                __nv_bfloat162 l1 = __floats2bfloat162_rn(v10 - __bfloat162float(h1.x),
                                                          v11 - __bfloat162float(h1.y));
                int colp = (col & ~15) + perm16(col & 15);   // pair-interleave
                *(uint32_t*)&Ybh[(size_t)row       * 512 + colp] = b2u(h0);
                *(uint32_t*)&Ybh[(size_t)(row + 8) * 512 + colp] = b2u(h1);
                *(uint32_t*)&Ybl[(size_t)row       * 512 + colp] = b2u(l0);
                *(uint32_t*)&Ybl[(size_t)(row + 8) * 512 + colp] = b2u(l1);
            }
        }
    }
}

// ---------------------------------------------------------------------------
// Tensor-core flash attention.  P kept entirely in registers (C-frag == A-frag
// layout identity).  All K/V fragment loads are LDS.64 via pair-interleaved
// storage.  Row stride 160 B -> conflict-free.
// Smem: buf[2] of 40960 B  {Kh 0 | Kl 10240 | Vh 20480 | Vl 30720}.  Total 81920.
// ---------------------------------------------------------------------------
constexpr int ATTN_SMEM_B = 81920;

__global__ __launch_bounds__(256, 2)
void attn_tc(const __nv_bfloat16* __restrict__ qh, const __nv_bfloat16* __restrict__ ql,
             const __nv_bfloat16* __restrict__ kh, const __nv_bfloat16* __restrict__ kl,
             const __nv_bfloat16* __restrict__ vth, const __nv_bfloat16* __restrict__ vtl,
             const float* __restrict__ heat,
             __nv_bfloat16* __restrict__ yh, __nv_bfloat16* __restrict__ yl) {
    extern __shared__ char smem[];
    const uint32_t sb = smem_u32(smem);

    const int b   = blockIdx.z;
    const int h   = blockIdx.y;
    const int q0  = blockIdx.x * 128;
    const int tid = threadIdx.x;
    const int w    = tid >> 5;
    const int lane = tid & 31;
    const int grp  = lane >> 2;
    const int tig  = lane & 3;

    const int sr  = tid >> 3;
    const int sc8 = tid & 7;

    auto issue_tile = [&](uint32_t bb, int c0) {
        #pragma unroll
        for (int j = 0; j < 2; ++j) {
            int r = sr + j * 32;
            size_t ksrc = (size_t)(b * NC + c0 + r) * 512 + h * 64 + sc8 * 8;
            size_t vsrc = ((size_t)(b * H_ + h) * 64 + r) * NC + c0 + sc8 * 8;
            uint32_t d0 = bb + r * 160 + sc8 * 16;
            CP16(d0,         kh  + ksrc);
            CP16(d0 + 10240, kl  + ksrc);
            CP16(d0 + 20480, vth + vsrc);
            CP16(d0 + 30720, vtl + vsrc);
        }
        CP_COMMIT();
    };

    // ---- Q fragments (permuted gmem -> uint2 loads) ----
    const int qrow0 = b * NQ + q0 + w * 16 + grp;
    uint32_t qfh[4][4], qfl[4][4];
    #pragma unroll
    for (int ks = 0; ks < 4; ++ks) {
        size_t e0 = (size_t)qrow0 * 512 + h * 64 + ks * 16 + tig * 4;
        size_t e1 = e0 + (size_t)8 * 512;
        uint2 h0 = *(const uint2*)(qh + e0);
        uint2 h1 = *(const uint2*)(qh + e1);
        uint2 l0v = *(const uint2*)(ql + e0);
        uint2 l1v = *(const uint2*)(ql + e1);
        qfh[ks][0] = h0.x; qfh[ks][1] = h1.x; qfh[ks][2] = h0.y; qfh[ks][3] = h1.y;
        qfl[ks][0] = l0v.x; qfl[ks][1] = l1v.x; qfl[ks][2] = l0v.y; qfl[ks][3] = l1v.y;
    }

    float acc[8][4];
    #pragma unroll
    for (int nt = 0; nt < 8; ++nt)
        #pragma unroll
        for (int r = 0; r < 4; ++r) acc[nt][r] = 0.f;
    float l0 = 0.f, l1 = 0.f;

    const float* hb0 = heat + (size_t)qrow0 * NC;
    const float* hb1 = hb0 + (size_t)8 * NC;

    issue_tile(sb, 0);

    for (int it = 0; it < 64; ++it) {
        const int cur = it & 1;
        const char* bufc = smem + cur * 40960;
        if (it < 63) issue_tile(sb + (cur ^ 1) * 40960, (it + 1) * 64);
        if (it < 63) asm volatile("cp.async.wait_group 1;" ::: "memory");
        else         asm volatile("cp.async.wait_group 0;" ::: "memory");
        __syncthreads();

        const int c0 = it * 64;
        uint32_t ph[8][2], pl[8][2];

        // ---- QK (3-pass) + exp + pack P in registers ----
        #pragma unroll
        for (int nt = 0; nt < 8; ++nt) {
            float s[4] = {0.f, 0.f, 0.f, 0.f};
            #pragma unroll
            for (int ks = 0; ks < 4; ++ks) {
                int roff = (nt * 8 + grp) * 160 + ks * 32 + tig * 8;
                uint2 kh2 = *(const uint2*)(bufc + roff);
                uint2 kl2 = *(const uint2*)(bufc + 10240 + roff);
                MMA_BF16(s, qfh[ks][0], qfh[ks][1], qfh[ks][2], qfh[ks][3], kh2.x, kh2.y);
                MMA_BF16(s, qfh[ks][0], qfh[ks][1], qfh[ks][2], qfh[ks][3], kl2.x, kl2.y);
                MMA_BF16(s, qfl[ks][0], qfl[ks][1], qfl[ks][2], qfl[ks][3], kh2.x, kh2.y);
            }
            int cc = nt * 8 + tig * 2;
            float2 h0 = *(const float2*)(hb0 + c0 + cc);
            float2 h1 = *(const float2*)(hb1 + c0 + cc);
            float e00 = __expf(s[0] + h0.x);
            float e01 = __expf(s[1] + h0.y);
            float e10 = __expf(s[2] + h1.x);
            float e11 = __expf(s[3] + h1.y);
            l0 += e00 + e01;
            l1 += e10 + e11;
            __nv_bfloat162 p0 = __floats2bfloat162_rn(e00, e01);
            __nv_bfloat162 p1 = __floats2bfloat162_rn(e10, e11);
            __nv_bfloat162 r0 = __floats2bfloat162_rn(e00 - __bfloat162float(p0.x),
                                                      e01 - __bfloat162float(p0.y));
            __nv_bfloat162 r1 = __floats2bfloat162_rn(e10 - __bfloat162float(p1.x),
                                                      e11 - __bfloat162float(p1.y));
            ph[nt][0] = b2u(p0); ph[nt][1] = b2u(p1);
            pl[nt][0] = b2u(r0); pl[nt][1] = b2u(r1);
        }

        // ---- AV (3-pass), P from registers ----
        #pragma unroll
        for (int ks = 0; ks < 4; ++ks) {
            uint32_t a0 = ph[2 * ks][0],     a1 = ph[2 * ks][1];
            uint32_t a2 = ph[2 * ks + 1][0], a3 = ph[2 * ks + 1][1];
            uint32_t c0r = pl[2 * ks][0],     c1r = pl[2 * ks][1];
            uint32_t c2r = pl[2 * ks + 1][0], c3r = pl[2 * ks + 1][1];
            #pragma unroll
            for (int nt = 0; nt < 8; ++nt) {
                int boff = 20480 + (nt * 8 + grp) * 160 + ks * 32 + tig * 8;
                uint2 vh2 = *(const uint2*)(bufc + boff);
                uint2 vl2 = *(const uint2*)(bufc + boff + 10240);
                MMA_BF16(acc[nt], a0, a1, a2, a3, vh2.x, vh2.y);
                MMA_BF16(acc[nt], a0, a1, a2, a3, vl2.x, vl2.y);
                MMA_BF16(acc[nt], c0r, c1r, c2r, c3r, vh2.x, vh2.y);
            }
        }
        __syncthreads();
    }

    // ---- final row sums + bf16 hi/lo write (logical layout) ----
    l0 += __shfl_xor_sync(0xffffffffu, l0, 1);
    l0 += __shfl_xor_sync(0xffffffffu, l0, 2);
    l1 += __shfl_xor_sync(0xffffffffu, l1, 1);
    l1 += __shfl_xor_sync(0xffffffffu, l1, 2);
    float i0 = 1.0f / l0;
    float i1 = 1.0f / l1;

    size_t yr0 = (size_t)qrow0 * 512 + h * 64;
    size_t yr1 = yr0 + (size_t)8 * 512;
    #pragma unroll
    for (int nt = 0; nt < 8; ++nt) {
        int cc = nt * 8 + tig * 2;
        float v00 = acc[nt][0] * i0, v01 = acc[nt][1] * i0;
        float v10 = acc[nt][2] * i1, v11 = acc[nt][3] * i1;
        __nv_bfloat162 h0 = __floats2bfloat162_rn(v00, v01);
        __nv_bfloat162 h1 = __floats2bfloat162_rn(v10, v11);
        __nv_bfloat162 l0v = __floats2bfloat162_rn(v00 - __bfloat162float(h0.x),
                                                   v01 - __bfloat162float(h0.y));
        __nv_bfloat162 l1v = __floats2bfloat162_rn(v10 - __bfloat162float(h1.x),
                                                   v11 - __bfloat162float(h1.y));
        *(uint32_t*)&yh[yr0 + cc] = b2u(h0);
        *(uint32_t*)&yh[yr1 + cc] = b2u(h1);
        *(uint32_t*)&yl[yr0 + cc] = b2u(l0v);
        *(uint32_t*)&yl[yr1 + cc] = b2u(l1v);
    }
}

// ---------------------------------------------------------------------------
// Launch
// ---------------------------------------------------------------------------
extern "C" void kernel_launch(void* const* d_in, const int* in_sizes, int n_in,
                              void* d_out, int out_size) {
    (void)in_sizes; (void)n_in; (void)out_size;
    const float* x_ctx     = (const float*)d_in[0];
    const float* x_query   = (const float*)d_in[1];
    const float* pos_ctx   = (const float*)d_in[2];
    const float* pos_query = (const float*)d_in[3];
    const float* Wq = (const float*)d_in[4];
    const float* bq = (const float*)d_in[5];
    const float* Wk = (const float*)d_in[6];
    const float* bk = (const float*)d_in[7];
    const float* Wv = (const float*)d_in[8];
    const float* bv = (const float*)d_in[9];
    const float* Wo = (const float*)d_in[10];
    const float* bo = (const float*)d_in[11];
    float* out = (float*)d_out;

    float *gv, *gh;
    __nv_bfloat16 *gxqh, *gxql, *gxch, *gxcl, *gwh, *gwl;
    __nv_bfloat16 *gqh, *gql, *gkh, *gkl, *gvth, *gvtl, *gyh, *gyl;
    cudaGetSymbolAddress((void**)&gv,   g_v);
    cudaGetSymbolAddress((void**)&gh,   g_heat);
    cudaGetSymbolAddress((void**)&gxqh, g_xqh);
    cudaGetSymbolAddress((void**)&gxql, g_xql);
    cudaGetSymbolAddress((void**)&gxch, g_xch);
    cudaGetSymbolAddress((void**)&gxcl, g_xcl);
    cudaGetSymbolAddress((void**)&gwh,  g_wh);
    cudaGetSymbolAddress((void**)&gwl,  g_wl);
    cudaGetSymbolAddress((void**)&gqh,  g_qh);
    cudaGetSymbolAddress((void**)&gql,  g_ql);
    cudaGetSymbolAddress((void**)&gkh,  g_kh);
    cudaGetSymbolAddress((void**)&gkl,  g_kl);
    cudaGetSymbolAddress((void**)&gvth, g_vth);
    cudaGetSymbolAddress((void**)&gvtl, g_vtl);
    cudaGetSymbolAddress((void**)&gyh,  g_yh);
    cudaGetSymbolAddress((void**)&gyl,  g_yl);

    cudaFuncSetAttribute(attn_tc,
                         cudaFuncAttributeMaxDynamicSharedMemorySize, ATTN_SMEM_B);

    heat_precompute<<<dim3(NQ, B_), 256>>>(pos_ctx, pos_query, gh);

    split_bf16<<<(B_ * NQ * CE) / 1024, 256>>>(x_query, gxqh, gxql);
    split_bf16<<<(B_ * NC * CE) / 1024, 256>>>(x_ctx,   gxch, gxcl);
    split_bf16<<<(CE * CE) / 1024, 256>>>(Wq, gwh,               gwl);
    split_bf16<<<(CE * CE) / 1024, 256>>>(Wk, gwh + CE * CE,     gwl + CE * CE);
    split_bf16<<<(CE * CE) / 1024, 256>>>(Wv, gwh + 2 * CE * CE, gwl + 2 * CE * CE);
    split_bf16<<<(CE * CE) / 1024, 256>>>(Wo, gwh + 3 * CE * CE, gwl + 3 * CE * CE);

    gemm_bf16<<<dim3(4, (B_ * NQ) / 128), 256>>>(
        gxqh, gxql, gwh, gwl, bq, nullptr, gqh, gql, 1, SCALE);
    gemm_bf16<<<dim3(4, (B_ * NC) / 128), 256>>>(
        gxch, gxcl, gwh + CE * CE, gwl + CE * CE, bk, nullptr, gkh, gkl, 1, 1.0f);
    gemm_bf16<<<dim3(4, (B_ * NC) / 128), 256>>>(
        gxch, gxcl, gwh + 2 * CE * CE, gwl + 2 * CE * CE, bv, gv, nullptr, nullptr, 0, 1.0f);

    split_v_T<<<dim3(NC / 64, H_, B_), 256>>>(gv, gvth, gvtl);

    attn_tc<<<dim3(NQ / 128, H_, B_), 256, ATTN_SMEM_B>>>(
        gqh, gql, gkh, gkl, gvth, gvtl, gh, gyh, gyl);

    gemm_bf16<<<dim3(4, (B_ * NQ) / 128), 256>>>(
        gyh, gyl, gwh + 3 * CE * CE, gwl + 3 * CE * CE, bo, out, nullptr, nullptr, 0, 1.0f);
}

// round 8
// speedup vs baseline: 3.0854x; 1.0189x over previous
#include <cuda_runtime.h>
#include <cuda_bf16.h>
#include <cstdint>
#include <math.h>

// ---------------------------------------------------------------------------
// Problem constants
// ---------------------------------------------------------------------------
constexpr int B_  = 2;
constexpr int NQ  = 2048;
constexpr int NC  = 4096;
constexpr int CE  = 512;
constexpr int H_  = 8;
constexpr float SCALE  = 0.125f;
constexpr float FOURNU = 0.4f;
constexpr float EPS_   = 1e-6f;

// Pair-interleave permutation within a 16-element k-chunk:
// physical slot order of logical pairs is [0,4,1,5,2,6,3,7], so lane tig's
// 8-byte read at phys elem tig*4 returns logical {2t,2t+1, 8+2t,8+2t+1}
// = exactly mma fragment regs (b0,b1) / (a0,a2).
__host__ __device__ constexpr int perm16(int e) {
    int lp = e >> 1, o = e & 1;
    int slot = (lp < 4) ? (lp * 2) : ((lp - 4) * 2 + 1);
    return slot * 2 + o;
}

// ---------------------------------------------------------------------------
// Scratch
// ---------------------------------------------------------------------------
__device__ float g_v [B_ * NC * CE];
__device__ float g_heat[(size_t)B_ * NQ * NC];            // 67 MB
__device__ __nv_bfloat16 g_xqh[B_ * NQ * CE];             // k-permuted
__device__ __nv_bfloat16 g_xql[B_ * NQ * CE];
__device__ __nv_bfloat16 g_xch[B_ * NC * CE];             // k-permuted
__device__ __nv_bfloat16 g_xcl[B_ * NC * CE];
__device__ __nv_bfloat16 g_wh[4 * CE * CE];               // k-permuted
__device__ __nv_bfloat16 g_wl[4 * CE * CE];
__device__ __nv_bfloat16 g_qh[B_ * NQ * CE];              // scaled, d-permuted
__device__ __nv_bfloat16 g_ql[B_ * NQ * CE];
__device__ __nv_bfloat16 g_kh[B_ * NC * CE];              // d-permuted
__device__ __nv_bfloat16 g_kl[B_ * NC * CE];
__device__ __nv_bfloat16 g_vth[B_ * NC * CE];             // [b][h][d][c], c-permuted
__device__ __nv_bfloat16 g_vtl[B_ * NC * CE];
__device__ __nv_bfloat16 g_yh[B_ * NQ * CE];              // attn out, d-permuted
__device__ __nv_bfloat16 g_yl[B_ * NQ * CE];

// ---------------------------------------------------------------------------
// helpers
// ---------------------------------------------------------------------------
#define MMA_BF16(d, a0, a1, a2, a3, b0, b1) \
    asm volatile("mma.sync.aligned.m16n8k16.row.col.f32.bf16.bf16.f32 " \
        "{%0,%1,%2,%3}, {%4,%5,%6,%7}, {%8,%9}, {%0,%1,%2,%3};" \
        : "+f"((d)[0]), "+f"((d)[1]), "+f"((d)[2]), "+f"((d)[3]) \
        : "r"(a0), "r"(a1), "r"(a2), "r"(a3), "r"(b0), "r"(b1))

#define CP16(dst, src) \
    asm volatile("cp.async.cg.shared.global [%0], [%1], 16;" \
                 :: "r"(dst), "l"(src))
#define CP_COMMIT() asm volatile("cp.async.commit_group;")

__device__ __forceinline__ uint32_t b2u(__nv_bfloat162 x) {
    return *reinterpret_cast<uint32_t*>(&x);
}
__device__ __forceinline__ uint32_t smem_u32(const void* p) {
    uint32_t a;
    asm("{ .reg .u64 t; cvta.to.shared.u64 t, %1; cvt.u32.u64 %0, t; }"
        : "=r"(a) : "l"(p));
    return a;
}

// ---------------------------------------------------------------------------
// Heat-kernel bias precompute (head-independent)
// ---------------------------------------------------------------------------
__global__ __launch_bounds__(256)
void heat_precompute(const float* __restrict__ pos_c, const float* __restrict__ pos_q,
                     float* __restrict__ heat) {
    const int b  = blockIdx.y;
    const int qi = blockIdx.x;
    const float* pq = pos_q + (size_t)(b * NQ + qi) * 3;
    const float qx = pq[0], qy = pq[1], qt = pq[2];
    float* hrow = heat + ((size_t)b * NQ + qi) * NC;
    for (int ci = threadIdx.x; ci < NC; ci += 256) {
        const float* pc = pos_c + (size_t)(b * NC + ci) * 3;
        float dx = qx - pc[0];
        float dy = qy - pc[1];
        float dt = qt - pc[2];
        float denom = FOURNU * fabsf(dt) + EPS_;
        float dist  = dx * dx + dy * dy;
        hrow[ci] = __expf(-__fdividef(dist, denom));
    }
}

// ---------------------------------------------------------------------------
// bf16 hi/lo split, k-pair-interleaved output
// ---------------------------------------------------------------------------
__global__ __launch_bounds__(256)
void split_bf16(const float* __restrict__ in, __nv_bfloat16* __restrict__ oh,
                __nv_bfloat16* __restrict__ ol) {
    int i = blockIdx.x * 256 + threadIdx.x;
    float4 v = ((const float4*)in)[i];
    __nv_bfloat162 hA = __floats2bfloat162_rn(v.x, v.y);
    __nv_bfloat162 hB = __floats2bfloat162_rn(v.z, v.w);
    __nv_bfloat162 lA = __floats2bfloat162_rn(v.x - __bfloat162float(hA.x),
                                              v.y - __bfloat162float(hA.y));
    __nv_bfloat162 lB = __floats2bfloat162_rn(v.z - __bfloat162float(hB.x),
                                              v.w - __bfloat162float(hB.y));
    size_t e = (size_t)i * 4;
    size_t base = e & ~(size_t)15;
    int lp0 = (int)(e & 15) >> 1;                 // 0,2,4,6
    int s0 = (lp0 < 4) ? lp0 * 2 : (lp0 - 4) * 2 + 1;
    int lp1 = lp0 + 1;                            // 1,3,5,7
    int s1 = (lp1 < 4) ? lp1 * 2 : (lp1 - 4) * 2 + 1;
    *(uint32_t*)&oh[base + s0 * 2] = b2u(hA);
    *(uint32_t*)&oh[base + s1 * 2] = b2u(hB);
    *(uint32_t*)&ol[base + s0 * 2] = b2u(lA);
    *(uint32_t*)&ol[base + s1 * 2] = b2u(lB);
}

// ---------------------------------------------------------------------------
// V: per-head transpose + bf16 split + c-pair-interleave.
// ---------------------------------------------------------------------------
__global__ __launch_bounds__(256)
void split_v_T(const float* __restrict__ v, __nv_bfloat16* __restrict__ oh,
               __nv_bfloat16* __restrict__ ol) {
    __shared__ float ts[64][65];
    const int b  = blockIdx.z;
    const int h  = blockIdx.y;
    const int c0 = blockIdx.x * 64;
    const int tid = threadIdx.x;
    #pragma unroll
    for (int t = 0; t < 4; ++t) {
        int idx = tid + t * 256;
        int r   = idx >> 4;
        int d4  = (idx & 15) << 2;
        float4 vv = *(const float4*)&v[(size_t)(b * NC + c0 + r) * 512 + h * 64 + d4];
        ts[d4 + 0][r] = vv.x; ts[d4 + 1][r] = vv.y;
        ts[d4 + 2][r] = vv.z; ts[d4 + 3][r] = vv.w;
    }
    __syncthreads();
    #pragma unroll
    for (int t = 0; t < 4; ++t) {
        int idx = tid + t * 256;
        int d   = idx >> 4;
        int r4  = (idx & 15) << 2;
        size_t orow = ((size_t)(b * H_ + h) * 64 + d) * NC + c0;
        #pragma unroll
        for (int pp = 0; pp < 2; ++pp) {
            int cl = r4 + pp * 2;
            float x0 = ts[d][cl], x1 = ts[d][cl + 1];
            __nv_bfloat162 hh = __floats2bfloat162_rn(x0, x1);
            __nv_bfloat162 ll = __floats2bfloat162_rn(x0 - __bfloat162float(hh.x),
                                                      x1 - __bfloat162float(hh.y));
            int cp = (cl & ~15) + perm16(cl & 15);
            *(uint32_t*)&oh[orow + cp] = b2u(hh);
            *(uint32_t*)&ol[orow + cp] = b2u(ll);
        }
    }
}

// ---------------------------------------------------------------------------
// bf16 3-pass GEMM v2.  128x64 CTA tile, BK=32, cp.async double-buffered,
// pair-interleaved operands -> all LDS.64 frags, 2 CTA/SM.
// Smem per buffer (bytes): Ah 0 (128x48) | Al 12288 | Bh 24576 (64x48) | Bl 30720
// Buffer stride 36864, total 73728.  Row stride 48 elems = 96 B (bank stride
// 24 -> conflict-free for grp*24+tig*2 pattern).
// mode 0: fp32 out.  mode 1: (acc+bias)*scale -> bf16 hi/lo, k-permuted cols.
// ---------------------------------------------------------------------------
constexpr int GEMM_SMEM_B = 73728;

__global__ __launch_bounds__(256, 2)
void gemm_bf16(const __nv_bfloat16* __restrict__ Ah, const __nv_bfloat16* __restrict__ Al,
               const __nv_bfloat16* __restrict__ Bh, const __nv_bfloat16* __restrict__ Bl,
               const float* __restrict__ bias, float* __restrict__ Yf,
               __nv_bfloat16* __restrict__ Ybh, __nv_bfloat16* __restrict__ Ybl,
               int mode, float scale) {
    extern __shared__ char gsm[];
    const uint32_t sb = smem_u32(gsm);

    const int tid  = threadIdx.x;
    const int lane = tid & 31;
    const int wid  = tid >> 5;
    const int grp  = lane >> 2;
    const int tig  = lane & 3;
    const int wm   = (wid >> 1) * 32;     // 4 M-warps
    const int wn   = (wid & 1) * 32;      // 2 N-warps
    const int rowBase = blockIdx.y * 128;
    const int colBase = blockIdx.x * 64;

    const int ar = tid >> 2;              // A row 0..63 (+64 via t)
    const int ac = tid & 3;               // chunk
    const int br = tid >> 2;              // B row 0..63
    // B uses same mapping (64 rows x 4 chunks = 256)

    auto issue = [&](uint32_t bb, int k0) {
        #pragma unroll
        for (int t = 0; t < 2; ++t) {
            int r = ar + t * 64;
            size_t src = (size_t)(rowBase + r) * 512 + k0 + ac * 8;
            uint32_t dst = bb + r * 96 + ac * 16;
            CP16(dst,         Ah + src);
            CP16(dst + 12288, Al + src);
        }
        {
            size_t src = (size_t)(colBase + br) * 512 + k0 + ac * 8;
            uint32_t dst = bb + 24576 + br * 96 + ac * 16;
            CP16(dst,        Bh + src);
            CP16(dst + 6144, Bl + src);
        }
        CP_COMMIT();
    };

    float acc[2][4][4];
    #pragma unroll
    for (int mt = 0; mt < 2; ++mt)
        #pragma unroll
        for (int nt = 0; nt < 4; ++nt)
            #pragma unroll
            for (int r = 0; r < 4; ++r) acc[mt][nt][r] = 0.f;

    issue(sb, 0);

    for (int c = 0; c < 16; ++c) {
        const int cur = c & 1;
        const char* bufc = gsm + cur * 36864;
        if (c < 15) issue(sb + (cur ^ 1) * 36864, (c + 1) * 32);
        if (c < 15) asm volatile("cp.async.wait_group 1;" ::: "memory");
        else        asm volatile("cp.async.wait_group 0;" ::: "memory");
        __syncthreads();

        #pragma unroll
        for (int sub = 0; sub < 2; ++sub) {
            const int kbyte = sub * 32 + tig * 8;
            uint32_t ah[2][4], al[2][4];
            #pragma unroll
            for (int mt = 0; mt < 2; ++mt) {
                int r0 = wm + mt * 16 + grp;
                uint2 h0 = *(const uint2*)(bufc + r0 * 96 + kbyte);
                uint2 h1 = *(const uint2*)(bufc + (r0 + 8) * 96 + kbyte);
                uint2 l0 = *(const uint2*)(bufc + 12288 + r0 * 96 + kbyte);
                uint2 l1 = *(const uint2*)(bufc + 12288 + (r0 + 8) * 96 + kbyte);
                ah[mt][0] = h0.x; ah[mt][1] = h1.x; ah[mt][2] = h0.y; ah[mt][3] = h1.y;
                al[mt][0] = l0.x; al[mt][1] = l1.x; al[mt][2] = l0.y; al[mt][3] = l1.y;
            }
            #pragma unroll
            for (int nt = 0; nt < 4; ++nt) {
                int n = wn + nt * 8 + grp;
                uint2 bh2 = *(const uint2*)(bufc + 24576 + n * 96 + kbyte);
                uint2 bl2 = *(const uint2*)(bufc + 30720 + n * 96 + kbyte);
                #pragma unroll
                for (int mt = 0; mt < 2; ++mt) {
                    MMA_BF16(acc[mt][nt], ah[mt][0], ah[mt][1], ah[mt][2], ah[mt][3],
                             bh2.x, bh2.y);
                    MMA_BF16(acc[mt][nt], ah[mt][0], ah[mt][1], ah[mt][2], ah[mt][3],
                             bl2.x, bl2.y);
                    MMA_BF16(acc[mt][nt], al[mt][0], al[mt][1], al[mt][2], al[mt][3],
                             bh2.x, bh2.y);
                }
            }
        }
        __syncthreads();
    }

    #pragma unroll
    for (int nt = 0; nt < 4; ++nt) {
        int col = colBase + wn + nt * 8 + tig * 2;
        float b0 = __ldg(&bias[col]);
        float b1 = __ldg(&bias[col + 1]);
        #pragma unroll
        for (int mt = 0; mt < 2; ++mt) {
            int row = rowBase + wm + mt * 16 + grp;
            float v00 = acc[mt][nt][0] + b0, v01 = acc[mt][nt][1] + b1;
            float v10 = acc[mt][nt][2] + b0, v11 = acc[mt][nt][3] + b1;
            if (mode == 0) {
                *(float2*)&Yf[(size_t)row       * 512 + col] = make_float2(v00, v01);
                *(float2*)&Yf[(size_t)(row + 8) * 512 + col] = make_float2(v10, v11);
            } else {
                v00 *= scale; v01 *= scale; v10 *= scale; v11 *= scale;
                __nv_bfloat162 h0 = __floats2bfloat162_rn(v00, v01);
                __nv_bfloat162 h1 = __floats2bfloat162_rn(v10, v11);
                __nv_bfloat162 l0 = __floats2bfloat162_rn(v00 - __bfloat162float(h0.x),
                                                          v01 - __bfloat162float(h0.y));
                __nv_bfloat162 l1 = __floats2bfloat162_rn(v10 - __bfloat162float(h1.x),
                                                          v11 - __bfloat162float(h1.y));
                int colp = (col & ~15) + perm16(col & 15);
                *(uint32_t*)&Ybh[(size_t)row       * 512 + colp] = b2u(h0);
                *(uint32_t*)&Ybh[(size_t)(row + 8) * 512 + colp] = b2u(h1);
                *(uint32_t*)&Ybl[(size_t)row       * 512 + colp] = b2u(l0);
                *(uint32_t*)&Ybl[(size_t)(row + 8) * 512 + colp] = b2u(l1);
            }
        }
    }
}

// ---------------------------------------------------------------------------
// Tensor-core flash attention (unchanged from R7 except permuted y epilogue).
// ---------------------------------------------------------------------------
constexpr int ATTN_SMEM_B = 81920;

__global__ __launch_bounds__(256, 2)
void attn_tc(const __nv_bfloat16* __restrict__ qh, const __nv_bfloat16* __restrict__ ql,
             const __nv_bfloat16* __restrict__ kh, const __nv_bfloat16* __restrict__ kl,
             const __nv_bfloat16* __restrict__ vth, const __nv_bfloat16* __restrict__ vtl,
             const float* __restrict__ heat,
             __nv_bfloat16* __restrict__ yh, __nv_bfloat16* __restrict__ yl) {
    extern __shared__ char smem[];
    const uint32_t sb = smem_u32(smem);

    const int b   = blockIdx.z;
    const int h   = blockIdx.y;
    const int q0  = blockIdx.x * 128;
    const int tid = threadIdx.x;
    const int w    = tid >> 5;
    const int lane = tid & 31;
    const int grp  = lane >> 2;
    const int tig  = lane & 3;

    const int sr  = tid >> 3;
    const int sc8 = tid & 7;

    auto issue_tile = [&](uint32_t bb, int c0) {
        #pragma unroll
        for (int j = 0; j < 2; ++j) {
            int r = sr + j * 32;
            size_t ksrc = (size_t)(b * NC + c0 + r) * 512 + h * 64 + sc8 * 8;
            size_t vsrc = ((size_t)(b * H_ + h) * 64 + r) * NC + c0 + sc8 * 8;
            uint32_t d0 = bb + r * 160 + sc8 * 16;
            CP16(d0,         kh  + ksrc);
            CP16(d0 + 10240, kl  + ksrc);
            CP16(d0 + 20480, vth + vsrc);
            CP16(d0 + 30720, vtl + vsrc);
        }
        CP_COMMIT();
    };

    const int qrow0 = b * NQ + q0 + w * 16 + grp;
    uint32_t qfh[4][4], qfl[4][4];
    #pragma unroll
    for (int ks = 0; ks < 4; ++ks) {
        size_t e0 = (size_t)qrow0 * 512 + h * 64 + ks * 16 + tig * 4;
        size_t e1 = e0 + (size_t)8 * 512;
        uint2 h0 = *(const uint2*)(qh + e0);
        uint2 h1 = *(const uint2*)(qh + e1);
        uint2 l0v = *(const uint2*)(ql + e0);
        uint2 l1v = *(const uint2*)(ql + e1);
        qfh[ks][0] = h0.x; qfh[ks][1] = h1.x; qfh[ks][2] = h0.y; qfh[ks][3] = h1.y;
        qfl[ks][0] = l0v.x; qfl[ks][1] = l1v.x; qfl[ks][2] = l0v.y; qfl[ks][3] = l1v.y;
    }

    float acc[8][4];
    #pragma unroll
    for (int nt = 0; nt < 8; ++nt)
        #pragma unroll
        for (int r = 0; r < 4; ++r) acc[nt][r] = 0.f;
    float l0 = 0.f, l1 = 0.f;

    const float* hb0 = heat + (size_t)qrow0 * NC;
    const float* hb1 = hb0 + (size_t)8 * NC;

    issue_tile(sb, 0);

    for (int it = 0; it < 64; ++it) {
        const int cur = it & 1;
        const char* bufc = smem + cur * 40960;
        if (it < 63) issue_tile(sb + (cur ^ 1) * 40960, (it + 1) * 64);
        if (it < 63) asm volatile("cp.async.wait_group 1;" ::: "memory");
        else         asm volatile("cp.async.wait_group 0;" ::: "memory");
        __syncthreads();

        const int c0 = it * 64;
        uint32_t ph[8][2], pl[8][2];

        #pragma unroll
        for (int nt = 0; nt < 8; ++nt) {
            float s[4] = {0.f, 0.f, 0.f, 0.f};
            #pragma unroll
            for (int ks = 0; ks < 4; ++ks) {
                int roff = (nt * 8 + grp) * 160 + ks * 32 + tig * 8;
                uint2 kh2 = *(const uint2*)(bufc + roff);
                uint2 kl2 = *(const uint2*)(bufc + 10240 + roff);
                MMA_BF16(s, qfh[ks][0], qfh[ks][1], qfh[ks][2], qfh[ks][3], kh2.x, kh2.y);
                MMA_BF16(s, qfh[ks][0], qfh[ks][1], qfh[ks][2], qfh[ks][3], kl2.x, kl2.y);
                MMA_BF16(s, qfl[ks][0], qfl[ks][1], qfl[ks][2], qfl[ks][3], kh2.x, kh2.y);
            }
            int cc = nt * 8 + tig * 2;
            float2 h0 = *(const float2*)(hb0 + c0 + cc);
            float2 h1 = *(const float2*)(hb1 + c0 + cc);
            float e00 = __expf(s[0] + h0.x);
            float e01 = __expf(s[1] + h0.y);
            float e10 = __expf(s[2] + h1.x);
            float e11 = __expf(s[3] + h1.y);
            l0 += e00 + e01;
            l1 += e10 + e11;
            __nv_bfloat162 p0 = __floats2bfloat162_rn(e00, e01);
            __nv_bfloat162 p1 = __floats2bfloat162_rn(e10, e11);
            __nv_bfloat162 r0 = __floats2bfloat162_rn(e00 - __bfloat162float(p0.x),
                                                      e01 - __bfloat162float(p0.y));
            __nv_bfloat162 r1 = __floats2bfloat162_rn(e10 - __bfloat162float(p1.x),
                                                      e11 - __bfloat162float(p1.y));
            ph[nt][0] = b2u(p0); ph[nt][1] = b2u(p1);
            pl[nt][0] = b2u(r0); pl[nt][1] = b2u(r1);
        }

        #pragma unroll
        for (int ks = 0; ks < 4; ++ks) {
            uint32_t a0 = ph[2 * ks][0],     a1 = ph[2 * ks][1];
            uint32_t a2 = ph[2 * ks + 1][0], a3 = ph[2 * ks + 1][1];
            uint32_t c0r = pl[2 * ks][0],     c1r = pl[2 * ks][1];
            uint32_t c2r = pl[2 * ks + 1][0], c3r = pl[2 * ks + 1][1];
            #pragma unroll
            for (int nt = 0; nt < 8; ++nt) {
                int boff = 20480 + (nt * 8 + grp) * 160 + ks * 32 + tig * 8;
                uint2 vh2 = *(const uint2*)(bufc + boff);
                uint2 vl2 = *(const uint2*)(bufc + boff + 10240);
                MMA_BF16(acc[nt], a0, a1, a2, a3, vh2.x, vh2.y);
                MMA_BF16(acc[nt], a0, a1, a2, a3, vl2.x, vl2.y);
                MMA_BF16(acc[nt], c0r, c1r, c2r, c3r, vh2.x, vh2.y);
            }
        }
        __syncthreads();
    }

    l0 += __shfl_xor_sync(0xffffffffu, l0, 1);
    l0 += __shfl_xor_sync(0xffffffffu, l0, 2);
    l1 += __shfl_xor_sync(0xffffffffu, l1, 1);
    l1 += __shfl_xor_sync(0xffffffffu, l1, 2);
    float i0 = 1.0f / l0;
    float i1 = 1.0f / l1;

    size_t yr0 = (size_t)qrow0 * 512 + h * 64;
    size_t yr1 = yr0 + (size_t)8 * 512;
    #pragma unroll
    for (int nt = 0; nt < 8; ++nt) {
        // permuted within-16 position so y feeds gemm A operand directly
        int ccp = (nt >> 1) * 16 + (nt & 1) * 2 + tig * 4;
        float v00 = acc[nt][0] * i0, v01 = acc[nt][1] * i0;
        float v10 = acc[nt][2] * i1, v11 = acc[nt][3] * i1;
        __nv_bfloat162 h0 = __floats2bfloat162_rn(v00, v01);
        __nv_bfloat162 h1 = __floats2bfloat162_rn(v10, v11);
        __nv_bfloat162 l0v = __floats2bfloat162_rn(v00 - __bfloat162float(h0.x),
                                                   v01 - __bfloat162float(h0.y));
        __nv_bfloat162 l1v = __floats2bfloat162_rn(v10 - __bfloat162float(h1.x),
                                                   v11 - __bfloat162float(h1.y));
        *(uint32_t*)&yh[yr0 + ccp] = b2u(h0);
        *(uint32_t*)&yh[yr1 + ccp] = b2u(h1);
        *(uint32_t*)&yl[yr0 + ccp] = b2u(l0v);
        *(uint32_t*)&yl[yr1 + ccp] = b2u(l1v);
    }
}

// ---------------------------------------------------------------------------
// Launch
// ---------------------------------------------------------------------------
extern "C" void kernel_launch(void* const* d_in, const int* in_sizes, int n_in,
                              void* d_out, int out_size) {
    (void)in_sizes; (void)n_in; (void)out_size;
    const float* x_ctx     = (const float*)d_in[0];
    const float* x_query   = (const float*)d_in[1];
    const float* pos_ctx   = (const float*)d_in[2];
    const float* pos_query = (const float*)d_in[3];
    const float* Wq = (const float*)d_in[4];
    const float* bq = (const float*)d_in[5];
    const float* Wk = (const float*)d_in[6];
    const float* bk = (const float*)d_in[7];
    const float* Wv = (const float*)d_in[8];
    const float* bv = (const float*)d_in[9];
    const float* Wo = (const float*)d_in[10];
    const float* bo = (const float*)d_in[11];
    float* out = (float*)d_out;

    float *gv, *gh;
    __nv_bfloat16 *gxqh, *gxql, *gxch, *gxcl, *gwh, *gwl;
    __nv_bfloat16 *gqh, *gql, *gkh, *gkl, *gvth, *gvtl, *gyh, *gyl;
    cudaGetSymbolAddress((void**)&gv,   g_v);
    cudaGetSymbolAddress((void**)&gh,   g_heat);
    cudaGetSymbolAddress((void**)&gxqh, g_xqh);
    cudaGetSymbolAddress((void**)&gxql, g_xql);
    cudaGetSymbolAddress((void**)&gxch, g_xch);
    cudaGetSymbolAddress((void**)&gxcl, g_xcl);
    cudaGetSymbolAddress((void**)&gwh,  g_wh);
    cudaGetSymbolAddress((void**)&gwl,  g_wl);
    cudaGetSymbolAddress((void**)&gqh,  g_qh);
    cudaGetSymbolAddress((void**)&gql,  g_ql);
    cudaGetSymbolAddress((void**)&gkh,  g_kh);
    cudaGetSymbolAddress((void**)&gkl,  g_kl);
    cudaGetSymbolAddress((void**)&gvth, g_vth);
    cudaGetSymbolAddress((void**)&gvtl, g_vtl);
    cudaGetSymbolAddress((void**)&gyh,  g_yh);
    cudaGetSymbolAddress((void**)&gyl,  g_yl);

    cudaFuncSetAttribute(attn_tc,
                         cudaFuncAttributeMaxDynamicSharedMemorySize, ATTN_SMEM_B);
    cudaFuncSetAttribute(gemm_bf16,
                         cudaFuncAttributeMaxDynamicSharedMemorySize, GEMM_SMEM_B);

    heat_precompute<<<dim3(NQ, B_), 256>>>(pos_ctx, pos_query, gh);

    split_bf16<<<(B_ * NQ * CE) / 1024, 256>>>(x_query, gxqh, gxql);
    split_bf16<<<(B_ * NC * CE) / 1024, 256>>>(x_ctx,   gxch, gxcl);
    split_bf16<<<(CE * CE) / 1024, 256>>>(Wq, gwh,               gwl);
    split_bf16<<<(CE * CE) / 1024, 256>>>(Wk, gwh + CE * CE,     gwl + CE * CE);
    split_bf16<<<(CE * CE) / 1024, 256>>>(Wv, gwh + 2 * CE * CE, gwl + 2 * CE * CE);
    split_bf16<<<(CE * CE) / 1024, 256>>>(Wo, gwh + 3 * CE * CE, gwl + 3 * CE * CE);

    gemm_bf16<<<dim3(8, (B_ * NQ) / 128), 256, GEMM_SMEM_B>>>(
        gxqh, gxql, gwh, gwl, bq, nullptr, gqh, gql, 1, SCALE);
    gemm_bf16<<<dim3(8, (B_ * NC) / 128), 256, GEMM_SMEM_B>>>(
        gxch, gxcl, gwh + CE * CE, gwl + CE * CE, bk, nullptr, gkh, gkl, 1, 1.0f);
    gemm_bf16<<<dim3(8, (B_ * NC) / 128), 256, GEMM_SMEM_B>>>(
        gxch, gxcl, gwh + 2 * CE * CE, gwl + 2 * CE * CE, bv, gv, nullptr, nullptr, 0, 1.0f);

    split_v_T<<<dim3(NC / 64, H_, B_), 256>>>(gv, gvth, gvtl);

    attn_tc<<<dim3(NQ / 128, H_, B_), 256, ATTN_SMEM_B>>>(
        gqh, gql, gkh, gkl, gvth, gvtl, gh, gyh, gyl);

    gemm_bf16<<<dim3(8, (B_ * NQ) / 128), 256, GEMM_SMEM_B>>>(
        gyh, gyl, gwh + 3 * CE * CE, gwl + 3 * CE * CE, bo, out, nullptr, nullptr, 0, 1.0f);
}

// round 9
// speedup vs baseline: 3.1720x; 1.0281x over previous
#include <cuda_runtime.h>
#include <cuda_bf16.h>
#include <cstdint>
#include <math.h>

// ---------------------------------------------------------------------------
// Problem constants
// ---------------------------------------------------------------------------
constexpr int B_  = 2;
constexpr int NQ  = 2048;
constexpr int NC  = 4096;
constexpr int CE  = 512;
constexpr int H_  = 8;
constexpr float SCALE  = 0.125f;
constexpr float FOURNU = 0.4f;
constexpr float EPS_   = 1e-6f;

// Pair-interleave permutation within a 16-element k-chunk (see R7/R8).
__host__ __device__ constexpr int perm16(int e) {
    int lp = e >> 1, o = e & 1;
    int slot = (lp < 4) ? (lp * 2) : ((lp - 4) * 2 + 1);
    return slot * 2 + o;
}

// ---------------------------------------------------------------------------
// Scratch
// ---------------------------------------------------------------------------
__device__ float g_v [B_ * NC * CE];
__device__ float g_heat[(size_t)B_ * NQ * NC];            // 67 MB
__device__ __nv_bfloat16 g_xqh[B_ * NQ * CE];             // k-permuted
__device__ __nv_bfloat16 g_xql[B_ * NQ * CE];
__device__ __nv_bfloat16 g_xch[B_ * NC * CE];
__device__ __nv_bfloat16 g_xcl[B_ * NC * CE];
__device__ __nv_bfloat16 g_wh[4 * CE * CE];
__device__ __nv_bfloat16 g_wl[4 * CE * CE];
__device__ __nv_bfloat16 g_qh[B_ * NQ * CE];              // scaled, d-permuted
__device__ __nv_bfloat16 g_ql[B_ * NQ * CE];
__device__ __nv_bfloat16 g_kh[B_ * NC * CE];              // d-permuted
__device__ __nv_bfloat16 g_kl[B_ * NC * CE];
__device__ __nv_bfloat16 g_vth[B_ * NC * CE];             // [b][h][d][c], c-permuted
__device__ __nv_bfloat16 g_vtl[B_ * NC * CE];
__device__ __nv_bfloat16 g_yh[B_ * NQ * CE];              // attn out, d-permuted
__device__ __nv_bfloat16 g_yl[B_ * NQ * CE];

// ---------------------------------------------------------------------------
// helpers
// ---------------------------------------------------------------------------
#define MMA_BF16(d, a0, a1, a2, a3, b0, b1) \
    asm volatile("mma.sync.aligned.m16n8k16.row.col.f32.bf16.bf16.f32 " \
        "{%0,%1,%2,%3}, {%4,%5,%6,%7}, {%8,%9}, {%0,%1,%2,%3};" \
        : "+f"((d)[0]), "+f"((d)[1]), "+f"((d)[2]), "+f"((d)[3]) \
        : "r"(a0), "r"(a1), "r"(a2), "r"(a3), "r"(b0), "r"(b1))

#define CP16(dst, src) \
    asm volatile("cp.async.cg.shared.global [%0], [%1], 16;" \
                 :: "r"(dst), "l"(src))
#define CP_COMMIT() asm volatile("cp.async.commit_group;")

__device__ __forceinline__ uint32_t b2u(__nv_bfloat162 x) {
    return *reinterpret_cast<uint32_t*>(&x);
}
__device__ __forceinline__ uint32_t smem_u32(const void* p) {
    uint32_t a;
    asm("{ .reg .u64 t; cvta.to.shared.u64 t, %1; cvt.u32.u64 %0, t; }"
        : "=r"(a) : "l"(p));
    return a;
}

// ---------------------------------------------------------------------------
// Heat-kernel bias precompute (head-independent)
// ---------------------------------------------------------------------------
__global__ __launch_bounds__(256)
void heat_precompute(const float* __restrict__ pos_c, const float* __restrict__ pos_q,
                     float* __restrict__ heat) {
    const int b  = blockIdx.y;
    const int qi = blockIdx.x;
    const float* pq = pos_q + (size_t)(b * NQ + qi) * 3;
    const float qx = pq[0], qy = pq[1], qt = pq[2];
    float* hrow = heat + ((size_t)b * NQ + qi) * NC;
    for (int ci = threadIdx.x; ci < NC; ci += 256) {
        const float* pc = pos_c + (size_t)(b * NC + ci) * 3;
        float dx = qx - pc[0];
        float dy = qy - pc[1];
        float dt = qt - pc[2];
        float denom = FOURNU * fabsf(dt) + EPS_;
        float dist  = dx * dx + dy * dy;
        hrow[ci] = __expf(-__fdividef(dist, denom));
    }
}

// ---------------------------------------------------------------------------
// bf16 hi/lo split body (k-pair-interleaved output)
// ---------------------------------------------------------------------------
__device__ __forceinline__ void split_body(const float* __restrict__ in,
                                           __nv_bfloat16* __restrict__ oh,
                                           __nv_bfloat16* __restrict__ ol, int i) {
    float4 v = ((const float4*)in)[i];
    __nv_bfloat162 hA = __floats2bfloat162_rn(v.x, v.y);
    __nv_bfloat162 hB = __floats2bfloat162_rn(v.z, v.w);
    __nv_bfloat162 lA = __floats2bfloat162_rn(v.x - __bfloat162float(hA.x),
                                              v.y - __bfloat162float(hA.y));
    __nv_bfloat162 lB = __floats2bfloat162_rn(v.z - __bfloat162float(hB.x),
                                              v.w - __bfloat162float(hB.y));
    size_t e = (size_t)i * 4;
    size_t base = e & ~(size_t)15;
    int lp0 = (int)(e & 15) >> 1;
    int s0 = (lp0 < 4) ? lp0 * 2 : (lp0 - 4) * 2 + 1;
    int lp1 = lp0 + 1;
    int s1 = (lp1 < 4) ? lp1 * 2 : (lp1 - 4) * 2 + 1;
    *(uint32_t*)&oh[base + s0 * 2] = b2u(hA);
    *(uint32_t*)&oh[base + s1 * 2] = b2u(hB);
    *(uint32_t*)&ol[base + s0 * 2] = b2u(lA);
    *(uint32_t*)&ol[base + s1 * 2] = b2u(lB);
}

// merged x_query + x_ctx split (one launch)
__global__ __launch_bounds__(256)
void split_x(const float* __restrict__ xq, const float* __restrict__ xc,
             __nv_bfloat16* __restrict__ oqh, __nv_bfloat16* __restrict__ oql,
             __nv_bfloat16* __restrict__ och, __nv_bfloat16* __restrict__ ocl) {
    constexpr int NBQ = (B_ * NQ * CE) / 1024;   // 2048 blocks
    int bid = blockIdx.x;
    if (bid < NBQ) split_body(xq, oqh, oql, bid * 256 + threadIdx.x);
    else           split_body(xc, och, ocl, (bid - NBQ) * 256 + threadIdx.x);
}

// merged 4-way W split (one launch)
__global__ __launch_bounds__(256)
void split_w(const float* __restrict__ w0, const float* __restrict__ w1,
             const float* __restrict__ w2, const float* __restrict__ w3,
             __nv_bfloat16* __restrict__ oh, __nv_bfloat16* __restrict__ ol) {
    int j = blockIdx.y;
    const float* in = (j == 0) ? w0 : (j == 1) ? w1 : (j == 2) ? w2 : w3;
    size_t off = (size_t)j * CE * CE;
    split_body(in, oh + off, ol + off, blockIdx.x * 256 + threadIdx.x);
}

// ---------------------------------------------------------------------------
// V: per-head transpose + bf16 split + c-pair-interleave.
// ---------------------------------------------------------------------------
__global__ __launch_bounds__(256)
void split_v_T(const float* __restrict__ v, __nv_bfloat16* __restrict__ oh,
               __nv_bfloat16* __restrict__ ol) {
    __shared__ float ts[64][65];
    const int b  = blockIdx.z;
    const int h  = blockIdx.y;
    const int c0 = blockIdx.x * 64;
    const int tid = threadIdx.x;
    #pragma unroll
    for (int t = 0; t < 4; ++t) {
        int idx = tid + t * 256;
        int r   = idx >> 4;
        int d4  = (idx & 15) << 2;
        float4 vv = *(const float4*)&v[(size_t)(b * NC + c0 + r) * 512 + h * 64 + d4];
        ts[d4 + 0][r] = vv.x; ts[d4 + 1][r] = vv.y;
        ts[d4 + 2][r] = vv.z; ts[d4 + 3][r] = vv.w;
    }
    __syncthreads();
    #pragma unroll
    for (int t = 0; t < 4; ++t) {
        int idx = tid + t * 256;
        int d   = idx >> 4;
        int r4  = (idx & 15) << 2;
        size_t orow = ((size_t)(b * H_ + h) * 64 + d) * NC + c0;
        #pragma unroll
        for (int pp = 0; pp < 2; ++pp) {
            int cl = r4 + pp * 2;
            float x0 = ts[d][cl], x1 = ts[d][cl + 1];
            __nv_bfloat162 hh = __floats2bfloat162_rn(x0, x1);
            __nv_bfloat162 ll = __floats2bfloat162_rn(x0 - __bfloat162float(hh.x),
                                                      x1 - __bfloat162float(hh.y));
            int cp = (cl & ~15) + perm16(cl & 15);
            *(uint32_t*)&oh[orow + cp] = b2u(hh);
            *(uint32_t*)&ol[orow + cp] = b2u(ll);
        }
    }
}

// ---------------------------------------------------------------------------
// bf16 3-pass GEMM (as R8): 128x64 CTA tile, BK=32, cp.async double-buffered.
// ---------------------------------------------------------------------------
constexpr int GEMM_SMEM_B = 73728;

__global__ __launch_bounds__(256, 2)
void gemm_bf16(const __nv_bfloat16* __restrict__ Ah, const __nv_bfloat16* __restrict__ Al,
               const __nv_bfloat16* __restrict__ Bh, const __nv_bfloat16* __restrict__ Bl,
               const float* __restrict__ bias, float* __restrict__ Yf,
               __nv_bfloat16* __restrict__ Ybh, __nv_bfloat16* __restrict__ Ybl,
               int mode, float scale) {
    extern __shared__ char gsm[];
    const uint32_t sb = smem_u32(gsm);

    const int tid  = threadIdx.x;
    const int lane = tid & 31;
    const int wid  = tid >> 5;
    const int grp  = lane >> 2;
    const int tig  = lane & 3;
    const int wm   = (wid >> 1) * 32;
    const int wn   = (wid & 1) * 32;
    const int rowBase = blockIdx.y * 128;
    const int colBase = blockIdx.x * 64;

    const int ar = tid >> 2;
    const int ac = tid & 3;
    const int br = tid >> 2;

    auto issue = [&](uint32_t bb, int k0) {
        #pragma unroll
        for (int t = 0; t < 2; ++t) {
            int r = ar + t * 64;
            size_t src = (size_t)(rowBase + r) * 512 + k0 + ac * 8;
            uint32_t dst = bb + r * 96 + ac * 16;
            CP16(dst,         Ah + src);
            CP16(dst + 12288, Al + src);
        }
        {
            size_t src = (size_t)(colBase + br) * 512 + k0 + ac * 8;
            uint32_t dst = bb + 24576 + br * 96 + ac * 16;
            CP16(dst,        Bh + src);
            CP16(dst + 6144, Bl + src);
        }
        CP_COMMIT();
    };

    float acc[2][4][4];
    #pragma unroll
    for (int mt = 0; mt < 2; ++mt)
        #pragma unroll
        for (int nt = 0; nt < 4; ++nt)
            #pragma unroll
            for (int r = 0; r < 4; ++r) acc[mt][nt][r] = 0.f;

    issue(sb, 0);

    for (int c = 0; c < 16; ++c) {
        const int cur = c & 1;
        const char* bufc = gsm + cur * 36864;
        if (c < 15) issue(sb + (cur ^ 1) * 36864, (c + 1) * 32);
        if (c < 15) asm volatile("cp.async.wait_group 1;" ::: "memory");
        else        asm volatile("cp.async.wait_group 0;" ::: "memory");
        __syncthreads();

        #pragma unroll
        for (int sub = 0; sub < 2; ++sub) {
            const int kbyte = sub * 32 + tig * 8;
            uint32_t ah[2][4], al[2][4];
            #pragma unroll
            for (int mt = 0; mt < 2; ++mt) {
                int r0 = wm + mt * 16 + grp;
                uint2 h0 = *(const uint2*)(bufc + r0 * 96 + kbyte);
                uint2 h1 = *(const uint2*)(bufc + (r0 + 8) * 96 + kbyte);
                uint2 l0 = *(const uint2*)(bufc + 12288 + r0 * 96 + kbyte);
                uint2 l1 = *(const uint2*)(bufc + 12288 + (r0 + 8) * 96 + kbyte);
                ah[mt][0] = h0.x; ah[mt][1] = h1.x; ah[mt][2] = h0.y; ah[mt][3] = h1.y;
                al[mt][0] = l0.x; al[mt][1] = l1.x; al[mt][2] = l0.y; al[mt][3] = l1.y;
            }
            #pragma unroll
            for (int nt = 0; nt < 4; ++nt) {
                int n = wn + nt * 8 + grp;
                uint2 bh2 = *(const uint2*)(bufc + 24576 + n * 96 + kbyte);
                uint2 bl2 = *(const uint2*)(bufc + 30720 + n * 96 + kbyte);
                #pragma unroll
                for (int mt = 0; mt < 2; ++mt) {
                    MMA_BF16(acc[mt][nt], ah[mt][0], ah[mt][1], ah[mt][2], ah[mt][3],
                             bh2.x, bh2.y);
                    MMA_BF16(acc[mt][nt], ah[mt][0], ah[mt][1], ah[mt][2], ah[mt][3],
                             bl2.x, bl2.y);
                    MMA_BF16(acc[mt][nt], al[mt][0], al[mt][1], al[mt][2], al[mt][3],
                             bh2.x, bh2.y);
                }
            }
        }
        __syncthreads();
    }

    #pragma unroll
    for (int nt = 0; nt < 4; ++nt) {
        int col = colBase + wn + nt * 8 + tig * 2;
        float b0 = __ldg(&bias[col]);
        float b1 = __ldg(&bias[col + 1]);
        #pragma unroll
        for (int mt = 0; mt < 2; ++mt) {
            int row = rowBase + wm + mt * 16 + grp;
            float v00 = acc[mt][nt][0] + b0, v01 = acc[mt][nt][1] + b1;
            float v10 = acc[mt][nt][2] + b0, v11 = acc[mt][nt][3] + b1;
            if (mode == 0) {
                *(float2*)&Yf[(size_t)row       * 512 + col] = make_float2(v00, v01);
                *(float2*)&Yf[(size_t)(row + 8) * 512 + col] = make_float2(v10, v11);
            } else {
                v00 *= scale; v01 *= scale; v10 *= scale; v11 *= scale;
                __nv_bfloat162 h0 = __floats2bfloat162_rn(v00, v01);
                __nv_bfloat162 h1 = __floats2bfloat162_rn(v10, v11);
                __nv_bfloat162 l0 = __floats2bfloat162_rn(v00 - __bfloat162float(h0.x),
                                                          v01 - __bfloat162float(h0.y));
                __nv_bfloat162 l1 = __floats2bfloat162_rn(v10 - __bfloat162float(h1.x),
                                                          v11 - __bfloat162float(h1.y));
                int colp = (col & ~15) + perm16(col & 15);
                *(uint32_t*)&Ybh[(size_t)row       * 512 + colp] = b2u(h0);
                *(uint32_t*)&Ybh[(size_t)(row + 8) * 512 + colp] = b2u(h1);
                *(uint32_t*)&Ybl[(size_t)row       * 512 + colp] = b2u(l0);
                *(uint32_t*)&Ybl[(size_t)(row + 8) * 512 + colp] = b2u(l1);
            }
        }
    }
}

// ---------------------------------------------------------------------------
// Tensor-core flash attention v3: per-c-chunk fused QK->exp->AV (P live range
// 8 regs, no spills at 2 CTA/SM) + heat loads pipelined one chunk ahead.
// Numerics bit-identical to R7/R8.
// ---------------------------------------------------------------------------
constexpr int ATTN_SMEM_B = 81920;

__global__ __launch_bounds__(256, 2)
void attn_tc(const __nv_bfloat16* __restrict__ qh, const __nv_bfloat16* __restrict__ ql,
             const __nv_bfloat16* __restrict__ kh, const __nv_bfloat16* __restrict__ kl,
             const __nv_bfloat16* __restrict__ vth, const __nv_bfloat16* __restrict__ vtl,
             const float* __restrict__ heat,
             __nv_bfloat16* __restrict__ yh, __nv_bfloat16* __restrict__ yl) {
    extern __shared__ char smem[];
    const uint32_t sb = smem_u32(smem);

    const int b   = blockIdx.z;
    const int h   = blockIdx.y;
    const int q0  = blockIdx.x * 128;
    const int tid = threadIdx.x;
    const int w    = tid >> 5;
    const int lane = tid & 31;
    const int grp  = lane >> 2;
    const int tig  = lane & 3;

    const int sr  = tid >> 3;
    const int sc8 = tid & 7;

    auto issue_tile = [&](uint32_t bb, int c0) {
        #pragma unroll
        for (int j = 0; j < 2; ++j) {
            int r = sr + j * 32;
            size_t ksrc = (size_t)(b * NC + c0 + r) * 512 + h * 64 + sc8 * 8;
            size_t vsrc = ((size_t)(b * H_ + h) * 64 + r) * NC + c0 + sc8 * 8;
            uint32_t d0 = bb + r * 160 + sc8 * 16;
            CP16(d0,         kh  + ksrc);
            CP16(d0 + 10240, kl  + ksrc);
            CP16(d0 + 20480, vth + vsrc);
            CP16(d0 + 30720, vtl + vsrc);
        }
        CP_COMMIT();
    };

    const int qrow0 = b * NQ + q0 + w * 16 + grp;
    uint32_t qfh[4][4], qfl[4][4];
    #pragma unroll
    for (int ks = 0; ks < 4; ++ks) {
        size_t e0 = (size_t)qrow0 * 512 + h * 64 + ks * 16 + tig * 4;
        size_t e1 = e0 + (size_t)8 * 512;
        uint2 h0 = *(const uint2*)(qh + e0);
        uint2 h1 = *(const uint2*)(qh + e1);
        uint2 l0v = *(const uint2*)(ql + e0);
        uint2 l1v = *(const uint2*)(ql + e1);
        qfh[ks][0] = h0.x; qfh[ks][1] = h1.x; qfh[ks][2] = h0.y; qfh[ks][3] = h1.y;
        qfl[ks][0] = l0v.x; qfl[ks][1] = l1v.x; qfl[ks][2] = l0v.y; qfl[ks][3] = l1v.y;
    }

    float acc[8][4];
    #pragma unroll
    for (int m = 0; m < 8; ++m)
        #pragma unroll
        for (int r = 0; r < 4; ++r) acc[m][r] = 0.f;
    float lq0 = 0.f, lq8 = 0.f;

    const float* hb0 = heat + (size_t)qrow0 * NC;
    const float* hb1 = hb0 + (size_t)8 * NC;

    issue_tile(sb, 0);

    for (int it = 0; it < 64; ++it) {
        const int cur = it & 1;
        const char* bufc = smem + cur * 40960;
        if (it < 63) issue_tile(sb + (cur ^ 1) * 40960, (it + 1) * 64);
        if (it < 63) asm volatile("cp.async.wait_group 1;" ::: "memory");
        else         asm volatile("cp.async.wait_group 0;" ::: "memory");
        __syncthreads();

        const int c0 = it * 64;
        // heat for chunk 0 (pipelined one chunk ahead below)
        float2 hA0 = *(const float2*)(hb0 + c0 + tig * 2);
        float2 hA1 = *(const float2*)(hb1 + c0 + tig * 2);
        float2 hB0 = *(const float2*)(hb0 + c0 + 8 + tig * 2);
        float2 hB1 = *(const float2*)(hb1 + c0 + 8 + tig * 2);

        #pragma unroll
        for (int kc = 0; kc < 4; ++kc) {
            float2 ha0 = hA0, ha1 = hA1, hc0 = hB0, hc1 = hB1;
            if (kc < 3) {
                int nb = c0 + (kc + 1) * 16 + tig * 2;
                hA0 = *(const float2*)(hb0 + nb);
                hA1 = *(const float2*)(hb1 + nb);
                hB0 = *(const float2*)(hb0 + nb + 8);
                hB1 = *(const float2*)(hb1 + nb + 8);
            }
            // ---- QK for c-tiles n0 = 2kc, n1 = 2kc+1 (3-pass) ----
            float s0[4] = {0.f, 0.f, 0.f, 0.f};
            float s1[4] = {0.f, 0.f, 0.f, 0.f};
            #pragma unroll
            for (int ks = 0; ks < 4; ++ks) {
                int r0 = (kc * 16 + grp) * 160 + ks * 32 + tig * 8;
                int r1 = r0 + 8 * 160;
                uint2 k0h = *(const uint2*)(bufc + r0);
                uint2 k0l = *(const uint2*)(bufc + 10240 + r0);
                uint2 k1h = *(const uint2*)(bufc + r1);
                uint2 k1l = *(const uint2*)(bufc + 10240 + r1);
                MMA_BF16(s0, qfh[ks][0], qfh[ks][1], qfh[ks][2], qfh[ks][3], k0h.x, k0h.y);
                MMA_BF16(s0, qfh[ks][0], qfh[ks][1], qfh[ks][2], qfh[ks][3], k0l.x, k0l.y);
                MMA_BF16(s0, qfl[ks][0], qfl[ks][1], qfl[ks][2], qfl[ks][3], k0h.x, k0h.y);
                MMA_BF16(s1, qfh[ks][0], qfh[ks][1], qfh[ks][2], qfh[ks][3], k1h.x, k1h.y);
                MMA_BF16(s1, qfh[ks][0], qfh[ks][1], qfh[ks][2], qfh[ks][3], k1l.x, k1l.y);
                MMA_BF16(s1, qfl[ks][0], qfl[ks][1], qfl[ks][2], qfl[ks][3], k1h.x, k1h.y);
            }

            // ---- bias + exp + pack P (hi/lo) for this chunk ----
            float e00 = __expf(s0[0] + ha0.x);
            float e01 = __expf(s0[1] + ha0.y);
            float e10 = __expf(s0[2] + ha1.x);
            float e11 = __expf(s0[3] + ha1.y);
            lq0 += e00 + e01;
            lq8 += e10 + e11;
            __nv_bfloat162 p0 = __floats2bfloat162_rn(e00, e01);
            __nv_bfloat162 p1 = __floats2bfloat162_rn(e10, e11);
            __nv_bfloat162 r0v = __floats2bfloat162_rn(e00 - __bfloat162float(p0.x),
                                                       e01 - __bfloat162float(p0.y));
            __nv_bfloat162 r1v = __floats2bfloat162_rn(e10 - __bfloat162float(p1.x),
                                                       e11 - __bfloat162float(p1.y));
            float f00 = __expf(s1[0] + hc0.x);
            float f01 = __expf(s1[1] + hc0.y);
            float f10 = __expf(s1[2] + hc1.x);
            float f11 = __expf(s1[3] + hc1.y);
            lq0 += f00 + f01;
            lq8 += f10 + f11;
            __nv_bfloat162 p2 = __floats2bfloat162_rn(f00, f01);
            __nv_bfloat162 p3 = __floats2bfloat162_rn(f10, f11);
            __nv_bfloat162 r2v = __floats2bfloat162_rn(f00 - __bfloat162float(p2.x),
                                                       f01 - __bfloat162float(p2.y));
            __nv_bfloat162 r3v = __floats2bfloat162_rn(f10 - __bfloat162float(p3.x),
                                                       f11 - __bfloat162float(p3.y));
            uint32_t a0 = b2u(p0), a1 = b2u(p1), a2 = b2u(p2), a3 = b2u(p3);
            uint32_t c0r = b2u(r0v), c1r = b2u(r1v), c2r = b2u(r2v), c3r = b2u(r3v);

            // ---- AV for this c-chunk over all 8 d-tiles (3-pass) ----
            #pragma unroll
            for (int m = 0; m < 8; ++m) {
                int boff = 20480 + (m * 8 + grp) * 160 + kc * 32 + tig * 8;
                uint2 vh2 = *(const uint2*)(bufc + boff);
                uint2 vl2 = *(const uint2*)(bufc + boff + 10240);
                MMA_BF16(acc[m], a0, a1, a2, a3, vh2.x, vh2.y);
                MMA_BF16(acc[m], a0, a1, a2, a3, vl2.x, vl2.y);
                MMA_BF16(acc[m], c0r, c1r, c2r, c3r, vh2.x, vh2.y);
            }
        }
        __syncthreads();
    }

    lq0 += __shfl_xor_sync(0xffffffffu, lq0, 1);
    lq0 += __shfl_xor_sync(0xffffffffu, lq0, 2);
    lq8 += __shfl_xor_sync(0xffffffffu, lq8, 1);
    lq8 += __shfl_xor_sync(0xffffffffu, lq8, 2);
    float i0 = 1.0f / lq0;
    float i1 = 1.0f / lq8;

    size_t yr0 = (size_t)qrow0 * 512 + h * 64;
    size_t yr1 = yr0 + (size_t)8 * 512;
    #pragma unroll
    for (int nt = 0; nt < 8; ++nt) {
        int ccp = (nt >> 1) * 16 + (nt & 1) * 2 + tig * 4;   // d-permuted
        float v00 = acc[nt][0] * i0, v01 = acc[nt][1] * i0;
        float v10 = acc[nt][2] * i1, v11 = acc[nt][3] * i1;
        __nv_bfloat162 h0 = __floats2bfloat162_rn(v00, v01);
        __nv_bfloat162 h1 = __floats2bfloat162_rn(v10, v11);
        __nv_bfloat162 l0v = __floats2bfloat162_rn(v00 - __bfloat162float(h0.x),
                                                   v01 - __bfloat162float(h0.y));
        __nv_bfloat162 l1v = __floats2bfloat162_rn(v10 - __bfloat162float(h1.x),
                                                   v11 - __bfloat162float(h1.y));
        *(uint32_t*)&yh[yr0 + ccp] = b2u(h0);
        *(uint32_t*)&yh[yr1 + ccp] = b2u(h1);
        *(uint32_t*)&yl[yr0 + ccp] = b2u(l0v);
        *(uint32_t*)&yl[yr1 + ccp] = b2u(l1v);
    }
}

// ---------------------------------------------------------------------------
// Launch.  Order chosen so ncu's -s 5 profiles gemm_bf16 (V projection).
// ---------------------------------------------------------------------------
extern "C" void kernel_launch(void* const* d_in, const int* in_sizes, int n_in,
                              void* d_out, int out_size) {
    (void)in_sizes; (void)n_in; (void)out_size;
    const float* x_ctx     = (const float*)d_in[0];
    const float* x_query   = (const float*)d_in[1];
    const float* pos_ctx   = (const float*)d_in[2];
    const float* pos_query = (const float*)d_in[3];
    const float* Wq = (const float*)d_in[4];
    const float* bq = (const float*)d_in[5];
    const float* Wk = (const float*)d_in[6];
    const float* bk = (const float*)d_in[7];
    const float* Wv = (const float*)d_in[8];
    const float* bv = (const float*)d_in[9];
    const float* Wo = (const float*)d_in[10];
    const float* bo = (const float*)d_in[11];
    float* out = (float*)d_out;

    float *gv, *gh;
    __nv_bfloat16 *gxqh, *gxql, *gxch, *gxcl, *gwh, *gwl;
    __nv_bfloat16 *gqh, *gql, *gkh, *gkl, *gvth, *gvtl, *gyh, *gyl;
    cudaGetSymbolAddress((void**)&gv,   g_v);
    cudaGetSymbolAddress((void**)&gh,   g_heat);
    cudaGetSymbolAddress((void**)&gxqh, g_xqh);
    cudaGetSymbolAddress((void**)&gxql, g_xql);
    cudaGetSymbolAddress((void**)&gxch, g_xch);
    cudaGetSymbolAddress((void**)&gxcl, g_xcl);
    cudaGetSymbolAddress((void**)&gwh,  g_wh);
    cudaGetSymbolAddress((void**)&gwl,  g_wl);
    cudaGetSymbolAddress((void**)&gqh,  g_qh);
    cudaGetSymbolAddress((void**)&gql,  g_ql);
    cudaGetSymbolAddress((void**)&gkh,  g_kh);
    cudaGetSymbolAddress((void**)&gkl,  g_kl);
    cudaGetSymbolAddress((void**)&gvth, g_vth);
    cudaGetSymbolAddress((void**)&gvtl, g_vtl);
    cudaGetSymbolAddress((void**)&gyh,  g_yh);
    cudaGetSymbolAddress((void**)&gyl,  g_yl);

    cudaFuncSetAttribute(attn_tc,
                         cudaFuncAttributeMaxDynamicSharedMemorySize, ATTN_SMEM_B);
    cudaFuncSetAttribute(gemm_bf16,
                         cudaFuncAttributeMaxDynamicSharedMemorySize, GEMM_SMEM_B);

    // launch 0
    heat_precompute<<<dim3(NQ, B_), 256>>>(pos_ctx, pos_query, gh);
    // launch 1
    split_x<<<(B_ * NQ * CE + B_ * NC * CE) / 1024, 256>>>(
        x_query, x_ctx, gxqh, gxql, gxch, gxcl);
    // launch 2
    split_w<<<dim3((CE * CE) / 1024, 4), 256>>>(Wq, Wk, Wv, Wo, gwh, gwl);
    // launch 3
    gemm_bf16<<<dim3(8, (B_ * NQ) / 128), 256, GEMM_SMEM_B>>>(
        gxqh, gxql, gwh, gwl, bq, nullptr, gqh, gql, 1, SCALE);
    // launch 4
    gemm_bf16<<<dim3(8, (B_ * NC) / 128), 256, GEMM_SMEM_B>>>(
        gxch, gxcl, gwh + CE * CE, gwl + CE * CE, bk, nullptr, gkh, gkl, 1, 1.0f);
    // launch 5  <-- ncu -s 5 profiles this one
    gemm_bf16<<<dim3(8, (B_ * NC) / 128), 256, GEMM_SMEM_B>>>(
        gxch, gxcl, gwh + 2 * CE * CE, gwl + 2 * CE * CE, bv, gv, nullptr, nullptr, 0, 1.0f);
    // launch 6
    split_v_T<<<dim3(NC / 64, H_, B_), 256>>>(gv, gvth, gvtl);
    // launch 7
    attn_tc<<<dim3(NQ / 128, H_, B_), 256, ATTN_SMEM_B>>>(
        gqh, gql, gkh, gkl, gvth, gvtl, gh, gyh, gyl);
    // launch 8
    gemm_bf16<<<dim3(8, (B_ * NQ) / 128), 256, GEMM_SMEM_B>>>(
        gyh, gyl, gwh + 3 * CE * CE, gwl + 3 * CE * CE, bo, out, nullptr, nullptr, 0, 1.0f);
}

// round 10
// speedup vs baseline: 3.2538x; 1.0258x over previous
#include <cuda_runtime.h>
#include <cuda_bf16.h>
#include <cstdint>
#include <math.h>

// ---------------------------------------------------------------------------
// Problem constants
// ---------------------------------------------------------------------------
constexpr int B_  = 2;
constexpr int NQ  = 2048;
constexpr int NC  = 4096;
constexpr int CE  = 512;
constexpr int H_  = 8;
constexpr float SCALE  = 0.125f;
constexpr float FOURNU = 0.4f;
constexpr float EPS_   = 1e-6f;

// Pair-interleave permutation within a 16-element k-chunk (validated R7/R8).
__host__ __device__ constexpr int perm16(int e) {
    int lp = e >> 1, o = e & 1;
    int slot = (lp < 4) ? (lp * 2) : ((lp - 4) * 2 + 1);
    return slot * 2 + o;
}

// ---------------------------------------------------------------------------
// Scratch
// ---------------------------------------------------------------------------
__device__ float g_v [B_ * NC * CE];
__device__ float g_heat[(size_t)B_ * NQ * NC];            // 67 MB
__device__ __nv_bfloat16 g_xqh[B_ * NQ * CE];             // k-permuted
__device__ __nv_bfloat16 g_xql[B_ * NQ * CE];
__device__ __nv_bfloat16 g_xch[B_ * NC * CE];
__device__ __nv_bfloat16 g_xcl[B_ * NC * CE];
__device__ __nv_bfloat16 g_wh[4 * CE * CE];
__device__ __nv_bfloat16 g_wl[4 * CE * CE];
__device__ __nv_bfloat16 g_qh[B_ * NQ * CE];              // scaled, d-permuted
__device__ __nv_bfloat16 g_ql[B_ * NQ * CE];
__device__ __nv_bfloat16 g_kh[B_ * NC * CE];              // d-permuted
__device__ __nv_bfloat16 g_kl[B_ * NC * CE];
__device__ __nv_bfloat16 g_vth[B_ * NC * CE];             // [b][h][d][c], c-permuted
__device__ __nv_bfloat16 g_vtl[B_ * NC * CE];
__device__ __nv_bfloat16 g_yh[B_ * NQ * CE];              // attn out, d-permuted
__device__ __nv_bfloat16 g_yl[B_ * NQ * CE];

// ---------------------------------------------------------------------------
// helpers
// ---------------------------------------------------------------------------
#define MMA_BF16(d, a0, a1, a2, a3, b0, b1) \
    asm volatile("mma.sync.aligned.m16n8k16.row.col.f32.bf16.bf16.f32 " \
        "{%0,%1,%2,%3}, {%4,%5,%6,%7}, {%8,%9}, {%0,%1,%2,%3};" \
        : "+f"((d)[0]), "+f"((d)[1]), "+f"((d)[2]), "+f"((d)[3]) \
        : "r"(a0), "r"(a1), "r"(a2), "r"(a3), "r"(b0), "r"(b1))

#define CP16(dst, src) \
    asm volatile("cp.async.cg.shared.global [%0], [%1], 16;" \
                 :: "r"(dst), "l"(src))
#define CP_COMMIT() asm volatile("cp.async.commit_group;")

__device__ __forceinline__ uint32_t b2u(__nv_bfloat162 x) {
    return *reinterpret_cast<uint32_t*>(&x);
}
__device__ __forceinline__ uint32_t smem_u32(const void* p) {
    uint32_t a;
    asm("{ .reg .u64 t; cvta.to.shared.u64 t, %1; cvt.u32.u64 %0, t; }"
        : "=r"(a) : "l"(p));
    return a;
}

// ---------------------------------------------------------------------------
// Heat-kernel bias precompute (head-independent)
// ---------------------------------------------------------------------------
__global__ __launch_bounds__(256)
void heat_precompute(const float* __restrict__ pos_c, const float* __restrict__ pos_q,
                     float* __restrict__ heat) {
    const int b  = blockIdx.y;
    const int qi = blockIdx.x;
    const float* pq = pos_q + (size_t)(b * NQ + qi) * 3;
    const float qx = pq[0], qy = pq[1], qt = pq[2];
    float* hrow = heat + ((size_t)b * NQ + qi) * NC;
    for (int ci = threadIdx.x; ci < NC; ci += 256) {
        const float* pc = pos_c + (size_t)(b * NC + ci) * 3;
        float dx = qx - pc[0];
        float dy = qy - pc[1];
        float dt = qt - pc[2];
        float denom = FOURNU * fabsf(dt) + EPS_;
        float dist  = dx * dx + dy * dy;
        hrow[ci] = __expf(-__fdividef(dist, denom));
    }
}

// ---------------------------------------------------------------------------
// bf16 hi/lo split body (k-pair-interleaved output)
// ---------------------------------------------------------------------------
__device__ __forceinline__ void split_body(const float* __restrict__ in,
                                           __nv_bfloat16* __restrict__ oh,
                                           __nv_bfloat16* __restrict__ ol, int i) {
    float4 v = ((const float4*)in)[i];
    __nv_bfloat162 hA = __floats2bfloat162_rn(v.x, v.y);
    __nv_bfloat162 hB = __floats2bfloat162_rn(v.z, v.w);
    __nv_bfloat162 lA = __floats2bfloat162_rn(v.x - __bfloat162float(hA.x),
                                              v.y - __bfloat162float(hA.y));
    __nv_bfloat162 lB = __floats2bfloat162_rn(v.z - __bfloat162float(hB.x),
                                              v.w - __bfloat162float(hB.y));
    size_t e = (size_t)i * 4;
    size_t base = e & ~(size_t)15;
    int lp0 = (int)(e & 15) >> 1;
    int s0 = (lp0 < 4) ? lp0 * 2 : (lp0 - 4) * 2 + 1;
    int lp1 = lp0 + 1;
    int s1 = (lp1 < 4) ? lp1 * 2 : (lp1 - 4) * 2 + 1;
    *(uint32_t*)&oh[base + s0 * 2] = b2u(hA);
    *(uint32_t*)&oh[base + s1 * 2] = b2u(hB);
    *(uint32_t*)&ol[base + s0 * 2] = b2u(lA);
    *(uint32_t*)&ol[base + s1 * 2] = b2u(lB);
}

// merged x_query + x_ctx + 4xW split (single launch)
__global__ __launch_bounds__(256)
void split_all(const float* __restrict__ xq, const float* __restrict__ xc,
               const float* __restrict__ w0, const float* __restrict__ w1,
               const float* __restrict__ w2, const float* __restrict__ w3,
               __nv_bfloat16* __restrict__ oqh, __nv_bfloat16* __restrict__ oql,
               __nv_bfloat16* __restrict__ och, __nv_bfloat16* __restrict__ ocl,
               __nv_bfloat16* __restrict__ owh, __nv_bfloat16* __restrict__ owl) {
    constexpr int NBQ = (B_ * NQ * CE) / 1024;   // 2048
    constexpr int NBC = (B_ * NC * CE) / 1024;   // 4096
    constexpr int NBW = (CE * CE) / 1024;        // 256
    int bid = blockIdx.x;
    if (bid < NBQ) {
        split_body(xq, oqh, oql, bid * 256 + threadIdx.x);
    } else if (bid < NBQ + NBC) {
        split_body(xc, och, ocl, (bid - NBQ) * 256 + threadIdx.x);
    } else {
        int wb = bid - NBQ - NBC;
        int j  = wb / NBW;
        const float* in = (j == 0) ? w0 : (j == 1) ? w1 : (j == 2) ? w2 : w3;
        size_t off = (size_t)j * CE * CE;
        split_body(in, owh + off, owl + off, (wb - j * NBW) * 256 + threadIdx.x);
    }
}

// ---------------------------------------------------------------------------
// V: per-head transpose + bf16 split + c-pair-interleave.
// ---------------------------------------------------------------------------
__global__ __launch_bounds__(256)
void split_v_T(const float* __restrict__ v, __nv_bfloat16* __restrict__ oh,
               __nv_bfloat16* __restrict__ ol) {
    __shared__ float ts[64][65];
    const int b  = blockIdx.z;
    const int h  = blockIdx.y;
    const int c0 = blockIdx.x * 64;
    const int tid = threadIdx.x;
    #pragma unroll
    for (int t = 0; t < 4; ++t) {
        int idx = tid + t * 256;
        int r   = idx >> 4;
        int d4  = (idx & 15) << 2;
        float4 vv = *(const float4*)&v[(size_t)(b * NC + c0 + r) * 512 + h * 64 + d4];
        ts[d4 + 0][r] = vv.x; ts[d4 + 1][r] = vv.y;
        ts[d4 + 2][r] = vv.z; ts[d4 + 3][r] = vv.w;
    }
    __syncthreads();
    #pragma unroll
    for (int t = 0; t < 4; ++t) {
        int idx = tid + t * 256;
        int d   = idx >> 4;
        int r4  = (idx & 15) << 2;
        size_t orow = ((size_t)(b * H_ + h) * 64 + d) * NC + c0;
        #pragma unroll
        for (int pp = 0; pp < 2; ++pp) {
            int cl = r4 + pp * 2;
            float x0 = ts[d][cl], x1 = ts[d][cl + 1];
            __nv_bfloat162 hh = __floats2bfloat162_rn(x0, x1);
            __nv_bfloat162 ll = __floats2bfloat162_rn(x0 - __bfloat162float(hh.x),
                                                      x1 - __bfloat162float(hh.y));
            int cp = (cl & ~15) + perm16(cl & 15);
            *(uint32_t*)&oh[orow + cp] = b2u(hh);
            *(uint32_t*)&ol[orow + cp] = b2u(ll);
        }
    }
}

// ---------------------------------------------------------------------------
// bf16 3-pass GEMM (R8 structure): used for Q projection and O projection.
// ---------------------------------------------------------------------------
constexpr int GEMM_SMEM_B = 73728;

__global__ __launch_bounds__(256, 2)
void gemm_bf16(const __nv_bfloat16* __restrict__ Ah, const __nv_bfloat16* __restrict__ Al,
               const __nv_bfloat16* __restrict__ Bh, const __nv_bfloat16* __restrict__ Bl,
               const float* __restrict__ bias, float* __restrict__ Yf,
               __nv_bfloat16* __restrict__ Ybh, __nv_bfloat16* __restrict__ Ybl,
               int mode, float scale) {
    extern __shared__ char gsm[];
    const uint32_t sb = smem_u32(gsm);

    const int tid  = threadIdx.x;
    const int lane = tid & 31;
    const int wid  = tid >> 5;
    const int grp  = lane >> 2;
    const int tig  = lane & 3;
    const int wm   = (wid >> 1) * 32;
    const int wn   = (wid & 1) * 32;
    const int rowBase = blockIdx.y * 128;
    const int colBase = blockIdx.x * 64;

    const int ar = tid >> 2;
    const int ac = tid & 3;

    auto issue = [&](uint32_t bb, int k0) {
        #pragma unroll
        for (int t = 0; t < 2; ++t) {
            int r = ar + t * 64;
            size_t src = (size_t)(rowBase + r) * 512 + k0 + ac * 8;
            uint32_t dst = bb + r * 96 + ac * 16;
            CP16(dst,         Ah + src);
            CP16(dst + 12288, Al + src);
        }
        {
            size_t src = (size_t)(colBase + ar) * 512 + k0 + ac * 8;
            uint32_t dst = bb + 24576 + ar * 96 + ac * 16;
            CP16(dst,        Bh + src);
            CP16(dst + 6144, Bl + src);
        }
        CP_COMMIT();
    };

    float acc[2][4][4];
    #pragma unroll
    for (int mt = 0; mt < 2; ++mt)
        #pragma unroll
        for (int nt = 0; nt < 4; ++nt)
            #pragma unroll
            for (int r = 0; r < 4; ++r) acc[mt][nt][r] = 0.f;

    issue(sb, 0);

    for (int c = 0; c < 16; ++c) {
        const int cur = c & 1;
        const char* bufc = gsm + cur * 36864;
        if (c < 15) issue(sb + (cur ^ 1) * 36864, (c + 1) * 32);
        if (c < 15) asm volatile("cp.async.wait_group 1;" ::: "memory");
        else        asm volatile("cp.async.wait_group 0;" ::: "memory");
        __syncthreads();

        #pragma unroll
        for (int sub = 0; sub < 2; ++sub) {
            const int kbyte = sub * 32 + tig * 8;
            uint32_t ah[2][4], al[2][4];
            #pragma unroll
            for (int mt = 0; mt < 2; ++mt) {
                int r0 = wm + mt * 16 + grp;
                uint2 h0 = *(const uint2*)(bufc + r0 * 96 + kbyte);
                uint2 h1 = *(const uint2*)(bufc + (r0 + 8) * 96 + kbyte);
                uint2 l0 = *(const uint2*)(bufc + 12288 + r0 * 96 + kbyte);
                uint2 l1 = *(const uint2*)(bufc + 12288 + (r0 + 8) * 96 + kbyte);
                ah[mt][0] = h0.x; ah[mt][1] = h1.x; ah[mt][2] = h0.y; ah[mt][3] = h1.y;
                al[mt][0] = l0.x; al[mt][1] = l1.x; al[mt][2] = l0.y; al[mt][3] = l1.y;
            }
            #pragma unroll
            for (int nt = 0; nt < 4; ++nt) {
                int n = wn + nt * 8 + grp;
                uint2 bh2 = *(const uint2*)(bufc + 24576 + n * 96 + kbyte);
                uint2 bl2 = *(const uint2*)(bufc + 30720 + n * 96 + kbyte);
                #pragma unroll
                for (int mt = 0; mt < 2; ++mt) {
                    MMA_BF16(acc[mt][nt], ah[mt][0], ah[mt][1], ah[mt][2], ah[mt][3],
                             bh2.x, bh2.y);
                    MMA_BF16(acc[mt][nt], ah[mt][0], ah[mt][1], ah[mt][2], ah[mt][3],
                             bl2.x, bl2.y);
                    MMA_BF16(acc[mt][nt], al[mt][0], al[mt][1], al[mt][2], al[mt][3],
                             bh2.x, bh2.y);
                }
            }
        }
        __syncthreads();
    }

    #pragma unroll
    for (int nt = 0; nt < 4; ++nt) {
        int col = colBase + wn + nt * 8 + tig * 2;
        float b0 = __ldg(&bias[col]);
        float b1 = __ldg(&bias[col + 1]);
        #pragma unroll
        for (int mt = 0; mt < 2; ++mt) {
            int row = rowBase + wm + mt * 16 + grp;
            float v00 = acc[mt][nt][0] + b0, v01 = acc[mt][nt][1] + b1;
            float v10 = acc[mt][nt][2] + b0, v11 = acc[mt][nt][3] + b1;
            if (mode == 0) {
                *(float2*)&Yf[(size_t)row       * 512 + col] = make_float2(v00, v01);
                *(float2*)&Yf[(size_t)(row + 8) * 512 + col] = make_float2(v10, v11);
            } else {
                v00 *= scale; v01 *= scale; v10 *= scale; v11 *= scale;
                __nv_bfloat162 h0 = __floats2bfloat162_rn(v00, v01);
                __nv_bfloat162 h1 = __floats2bfloat162_rn(v10, v11);
                __nv_bfloat162 l0 = __floats2bfloat162_rn(v00 - __bfloat162float(h0.x),
                                                          v01 - __bfloat162float(h0.y));
                __nv_bfloat162 l1 = __floats2bfloat162_rn(v10 - __bfloat162float(h1.x),
                                                          v11 - __bfloat162float(h1.y));
                int colp = (col & ~15) + perm16(col & 15);
                *(uint32_t*)&Ybh[(size_t)row       * 512 + colp] = b2u(h0);
                *(uint32_t*)&Ybh[(size_t)(row + 8) * 512 + colp] = b2u(h1);
                *(uint32_t*)&Ybl[(size_t)row       * 512 + colp] = b2u(l0);
                *(uint32_t*)&Ybl[(size_t)(row + 8) * 512 + colp] = b2u(l1);
            }
        }
    }
}

// ---------------------------------------------------------------------------
// Fused K+V projection GEMM: shares the A (x_ctx) tile; computes K-proj
// (bf16 hi/lo, d-permuted) and V-proj (fp32) per CTA.  Doubles MMA density
// per staged A tile.
// Smem buffer: Ah 0 | Al 12288 | Bkh 24576 | Bkl 30720 | Bvh 36864 | Bvl 43008
// buffer stride 49152, total 98304.
// ---------------------------------------------------------------------------
constexpr int GEMMKV_SMEM_B = 98304;

__global__ __launch_bounds__(256, 2)
void gemm_kv(const __nv_bfloat16* __restrict__ Ah, const __nv_bfloat16* __restrict__ Al,
             const __nv_bfloat16* __restrict__ Bkh, const __nv_bfloat16* __restrict__ Bkl,
             const __nv_bfloat16* __restrict__ Bvh, const __nv_bfloat16* __restrict__ Bvl,
             const float* __restrict__ bk, const float* __restrict__ bv,
             __nv_bfloat16* __restrict__ Kh, __nv_bfloat16* __restrict__ Kl,
             float* __restrict__ Vf) {
    extern __shared__ char gsm[];
    const uint32_t sb = smem_u32(gsm);

    const int tid  = threadIdx.x;
    const int lane = tid & 31;
    const int wid  = tid >> 5;
    const int grp  = lane >> 2;
    const int tig  = lane & 3;
    const int wm   = (wid >> 1) * 32;
    const int wn   = (wid & 1) * 32;
    const int rowBase = blockIdx.y * 128;
    const int colBase = blockIdx.x * 64;

    const int ar = tid >> 2;
    const int ac = tid & 3;

    auto issue = [&](uint32_t bb, int k0) {
        #pragma unroll
        for (int t = 0; t < 2; ++t) {
            int r = ar + t * 64;
            size_t src = (size_t)(rowBase + r) * 512 + k0 + ac * 8;
            uint32_t dst = bb + r * 96 + ac * 16;
            CP16(dst,         Ah + src);
            CP16(dst + 12288, Al + src);
        }
        {
            size_t src = (size_t)(colBase + ar) * 512 + k0 + ac * 8;
            uint32_t dst = bb + 24576 + ar * 96 + ac * 16;
            CP16(dst,         Bkh + src);
            CP16(dst +  6144, Bkl + src);
            CP16(dst + 12288, Bvh + src);
            CP16(dst + 18432, Bvl + src);
        }
        CP_COMMIT();
    };

    float accK[2][4][4], accV[2][4][4];
    #pragma unroll
    for (int mt = 0; mt < 2; ++mt)
        #pragma unroll
        for (int nt = 0; nt < 4; ++nt)
            #pragma unroll
            for (int r = 0; r < 4; ++r) { accK[mt][nt][r] = 0.f; accV[mt][nt][r] = 0.f; }

    issue(sb, 0);

    for (int c = 0; c < 16; ++c) {
        const int cur = c & 1;
        const char* bufc = gsm + cur * 49152;
        if (c < 15) issue(sb + (cur ^ 1) * 49152, (c + 1) * 32);
        if (c < 15) asm volatile("cp.async.wait_group 1;" ::: "memory");
        else        asm volatile("cp.async.wait_group 0;" ::: "memory");
        __syncthreads();

        #pragma unroll
        for (int sub = 0; sub < 2; ++sub) {
            const int kbyte = sub * 32 + tig * 8;
            uint32_t ah[2][4], al[2][4];
            #pragma unroll
            for (int mt = 0; mt < 2; ++mt) {
                int r0 = wm + mt * 16 + grp;
                uint2 h0 = *(const uint2*)(bufc + r0 * 96 + kbyte);
                uint2 h1 = *(const uint2*)(bufc + (r0 + 8) * 96 + kbyte);
                uint2 l0 = *(const uint2*)(bufc + 12288 + r0 * 96 + kbyte);
                uint2 l1 = *(const uint2*)(bufc + 12288 + (r0 + 8) * 96 + kbyte);
                ah[mt][0] = h0.x; ah[mt][1] = h1.x; ah[mt][2] = h0.y; ah[mt][3] = h1.y;
                al[mt][0] = l0.x; al[mt][1] = l1.x; al[mt][2] = l0.y; al[mt][3] = l1.y;
            }
            #pragma unroll
            for (int nt = 0; nt < 4; ++nt) {
                int n = wn + nt * 8 + grp;
                uint2 kh2 = *(const uint2*)(bufc + 24576 + n * 96 + kbyte);
                uint2 kl2 = *(const uint2*)(bufc + 30720 + n * 96 + kbyte);
                uint2 vh2 = *(const uint2*)(bufc + 36864 + n * 96 + kbyte);
                uint2 vl2 = *(const uint2*)(bufc + 43008 + n * 96 + kbyte);
                #pragma unroll
                for (int mt = 0; mt < 2; ++mt) {
                    MMA_BF16(accK[mt][nt], ah[mt][0], ah[mt][1], ah[mt][2], ah[mt][3],
                             kh2.x, kh2.y);
                    MMA_BF16(accK[mt][nt], ah[mt][0], ah[mt][1], ah[mt][2], ah[mt][3],
                             kl2.x, kl2.y);
                    MMA_BF16(accK[mt][nt], al[mt][0], al[mt][1], al[mt][2], al[mt][3],
                             kh2.x, kh2.y);
                    MMA_BF16(accV[mt][nt], ah[mt][0], ah[mt][1], ah[mt][2], ah[mt][3],
                             vh2.x, vh2.y);
                    MMA_BF16(accV[mt][nt], ah[mt][0], ah[mt][1], ah[mt][2], ah[mt][3],
                             vl2.x, vl2.y);
                    MMA_BF16(accV[mt][nt], al[mt][0], al[mt][1], al[mt][2], al[mt][3],
                             vh2.x, vh2.y);
                }
            }
        }
        __syncthreads();
    }

    #pragma unroll
    for (int nt = 0; nt < 4; ++nt) {
        int col = colBase + wn + nt * 8 + tig * 2;
        float bk0 = __ldg(&bk[col]);
        float bk1 = __ldg(&bk[col + 1]);
        float bv0 = __ldg(&bv[col]);
        float bv1 = __ldg(&bv[col + 1]);
        int colp = (col & ~15) + perm16(col & 15);
        #pragma unroll
        for (int mt = 0; mt < 2; ++mt) {
            int row = rowBase + wm + mt * 16 + grp;
            // K: bf16 hi/lo, permuted
            float k00 = accK[mt][nt][0] + bk0, k01 = accK[mt][nt][1] + bk1;
            float k10 = accK[mt][nt][2] + bk0, k11 = accK[mt][nt][3] + bk1;
            __nv_bfloat162 h0 = __floats2bfloat162_rn(k00, k01);
            __nv_bfloat162 h1 = __floats2bfloat162_rn(k10, k11);
            __nv_bfloat162 l0 = __floats2bfloat162_rn(k00 - __bfloat162float(h0.x),
                                                      k01 - __bfloat162float(h0.y));
            __nv_bfloat162 l1 = __floats2bfloat162_rn(k10 - __bfloat162float(h1.x),
                                                      k11 - __bfloat162float(h1.y));
            *(uint32_t*)&Kh[(size_t)row       * 512 + colp] = b2u(h0);
            *(uint32_t*)&Kh[(size_t)(row + 8) * 512 + colp] = b2u(h1);
            *(uint32_t*)&Kl[(size_t)row       * 512 + colp] = b2u(l0);
            *(uint32_t*)&Kl[(size_t)(row + 8) * 512 + colp] = b2u(l1);
            // V: fp32
            *(float2*)&Vf[(size_t)row       * 512 + col] =
                make_float2(accV[mt][nt][0] + bv0, accV[mt][nt][1] + bv1);
            *(float2*)&Vf[(size_t)(row + 8) * 512 + col] =
                make_float2(accV[mt][nt][2] + bv0, accV[mt][nt][3] + bv1);
        }
    }
}

// ---------------------------------------------------------------------------
// Tensor-core flash attention v4: software-pipelined chunks.
// Per iter: QK(0); for kc: exp(kc) -> QK(kc+1) -> AV(kc).
// QK(kc+1) fills the tensor pipe while exp(kc) results land; AV(kc) operands
// ready by issue time.  Accumulation orders unchanged -> bit-identical.
// ---------------------------------------------------------------------------
constexpr int ATTN_SMEM_B = 81920;

__global__ __launch_bounds__(256, 2)
void attn_tc(const __nv_bfloat16* __restrict__ qh, const __nv_bfloat16* __restrict__ ql,
             const __nv_bfloat16* __restrict__ kh, const __nv_bfloat16* __restrict__ kl,
             const __nv_bfloat16* __restrict__ vth, const __nv_bfloat16* __restrict__ vtl,
             const float* __restrict__ heat,
             __nv_bfloat16* __restrict__ yh, __nv_bfloat16* __restrict__ yl) {
    extern __shared__ char smem[];
    const uint32_t sb = smem_u32(smem);

    const int b   = blockIdx.z;
    const int h   = blockIdx.y;
    const int q0  = blockIdx.x * 128;
    const int tid = threadIdx.x;
    const int w    = tid >> 5;
    const int lane = tid & 31;
    const int grp  = lane >> 2;
    const int tig  = lane & 3;

    const int sr  = tid >> 3;
    const int sc8 = tid & 7;

    auto issue_tile = [&](uint32_t bb, int c0) {
        #pragma unroll
        for (int j = 0; j < 2; ++j) {
            int r = sr + j * 32;
            size_t ksrc = (size_t)(b * NC + c0 + r) * 512 + h * 64 + sc8 * 8;
            size_t vsrc = ((size_t)(b * H_ + h) * 64 + r) * NC + c0 + sc8 * 8;
            uint32_t d0 = bb + r * 160 + sc8 * 16;
            CP16(d0,         kh  + ksrc);
            CP16(d0 + 10240, kl  + ksrc);
            CP16(d0 + 20480, vth + vsrc);
            CP16(d0 + 30720, vtl + vsrc);
        }
        CP_COMMIT();
    };

    const int qrow0 = b * NQ + q0 + w * 16 + grp;
    uint32_t qfh[4][4], qfl[4][4];
    #pragma unroll
    for (int ks = 0; ks < 4; ++ks) {
        size_t e0 = (size_t)qrow0 * 512 + h * 64 + ks * 16 + tig * 4;
        size_t e1 = e0 + (size_t)8 * 512;
        uint2 h0 = *(const uint2*)(qh + e0);
        uint2 h1 = *(const uint2*)(qh + e1);
        uint2 l0v = *(const uint2*)(ql + e0);
        uint2 l1v = *(const uint2*)(ql + e1);
        qfh[ks][0] = h0.x; qfh[ks][1] = h1.x; qfh[ks][2] = h0.y; qfh[ks][3] = h1.y;
        qfl[ks][0] = l0v.x; qfl[ks][1] = l1v.x; qfl[ks][2] = l0v.y; qfl[ks][3] = l1v.y;
    }

    float acc[8][4];
    #pragma unroll
    for (int m = 0; m < 8; ++m)
        #pragma unroll
        for (int r = 0; r < 4; ++r) acc[m][r] = 0.f;
    float lq0 = 0.f, lq8 = 0.f;

    const float* hb0 = heat + (size_t)qrow0 * NC;
    const float* hb1 = hb0 + (size_t)8 * NC;

    // QK MMA block for one 16-c chunk
    auto qk_chunk = [&](const char* bufc, int kc, float* s0, float* s1) {
        #pragma unroll
        for (int ks = 0; ks < 4; ++ks) {
            int r0 = (kc * 16 + grp) * 160 + ks * 32 + tig * 8;
            int r1 = r0 + 8 * 160;
            uint2 k0h = *(const uint2*)(bufc + r0);
            uint2 k0l = *(const uint2*)(bufc + 10240 + r0);
            uint2 k1h = *(const uint2*)(bufc + r1);
            uint2 k1l = *(const uint2*)(bufc + 10240 + r1);
            MMA_BF16(s0, qfh[ks][0], qfh[ks][1], qfh[ks][2], qfh[ks][3], k0h.x, k0h.y);
            MMA_BF16(s0, qfh[ks][0], qfh[ks][1], qfh[ks][2], qfh[ks][3], k0l.x, k0l.y);
            MMA_BF16(s0, qfl[ks][0], qfl[ks][1], qfl[ks][2], qfl[ks][3], k0h.x, k0h.y);
            MMA_BF16(s1, qfh[ks][0], qfh[ks][1], qfh[ks][2], qfh[ks][3], k1h.x, k1h.y);
            MMA_BF16(s1, qfh[ks][0], qfh[ks][1], qfh[ks][2], qfh[ks][3], k1l.x, k1l.y);
            MMA_BF16(s1, qfl[ks][0], qfl[ks][1], qfl[ks][2], qfl[ks][3], k1h.x, k1h.y);
        }
    };

    issue_tile(sb, 0);

    for (int it = 0; it < 64; ++it) {
        const int cur = it & 1;
        const char* bufc = smem + cur * 40960;
        if (it < 63) issue_tile(sb + (cur ^ 1) * 40960, (it + 1) * 64);
        if (it < 63) asm volatile("cp.async.wait_group 1;" ::: "memory");
        else         asm volatile("cp.async.wait_group 0;" ::: "memory");
        __syncthreads();

        const int c0 = it * 64;
        float2 hA0 = *(const float2*)(hb0 + c0 + tig * 2);
        float2 hA1 = *(const float2*)(hb1 + c0 + tig * 2);
        float2 hB0 = *(const float2*)(hb0 + c0 + 8 + tig * 2);
        float2 hB1 = *(const float2*)(hb1 + c0 + 8 + tig * 2);

        float s0[4] = {0.f, 0.f, 0.f, 0.f};
        float s1[4] = {0.f, 0.f, 0.f, 0.f};
        qk_chunk(bufc, 0, s0, s1);

        #pragma unroll
        for (int kc = 0; kc < 4; ++kc) {
            float2 ha0 = hA0, ha1 = hA1, hc0 = hB0, hc1 = hB1;
            if (kc < 3) {
                int nb = c0 + (kc + 1) * 16 + tig * 2;
                hA0 = *(const float2*)(hb0 + nb);
                hA1 = *(const float2*)(hb1 + nb);
                hB0 = *(const float2*)(hb0 + nb + 8);
                hB1 = *(const float2*)(hb1 + nb + 8);
            }

            // ---- exp + pack P (hi/lo) for chunk kc ----
            float e00 = __expf(s0[0] + ha0.x);
            float e01 = __expf(s0[1] + ha0.y);
            float e10 = __expf(s0[2] + ha1.x);
            float e11 = __expf(s0[3] + ha1.y);
            lq0 += e00 + e01;
            lq8 += e10 + e11;
            __nv_bfloat162 p0 = __floats2bfloat162_rn(e00, e01);
            __nv_bfloat162 p1 = __floats2bfloat162_rn(e10, e11);
            __nv_bfloat162 r0v = __floats2bfloat162_rn(e00 - __bfloat162float(p0.x),
                                                       e01 - __bfloat162float(p0.y));
            __nv_bfloat162 r1v = __floats2bfloat162_rn(e10 - __bfloat162float(p1.x),
                                                       e11 - __bfloat162float(p1.y));
            float f00 = __expf(s1[0] + hc0.x);
            float f01 = __expf(s1[1] + hc0.y);
            float f10 = __expf(s1[2] + hc1.x);
            float f11 = __expf(s1[3] + hc1.y);
            lq0 += f00 + f01;
            lq8 += f10 + f11;
            __nv_bfloat162 p2 = __floats2bfloat162_rn(f00, f01);
            __nv_bfloat162 p3 = __floats2bfloat162_rn(f10, f11);
            __nv_bfloat162 r2v = __floats2bfloat162_rn(f00 - __bfloat162float(p2.x),
                                                       f01 - __bfloat162float(p2.y));
            __nv_bfloat162 r3v = __floats2bfloat162_rn(f10 - __bfloat162float(p3.x),
                                                       f11 - __bfloat162float(p3.y));
            uint32_t a0 = b2u(p0), a1 = b2u(p1), a2 = b2u(p2), a3 = b2u(p3);
            uint32_t c0r = b2u(r0v), c1r = b2u(r1v), c2r = b2u(r2v), c3r = b2u(r3v);

            // ---- QK for chunk kc+1 (independent; fills tensor pipe while
            //      exp results land) ----
            float t0[4] = {0.f, 0.f, 0.f, 0.f};
            float t1[4] = {0.f, 0.f, 0.f, 0.f};
            if (kc < 3) qk_chunk(bufc, kc + 1, t0, t1);

            // ---- AV for chunk kc ----
            #pragma unroll
            for (int m = 0; m < 8; ++m) {
                int boff = 20480 + (m * 8 + grp) * 160 + kc * 32 + tig * 8;
                uint2 vh2 = *(const uint2*)(bufc + boff);
                uint2 vl2 = *(const uint2*)(bufc + boff + 10240);
                MMA_BF16(acc[m], a0, a1, a2, a3, vh2.x, vh2.y);
                MMA_BF16(acc[m], a0, a1, a2, a3, vl2.x, vl2.y);
                MMA_BF16(acc[m], c0r, c1r, c2r, c3r, vh2.x, vh2.y);
            }

            #pragma unroll
            for (int r = 0; r < 4; ++r) { s0[r] = t0[r]; s1[r] = t1[r]; }
        }
        __syncthreads();
    }

    lq0 += __shfl_xor_sync(0xffffffffu, lq0, 1);
    lq0 += __shfl_xor_sync(0xffffffffu, lq0, 2);
    lq8 += __shfl_xor_sync(0xffffffffu, lq8, 1);
    lq8 += __shfl_xor_sync(0xffffffffu, lq8, 2);
    float i0 = 1.0f / lq0;
    float i1 = 1.0f / lq8;

    size_t yr0 = (size_t)qrow0 * 512 + h * 64;
    size_t yr1 = yr0 + (size_t)8 * 512;
    #pragma unroll
    for (int nt = 0; nt < 8; ++nt) {
        int ccp = (nt >> 1) * 16 + (nt & 1) * 2 + tig * 4;   // d-permuted
        float v00 = acc[nt][0] * i0, v01 = acc[nt][1] * i0;
        float v10 = acc[nt][2] * i1, v11 = acc[nt][3] * i1;
        __nv_bfloat162 h0 = __floats2bfloat162_rn(v00, v01);
        __nv_bfloat162 h1 = __floats2bfloat162_rn(v10, v11);
        __nv_bfloat162 l0v = __floats2bfloat162_rn(v00 - __bfloat162float(h0.x),
                                                   v01 - __bfloat162float(h0.y));
        __nv_bfloat162 l1v = __floats2bfloat162_rn(v10 - __bfloat162float(h1.x),
                                                   v11 - __bfloat162float(h1.y));
        *(uint32_t*)&yh[yr0 + ccp] = b2u(h0);
        *(uint32_t*)&yh[yr1 + ccp] = b2u(h1);
        *(uint32_t*)&yl[yr0 + ccp] = b2u(l0v);
        *(uint32_t*)&yl[yr1 + ccp] = b2u(l1v);
    }
}

// ---------------------------------------------------------------------------
// Launch.  attn_tc is launch index 5 -> ncu -s 5 profiles it next round.
// ---------------------------------------------------------------------------
extern "C" void kernel_launch(void* const* d_in, const int* in_sizes, int n_in,
                              void* d_out, int out_size) {
    (void)in_sizes; (void)n_in; (void)out_size;
    const float* x_ctx     = (const float*)d_in[0];
    const float* x_query   = (const float*)d_in[1];
    const float* pos_ctx   = (const float*)d_in[2];
    const float* pos_query = (const float*)d_in[3];
    const float* Wq = (const float*)d_in[4];
    const float* bq = (const float*)d_in[5];
    const float* Wk = (const float*)d_in[6];
    const float* bk = (const float*)d_in[7];
    const float* Wv = (const float*)d_in[8];
    const float* bv = (const float*)d_in[9];
    const float* Wo = (const float*)d_in[10];
    const float* bo = (const float*)d_in[11];
    float* out = (float*)d_out;

    float *gv, *gh;
    __nv_bfloat16 *gxqh, *gxql, *gxch, *gxcl, *gwh, *gwl;
    __nv_bfloat16 *gqh, *gql, *gkh, *gkl, *gvth, *gvtl, *gyh, *gyl;
    cudaGetSymbolAddress((void**)&gv,   g_v);
    cudaGetSymbolAddress((void**)&gh,   g_heat);
    cudaGetSymbolAddress((void**)&gxqh, g_xqh);
    cudaGetSymbolAddress((void**)&gxql, g_xql);
    cudaGetSymbolAddress((void**)&gxch, g_xch);
    cudaGetSymbolAddress((void**)&gxcl, g_xcl);
    cudaGetSymbolAddress((void**)&gwh,  g_wh);
    cudaGetSymbolAddress((void**)&gwl,  g_wl);
    cudaGetSymbolAddress((void**)&gqh,  g_qh);
    cudaGetSymbolAddress((void**)&gql,  g_ql);
    cudaGetSymbolAddress((void**)&gkh,  g_kh);
    cudaGetSymbolAddress((void**)&gkl,  g_kl);
    cudaGetSymbolAddress((void**)&gvth, g_vth);
    cudaGetSymbolAddress((void**)&gvtl, g_vtl);
    cudaGetSymbolAddress((void**)&gyh,  g_yh);
    cudaGetSymbolAddress((void**)&gyl,  g_yl);

    cudaFuncSetAttribute(attn_tc,
                         cudaFuncAttributeMaxDynamicSharedMemorySize, ATTN_SMEM_B);
    cudaFuncSetAttribute(gemm_bf16,
                         cudaFuncAttributeMaxDynamicSharedMemorySize, GEMM_SMEM_B);
    cudaFuncSetAttribute(gemm_kv,
                         cudaFuncAttributeMaxDynamicSharedMemorySize, GEMMKV_SMEM_B);

    // launch 0: all splits
    split_all<<<(B_ * NQ * CE + B_ * NC * CE) / 1024 + 4 * (CE * CE) / 1024, 256>>>(
        x_query, x_ctx, Wq, Wk, Wv, Wo, gxqh, gxql, gxch, gxcl, gwh, gwl);
    // launch 1: heat
    heat_precompute<<<dim3(NQ, B_), 256>>>(pos_ctx, pos_query, gh);
    // launch 2: Q projection (bf16 hi/lo, scaled)
    gemm_bf16<<<dim3(8, (B_ * NQ) / 128), 256, GEMM_SMEM_B>>>(
        gxqh, gxql, gwh, gwl, bq, nullptr, gqh, gql, 1, SCALE);
    // launch 3: fused K+V projections
    gemm_kv<<<dim3(8, (B_ * NC) / 128), 256, GEMMKV_SMEM_B>>>(
        gxch, gxcl, gwh + CE * CE, gwl + CE * CE,
        gwh + 2 * CE * CE, gwl + 2 * CE * CE,
        bk, bv, gkh, gkl, gv);
    // launch 4: V transpose/split
    split_v_T<<<dim3(NC / 64, H_, B_), 256>>>(gv, gvth, gvtl);
    // launch 5: attention  <-- ncu -s 5 profiles this
    attn_tc<<<dim3(NQ / 128, H_, B_), 256, ATTN_SMEM_B>>>(
        gqh, gql, gkh, gkl, gvth, gvtl, gh, gyh, gyl);
    // launch 6: O projection
    gemm_bf16<<<dim3(8, (B_ * NQ) / 128), 256, GEMM_SMEM_B>>>(
        gyh, gyl, gwh + 3 * CE * CE, gwl + 3 * CE * CE, bo, out, nullptr, nullptr, 0, 1.0f);
}

// round 11
// speedup vs baseline: 3.4153x; 1.0496x over previous
#include <cuda_runtime.h>
#include <cuda_bf16.h>
#include <cuda_fp16.h>
#include <cstdint>
#include <math.h>

// ---------------------------------------------------------------------------
// Problem constants
// ---------------------------------------------------------------------------
constexpr int B_  = 2;
constexpr int NQ  = 2048;
constexpr int NC  = 4096;
constexpr int CE  = 512;
constexpr int H_  = 8;
constexpr float SCALE  = 0.125f;
constexpr float FOURNU = 0.4f;
constexpr float EPS_   = 1e-6f;

// Pair-interleave permutation within a 16-element k-chunk (validated R7+).
__host__ __device__ constexpr int perm16(int e) {
    int lp = e >> 1, o = e & 1;
    int slot = (lp < 4) ? (lp * 2) : ((lp - 4) * 2 + 1);
    return slot * 2 + o;
}

// ---------------------------------------------------------------------------
// Scratch
// ---------------------------------------------------------------------------
__device__ __half g_heat[(size_t)B_ * NQ * NC];           // 33.5 MB (fp16)
__device__ __nv_bfloat16 g_xqh[B_ * NQ * CE];             // k-permuted
__device__ __nv_bfloat16 g_xql[B_ * NQ * CE];
__device__ __nv_bfloat16 g_xch[B_ * NC * CE];
__device__ __nv_bfloat16 g_xcl[B_ * NC * CE];
__device__ __nv_bfloat16 g_wh[4 * CE * CE];
__device__ __nv_bfloat16 g_wl[4 * CE * CE];
__device__ __nv_bfloat16 g_qh[B_ * NQ * CE];              // scaled, d-permuted
__device__ __nv_bfloat16 g_ql[B_ * NQ * CE];
__device__ __nv_bfloat16 g_kh[B_ * NC * CE];              // d-permuted
__device__ __nv_bfloat16 g_kl[B_ * NC * CE];
__device__ __nv_bfloat16 g_vth[B_ * NC * CE];             // [b][h][d][c], c-permuted
__device__ __nv_bfloat16 g_vtl[B_ * NC * CE];
__device__ __nv_bfloat16 g_yh[B_ * NQ * CE];              // attn out, d-permuted
__device__ __nv_bfloat16 g_yl[B_ * NQ * CE];

// ---------------------------------------------------------------------------
// helpers
// ---------------------------------------------------------------------------
#define MMA_BF16(d, a0, a1, a2, a3, b0, b1) \
    asm volatile("mma.sync.aligned.m16n8k16.row.col.f32.bf16.bf16.f32 " \
        "{%0,%1,%2,%3}, {%4,%5,%6,%7}, {%8,%9}, {%0,%1,%2,%3};" \
        : "+f"((d)[0]), "+f"((d)[1]), "+f"((d)[2]), "+f"((d)[3]) \
        : "r"(a0), "r"(a1), "r"(a2), "r"(a3), "r"(b0), "r"(b1))

#define CP16(dst, src) \
    asm volatile("cp.async.cg.shared.global [%0], [%1], 16;" \
                 :: "r"(dst), "l"(src))
#define CP_COMMIT() asm volatile("cp.async.commit_group;")

__device__ __forceinline__ uint32_t b2u(__nv_bfloat162 x) {
    return *reinterpret_cast<uint32_t*>(&x);
}
__device__ __forceinline__ uint32_t smem_u32(const void* p) {
    uint32_t a;
    asm("{ .reg .u64 t; cvta.to.shared.u64 t, %1; cvt.u32.u64 %0, t; }"
        : "=r"(a) : "l"(p));
    return a;
}

// ---------------------------------------------------------------------------
// Heat-kernel bias precompute -> fp16 (halves DRAM traffic; abs err <= 5e-4)
// ---------------------------------------------------------------------------
__global__ __launch_bounds__(256)
void heat_precompute(const float* __restrict__ pos_c, const float* __restrict__ pos_q,
                     __half* __restrict__ heat) {
    const int b  = blockIdx.y;
    const int qi = blockIdx.x;
    const float* pq = pos_q + (size_t)(b * NQ + qi) * 3;
    const float qx = pq[0], qy = pq[1], qt = pq[2];
    __half2* hrow = (__half2*)(heat + ((size_t)b * NQ + qi) * NC);
    for (int c2 = threadIdx.x; c2 < NC / 2; c2 += 256) {
        const float* pc = pos_c + (size_t)(b * NC + c2 * 2) * 3;
        float dx0 = qx - pc[0], dy0 = qy - pc[1], dt0 = qt - pc[2];
        float dx1 = qx - pc[3], dy1 = qy - pc[4], dt1 = qt - pc[5];
        float e0 = __expf(-__fdividef(dx0 * dx0 + dy0 * dy0,
                                      FOURNU * fabsf(dt0) + EPS_));
        float e1 = __expf(-__fdividef(dx1 * dx1 + dy1 * dy1,
                                      FOURNU * fabsf(dt1) + EPS_));
        hrow[c2] = __floats2half2_rn(e0, e1);
    }
}

// ---------------------------------------------------------------------------
// bf16 hi/lo split body (k-pair-interleaved output)
// ---------------------------------------------------------------------------
__device__ __forceinline__ void split_body(const float* __restrict__ in,
                                           __nv_bfloat16* __restrict__ oh,
                                           __nv_bfloat16* __restrict__ ol, int i) {
    float4 v = ((const float4*)in)[i];
    __nv_bfloat162 hA = __floats2bfloat162_rn(v.x, v.y);
    __nv_bfloat162 hB = __floats2bfloat162_rn(v.z, v.w);
    __nv_bfloat162 lA = __floats2bfloat162_rn(v.x - __bfloat162float(hA.x),
                                              v.y - __bfloat162float(hA.y));
    __nv_bfloat162 lB = __floats2bfloat162_rn(v.z - __bfloat162float(hB.x),
                                              v.w - __bfloat162float(hB.y));
    size_t e = (size_t)i * 4;
    size_t base = e & ~(size_t)15;
    int lp0 = (int)(e & 15) >> 1;
    int s0 = (lp0 < 4) ? lp0 * 2 : (lp0 - 4) * 2 + 1;
    int lp1 = lp0 + 1;
    int s1 = (lp1 < 4) ? lp1 * 2 : (lp1 - 4) * 2 + 1;
    *(uint32_t*)&oh[base + s0 * 2] = b2u(hA);
    *(uint32_t*)&oh[base + s1 * 2] = b2u(hB);
    *(uint32_t*)&ol[base + s0 * 2] = b2u(lA);
    *(uint32_t*)&ol[base + s1 * 2] = b2u(lB);
}

// merged x_query + x_ctx + 4xW split (single launch)
__global__ __launch_bounds__(256)
void split_all(const float* __restrict__ xq, const float* __restrict__ xc,
               const float* __restrict__ w0, const float* __restrict__ w1,
               const float* __restrict__ w2, const float* __restrict__ w3,
               __nv_bfloat16* __restrict__ oqh, __nv_bfloat16* __restrict__ oql,
               __nv_bfloat16* __restrict__ och, __nv_bfloat16* __restrict__ ocl,
               __nv_bfloat16* __restrict__ owh, __nv_bfloat16* __restrict__ owl) {
    constexpr int NBQ = (B_ * NQ * CE) / 1024;   // 2048
    constexpr int NBC = (B_ * NC * CE) / 1024;   // 4096
    constexpr int NBW = (CE * CE) / 1024;        // 256
    int bid = blockIdx.x;
    if (bid < NBQ) {
        split_body(xq, oqh, oql, bid * 256 + threadIdx.x);
    } else if (bid < NBQ + NBC) {
        split_body(xc, och, ocl, (bid - NBQ) * 256 + threadIdx.x);
    } else {
        int wb = bid - NBQ - NBC;
        int j  = wb / NBW;
        const float* in = (j == 0) ? w0 : (j == 1) ? w1 : (j == 2) ? w2 : w3;
        size_t off = (size_t)j * CE * CE;
        split_body(in, owh + off, owl + off, (wb - j * NBW) * 256 + threadIdx.x);
    }
}

// ---------------------------------------------------------------------------
// Batched Q/K/V projection GEMM (z selects target).  R8 gemm structure
// (87 regs, no fusion of accumulators — R10 lesson).  V (z=2) epilogue does
// per-head transpose + bf16 split + c-permute via smem (no fp32 round-trip).
// ---------------------------------------------------------------------------
constexpr int GEMM_SMEM_B = 73728;

__global__ __launch_bounds__(256, 2)
void proj_qkv(const __nv_bfloat16* __restrict__ xqh, const __nv_bfloat16* __restrict__ xql,
              const __nv_bfloat16* __restrict__ xch, const __nv_bfloat16* __restrict__ xcl,
              const __nv_bfloat16* __restrict__ wh,  const __nv_bfloat16* __restrict__ wl,
              const float* __restrict__ bq, const float* __restrict__ bk,
              const float* __restrict__ bv,
              __nv_bfloat16* __restrict__ qh, __nv_bfloat16* __restrict__ ql,
              __nv_bfloat16* __restrict__ kh, __nv_bfloat16* __restrict__ kl,
              __nv_bfloat16* __restrict__ vth, __nv_bfloat16* __restrict__ vtl) {
    const int z = blockIdx.z;
    const int nrows = (z == 0) ? 32 : 64;          // CTA rows of 128
    if (blockIdx.y >= nrows) return;

    const __nv_bfloat16* Ah = (z == 0) ? xqh : xch;
    const __nv_bfloat16* Al = (z == 0) ? xql : xcl;
    const __nv_bfloat16* Bh = wh + (size_t)z * CE * CE;
    const __nv_bfloat16* Bl = wl + (size_t)z * CE * CE;
    const float* bias = (z == 0) ? bq : (z == 1) ? bk : bv;

    extern __shared__ char gsm[];
    const uint32_t sb = smem_u32(gsm);

    const int tid  = threadIdx.x;
    const int lane = tid & 31;
    const int wid  = tid >> 5;
    const int grp  = lane >> 2;
    const int tig  = lane & 3;
    const int wm   = (wid >> 1) * 32;
    const int wn   = (wid & 1) * 32;
    const int rowBase = blockIdx.y * 128;
    const int colBase = blockIdx.x * 64;

    const int ar = tid >> 2;
    const int ac = tid & 3;

    auto issue = [&](uint32_t bb, int k0) {
        #pragma unroll
        for (int t = 0; t < 2; ++t) {
            int r = ar + t * 64;
            size_t src = (size_t)(rowBase + r) * 512 + k0 + ac * 8;
            uint32_t dst = bb + r * 96 + ac * 16;
            CP16(dst,         Ah + src);
            CP16(dst + 12288, Al + src);
        }
        {
            size_t src = (size_t)(colBase + ar) * 512 + k0 + ac * 8;
            uint32_t dst = bb + 24576 + ar * 96 + ac * 16;
            CP16(dst,        Bh + src);
            CP16(dst + 6144, Bl + src);
        }
        CP_COMMIT();
    };

    float acc[2][4][4];
    #pragma unroll
    for (int mt = 0; mt < 2; ++mt)
        #pragma unroll
        for (int nt = 0; nt < 4; ++nt)
            #pragma unroll
            for (int r = 0; r < 4; ++r) acc[mt][nt][r] = 0.f;

    issue(sb, 0);

    for (int c = 0; c < 16; ++c) {
        const int cur = c & 1;
        const char* bufc = gsm + cur * 36864;
        if (c < 15) issue(sb + (cur ^ 1) * 36864, (c + 1) * 32);
        if (c < 15) asm volatile("cp.async.wait_group 1;" ::: "memory");
        else        asm volatile("cp.async.wait_group 0;" ::: "memory");
        __syncthreads();

        #pragma unroll
        for (int sub = 0; sub < 2; ++sub) {
            const int kbyte = sub * 32 + tig * 8;
            uint32_t ah[2][4], al[2][4];
            #pragma unroll
            for (int mt = 0; mt < 2; ++mt) {
                int r0 = wm + mt * 16 + grp;
                uint2 h0 = *(const uint2*)(bufc + r0 * 96 + kbyte);
                uint2 h1 = *(const uint2*)(bufc + (r0 + 8) * 96 + kbyte);
                uint2 l0 = *(const uint2*)(bufc + 12288 + r0 * 96 + kbyte);
                uint2 l1 = *(const uint2*)(bufc + 12288 + (r0 + 8) * 96 + kbyte);
                ah[mt][0] = h0.x; ah[mt][1] = h1.x; ah[mt][2] = h0.y; ah[mt][3] = h1.y;
                al[mt][0] = l0.x; al[mt][1] = l1.x; al[mt][2] = l0.y; al[mt][3] = l1.y;
            }
            #pragma unroll
            for (int nt = 0; nt < 4; ++nt) {
                int n = wn + nt * 8 + grp;
                uint2 bh2 = *(const uint2*)(bufc + 24576 + n * 96 + kbyte);
                uint2 bl2 = *(const uint2*)(bufc + 30720 + n * 96 + kbyte);
                #pragma unroll
                for (int mt = 0; mt < 2; ++mt) {
                    MMA_BF16(acc[mt][nt], ah[mt][0], ah[mt][1], ah[mt][2], ah[mt][3],
                             bh2.x, bh2.y);
                    MMA_BF16(acc[mt][nt], ah[mt][0], ah[mt][1], ah[mt][2], ah[mt][3],
                             bl2.x, bl2.y);
                    MMA_BF16(acc[mt][nt], al[mt][0], al[mt][1], al[mt][2], al[mt][3],
                             bh2.x, bh2.y);
                }
            }
        }
        __syncthreads();
    }

    if (z < 2) {
        // ---- Q/K epilogue: bf16 hi/lo, k-permuted columns ----
        __nv_bfloat16* Oh = (z == 0) ? qh : kh;
        __nv_bfloat16* Ol = (z == 0) ? ql : kl;
        const float scale = (z == 0) ? SCALE : 1.0f;
        #pragma unroll
        for (int nt = 0; nt < 4; ++nt) {
            int col = colBase + wn + nt * 8 + tig * 2;
            float b0 = __ldg(&bias[col]);
            float b1 = __ldg(&bias[col + 1]);
            int colp = (col & ~15) + perm16(col & 15);
            #pragma unroll
            for (int mt = 0; mt < 2; ++mt) {
                int row = rowBase + wm + mt * 16 + grp;
                float v00 = (acc[mt][nt][0] + b0) * scale;
                float v01 = (acc[mt][nt][1] + b1) * scale;
                float v10 = (acc[mt][nt][2] + b0) * scale;
                float v11 = (acc[mt][nt][3] + b1) * scale;
                __nv_bfloat162 h0 = __floats2bfloat162_rn(v00, v01);
                __nv_bfloat162 h1 = __floats2bfloat162_rn(v10, v11);
                __nv_bfloat162 l0 = __floats2bfloat162_rn(v00 - __bfloat162float(h0.x),
                                                          v01 - __bfloat162float(h0.y));
                __nv_bfloat162 l1 = __floats2bfloat162_rn(v10 - __bfloat162float(h1.x),
                                                          v11 - __bfloat162float(h1.y));
                *(uint32_t*)&Oh[(size_t)row       * 512 + colp] = b2u(h0);
                *(uint32_t*)&Oh[(size_t)(row + 8) * 512 + colp] = b2u(h1);
                *(uint32_t*)&Ol[(size_t)row       * 512 + colp] = b2u(l0);
                *(uint32_t*)&Ol[(size_t)(row + 8) * 512 + colp] = b2u(l1);
            }
        }
    } else {
        // ---- V epilogue: transpose via smem -> [b][h][d][c] bf16 hi/lo,
        //      c-pair-interleaved.  This CTA's 64 cols = exactly head h=bx. ----
        constexpr int ST = 132;                         // padded row stride
        __nv_bfloat16* tsh = (__nv_bfloat16*)gsm;        // [64][ST]
        __nv_bfloat16* tsl = tsh + 64 * ST;
        __syncthreads();
        #pragma unroll
        for (int nt = 0; nt < 4; ++nt) {
            int dl = wn + nt * 8 + tig * 2;             // local d, 0..63
            float b0 = __ldg(&bias[colBase + dl]);
            float b1 = __ldg(&bias[colBase + dl + 1]);
            #pragma unroll
            for (int mt = 0; mt < 2; ++mt) {
                int rl = wm + mt * 16 + grp;            // local c, 0..127
                float v00 = acc[mt][nt][0] + b0, v01 = acc[mt][nt][1] + b1;
                float v10 = acc[mt][nt][2] + b0, v11 = acc[mt][nt][3] + b1;
                __nv_bfloat16 h00 = __float2bfloat16_rn(v00);
                __nv_bfloat16 h01 = __float2bfloat16_rn(v01);
                __nv_bfloat16 h10 = __float2bfloat16_rn(v10);
                __nv_bfloat16 h11 = __float2bfloat16_rn(v11);
                tsh[(dl)     * ST + rl]     = h00;
                tsh[(dl + 1) * ST + rl]     = h01;
                tsh[(dl)     * ST + rl + 8] = h10;
                tsh[(dl + 1) * ST + rl + 8] = h11;
                tsl[(dl)     * ST + rl]     = __float2bfloat16_rn(v00 - __bfloat162float(h00));
                tsl[(dl + 1) * ST + rl]     = __float2bfloat16_rn(v01 - __bfloat162float(h01));
                tsl[(dl)     * ST + rl + 8] = __float2bfloat16_rn(v10 - __bfloat162float(h10));
                tsl[(dl + 1) * ST + rl + 8] = __float2bfloat16_rn(v11 - __bfloat162float(h11));
            }
        }
        __syncthreads();
        const int bb = rowBase >> 12;                   // batch
        const int c0 = rowBase & 4095;
        const int hh = blockIdx.x;                      // head
        #pragma unroll
        for (int t = 0; t < 16; ++t) {
            int u  = tid + t * 256;                     // 0..4095 (d, c-pair)
            int d  = u >> 6;
            int cl = (u & 63) * 2;                      // even local c
            uint32_t val_h = *(uint32_t*)&tsh[d * ST + cl];
            uint32_t val_l = *(uint32_t*)&tsl[d * ST + cl];
            int cp = (cl & ~15) + perm16(cl & 15);
            size_t o = ((size_t)(bb * H_ + hh) * 64 + d) * NC + c0 + cp;
            *(uint32_t*)&vth[o] = val_h;
            *(uint32_t*)&vtl[o] = val_l;
        }
    }
}

// ---------------------------------------------------------------------------
// O-projection GEMM (fp32 out), same structure.
// ---------------------------------------------------------------------------
__global__ __launch_bounds__(256, 2)
void gemm_o(const __nv_bfloat16* __restrict__ Ah, const __nv_bfloat16* __restrict__ Al,
            const __nv_bfloat16* __restrict__ Bh, const __nv_bfloat16* __restrict__ Bl,
            const float* __restrict__ bias, float* __restrict__ Yf) {
    extern __shared__ char gsm[];
    const uint32_t sb = smem_u32(gsm);

    const int tid  = threadIdx.x;
    const int lane = tid & 31;
    const int wid  = tid >> 5;
    const int grp  = lane >> 2;
    const int tig  = lane & 3;
    const int wm   = (wid >> 1) * 32;
    const int wn   = (wid & 1) * 32;
    const int rowBase = blockIdx.y * 128;
    const int colBase = blockIdx.x * 64;

    const int ar = tid >> 2;
    const int ac = tid & 3;

    auto issue = [&](uint32_t bb, int k0) {
        #pragma unroll
        for (int t = 0; t < 2; ++t) {
            int r = ar + t * 64;
            size_t src = (size_t)(rowBase + r) * 512 + k0 + ac * 8;
            uint32_t dst = bb + r * 96 + ac * 16;
            CP16(dst,         Ah + src);
            CP16(dst + 12288, Al + src);
        }
        {
            size_t src = (size_t)(colBase + ar) * 512 + k0 + ac * 8;
            uint32_t dst = bb + 24576 + ar * 96 + ac * 16;
            CP16(dst,        Bh + src);
            CP16(dst + 6144, Bl + src);
        }
        CP_COMMIT();
    };

    float acc[2][4][4];
    #pragma unroll
    for (int mt = 0; mt < 2; ++mt)
        #pragma unroll
        for (int nt = 0; nt < 4; ++nt)
            #pragma unroll
            for (int r = 0; r < 4; ++r) acc[mt][nt][r] = 0.f;

    issue(sb, 0);

    for (int c = 0; c < 16; ++c) {
        const int cur = c & 1;
        const char* bufc = gsm + cur * 36864;
        if (c < 15) issue(sb + (cur ^ 1) * 36864, (c + 1) * 32);
        if (c < 15) asm volatile("cp.async.wait_group 1;" ::: "memory");
        else        asm volatile("cp.async.wait_group 0;" ::: "memory");
        __syncthreads();

        #pragma unroll
        for (int sub = 0; sub < 2; ++sub) {
            const int kbyte = sub * 32 + tig * 8;
            uint32_t ah[2][4], al[2][4];
            #pragma unroll
            for (int mt = 0; mt < 2; ++mt) {
                int r0 = wm + mt * 16 + grp;
                uint2 h0 = *(const uint2*)(bufc + r0 * 96 + kbyte);
                uint2 h1 = *(const uint2*)(bufc + (r0 + 8) * 96 + kbyte);
                uint2 l0 = *(const uint2*)(bufc + 12288 + r0 * 96 + kbyte);
                uint2 l1 = *(const uint2*)(bufc + 12288 + (r0 + 8) * 96 + kbyte);
                ah[mt][0] = h0.x; ah[mt][1] = h1.x; ah[mt][2] = h0.y; ah[mt][3] = h1.y;
                al[mt][0] = l0.x; al[mt][1] = l1.x; al[mt][2] = l0.y; al[mt][3] = l1.y;
            }
            #pragma unroll
            for (int nt = 0; nt < 4; ++nt) {
                int n = wn + nt * 8 + grp;
                uint2 bh2 = *(const uint2*)(bufc + 24576 + n * 96 + kbyte);
                uint2 bl2 = *(const uint2*)(bufc + 30720 + n * 96 + kbyte);
                #pragma unroll
                for (int mt = 0; mt < 2; ++mt) {
                    MMA_BF16(acc[mt][nt], ah[mt][0], ah[mt][1], ah[mt][2], ah[mt][3],
                             bh2.x, bh2.y);
                    MMA_BF16(acc[mt][nt], ah[mt][0], ah[mt][1], ah[mt][2], ah[mt][3],
                             bl2.x, bl2.y);
                    MMA_BF16(acc[mt][nt], al[mt][0], al[mt][1], al[mt][2], al[mt][3],
                             bh2.x, bh2.y);
                }
            }
        }
        __syncthreads();
    }

    #pragma unroll
    for (int nt = 0; nt < 4; ++nt) {
        int col = colBase + wn + nt * 8 + tig * 2;
        float b0 = __ldg(&bias[col]);
        float b1 = __ldg(&bias[col + 1]);
        #pragma unroll
        for (int mt = 0; mt < 2; ++mt) {
            int row = rowBase + wm + mt * 16 + grp;
            *(float2*)&Yf[(size_t)row       * 512 + col] =
                make_float2(acc[mt][nt][0] + b0, acc[mt][nt][1] + b1);
            *(float2*)&Yf[(size_t)(row + 8) * 512 + col] =
                make_float2(acc[mt][nt][2] + b0, acc[mt][nt][3] + b1);
        }
    }
}

// ---------------------------------------------------------------------------
// Tensor-core flash attention v4 (R10 pipelined structure; heat now fp16).
// ---------------------------------------------------------------------------
constexpr int ATTN_SMEM_B = 81920;

__global__ __launch_bounds__(256, 2)
void attn_tc(const __nv_bfloat16* __restrict__ qh, const __nv_bfloat16* __restrict__ ql,
             const __nv_bfloat16* __restrict__ kh, const __nv_bfloat16* __restrict__ kl,
             const __nv_bfloat16* __restrict__ vth, const __nv_bfloat16* __restrict__ vtl,
             const __half* __restrict__ heat,
             __nv_bfloat16* __restrict__ yh, __nv_bfloat16* __restrict__ yl) {
    extern __shared__ char smem[];
    const uint32_t sb = smem_u32(smem);

    const int b   = blockIdx.z;
    const int h   = blockIdx.y;
    const int q0  = blockIdx.x * 128;
    const int tid = threadIdx.x;
    const int w    = tid >> 5;
    const int lane = tid & 31;
    const int grp  = lane >> 2;
    const int tig  = lane & 3;

    const int sr  = tid >> 3;
    const int sc8 = tid & 7;

    auto issue_tile = [&](uint32_t bb, int c0) {
        #pragma unroll
        for (int j = 0; j < 2; ++j) {
            int r = sr + j * 32;
            size_t ksrc = (size_t)(b * NC + c0 + r) * 512 + h * 64 + sc8 * 8;
            size_t vsrc = ((size_t)(b * H_ + h) * 64 + r) * NC + c0 + sc8 * 8;
            uint32_t d0 = bb + r * 160 + sc8 * 16;
            CP16(d0,         kh  + ksrc);
            CP16(d0 + 10240, kl  + ksrc);
            CP16(d0 + 20480, vth + vsrc);
            CP16(d0 + 30720, vtl + vsrc);
        }
        CP_COMMIT();
    };

    const int qrow0 = b * NQ + q0 + w * 16 + grp;
    uint32_t qfh[4][4], qfl[4][4];
    #pragma unroll
    for (int ks = 0; ks < 4; ++ks) {
        size_t e0 = (size_t)qrow0 * 512 + h * 64 + ks * 16 + tig * 4;
        size_t e1 = e0 + (size_t)8 * 512;
        uint2 h0 = *(const uint2*)(qh + e0);
        uint2 h1 = *(const uint2*)(qh + e1);
        uint2 l0v = *(const uint2*)(ql + e0);
        uint2 l1v = *(const uint2*)(ql + e1);
        qfh[ks][0] = h0.x; qfh[ks][1] = h1.x; qfh[ks][2] = h0.y; qfh[ks][3] = h1.y;
        qfl[ks][0] = l0v.x; qfl[ks][1] = l1v.x; qfl[ks][2] = l0v.y; qfl[ks][3] = l1v.y;
    }

    float acc[8][4];
    #pragma unroll
    for (int m = 0; m < 8; ++m)
        #pragma unroll
        for (int r = 0; r < 4; ++r) acc[m][r] = 0.f;
    float lq0 = 0.f, lq8 = 0.f;

    const __half* hb0 = heat + (size_t)qrow0 * NC;
    const __half* hb1 = hb0 + (size_t)8 * NC;

    auto qk_chunk = [&](const char* bufc, int kc, float* s0, float* s1) {
        #pragma unroll
        for (int ks = 0; ks < 4; ++ks) {
            int r0 = (kc * 16 + grp) * 160 + ks * 32 + tig * 8;
            int r1 = r0 + 8 * 160;
            uint2 k0h = *(const uint2*)(bufc + r0);
            uint2 k0l = *(const uint2*)(bufc + 10240 + r0);
            uint2 k1h = *(const uint2*)(bufc + r1);
            uint2 k1l = *(const uint2*)(bufc + 10240 + r1);
            MMA_BF16(s0, qfh[ks][0], qfh[ks][1], qfh[ks][2], qfh[ks][3], k0h.x, k0h.y);
            MMA_BF16(s0, qfh[ks][0], qfh[ks][1], qfh[ks][2], qfh[ks][3], k0l.x, k0l.y);
            MMA_BF16(s0, qfl[ks][0], qfl[ks][1], qfl[ks][2], qfl[ks][3], k0h.x, k0h.y);
            MMA_BF16(s1, qfh[ks][0], qfh[ks][1], qfh[ks][2], qfh[ks][3], k1h.x, k1h.y);
            MMA_BF16(s1, qfh[ks][0], qfh[ks][1], qfh[ks][2], qfh[ks][3], k1l.x, k1l.y);
            MMA_BF16(s1, qfl[ks][0], qfl[ks][1], qfl[ks][2], qfl[ks][3], k1h.x, k1h.y);
        }
    };

    issue_tile(sb, 0);

    for (int it = 0; it < 64; ++it) {
        const int cur = it & 1;
        const char* bufc = smem + cur * 40960;
        if (it < 63) issue_tile(sb + (cur ^ 1) * 40960, (it + 1) * 64);
        if (it < 63) asm volatile("cp.async.wait_group 1;" ::: "memory");
        else         asm volatile("cp.async.wait_group 0;" ::: "memory");
        __syncthreads();

        const int c0 = it * 64;
        float2 hA0 = __half22float2(*(const __half2*)(hb0 + c0 + tig * 2));
        float2 hA1 = __half22float2(*(const __half2*)(hb1 + c0 + tig * 2));
        float2 hB0 = __half22float2(*(const __half2*)(hb0 + c0 + 8 + tig * 2));
        float2 hB1 = __half22float2(*(const __half2*)(hb1 + c0 + 8 + tig * 2));

        float s0[4] = {0.f, 0.f, 0.f, 0.f};
        float s1[4] = {0.f, 0.f, 0.f, 0.f};
        qk_chunk(bufc, 0, s0, s1);

        #pragma unroll
        for (int kc = 0; kc < 4; ++kc) {
            float2 ha0 = hA0, ha1 = hA1, hc0 = hB0, hc1 = hB1;
            if (kc < 3) {
                int nb = c0 + (kc + 1) * 16 + tig * 2;
                hA0 = __half22float2(*(const __half2*)(hb0 + nb));
                hA1 = __half22float2(*(const __half2*)(hb1 + nb));
                hB0 = __half22float2(*(const __half2*)(hb0 + nb + 8));
                hB1 = __half22float2(*(const __half2*)(hb1 + nb + 8));
            }

            float e00 = __expf(s0[0] + ha0.x);
            float e01 = __expf(s0[1] + ha0.y);
            float e10 = __expf(s0[2] + ha1.x);
            float e11 = __expf(s0[3] + ha1.y);
            lq0 += e00 + e01;
            lq8 += e10 + e11;
            __nv_bfloat162 p0 = __floats2bfloat162_rn(e00, e01);
            __nv_bfloat162 p1 = __floats2bfloat162_rn(e10, e11);
            __nv_bfloat162 r0v = __floats2bfloat162_rn(e00 - __bfloat162float(p0.x),
                                                       e01 - __bfloat162float(p0.y));
            __nv_bfloat162 r1v = __floats2bfloat162_rn(e10 - __bfloat162float(p1.x),
                                                       e11 - __bfloat162float(p1.y));
            float f00 = __expf(s1[0] + hc0.x);
            float f01 = __expf(s1[1] + hc0.y);
            float f10 = __expf(s1[2] + hc1.x);
            float f11 = __expf(s1[3] + hc1.y);
            lq0 += f00 + f01;
            lq8 += f10 + f11;
            __nv_bfloat162 p2 = __floats2bfloat162_rn(f00, f01);
            __nv_bfloat162 p3 = __floats2bfloat162_rn(f10, f11);
            __nv_bfloat162 r2v = __floats2bfloat162_rn(f00 - __bfloat162float(p2.x),
                                                       f01 - __bfloat162float(p2.y));
            __nv_bfloat162 r3v = __floats2bfloat162_rn(f10 - __bfloat162float(p3.x),
                                                       f11 - __bfloat162float(p3.y));
            uint32_t a0 = b2u(p0), a1 = b2u(p1), a2 = b2u(p2), a3 = b2u(p3);
            uint32_t c0r = b2u(r0v), c1r = b2u(r1v), c2r = b2u(r2v), c3r = b2u(r3v);

            float t0[4] = {0.f, 0.f, 0.f, 0.f};
            float t1[4] = {0.f, 0.f, 0.f, 0.f};
            if (kc < 3) qk_chunk(bufc, kc + 1, t0, t1);

            #pragma unroll
            for (int m = 0; m < 8; ++m) {
                int boff = 20480 + (m * 8 + grp) * 160 + kc * 32 + tig * 8;
                uint2 vh2 = *(const uint2*)(bufc + boff);
                uint2 vl2 = *(const uint2*)(bufc + boff + 10240);
                MMA_BF16(acc[m], a0, a1, a2, a3, vh2.x, vh2.y);
                MMA_BF16(acc[m], a0, a1, a2, a3, vl2.x, vl2.y);
                MMA_BF16(acc[m], c0r, c1r, c2r, c3r, vh2.x, vh2.y);
            }

            #pragma unroll
            for (int r = 0; r < 4; ++r) { s0[r] = t0[r]; s1[r] = t1[r]; }
        }
        __syncthreads();
    }

    lq0 += __shfl_xor_sync(0xffffffffu, lq0, 1);
    lq0 += __shfl_xor_sync(0xffffffffu, lq0, 2);
    lq8 += __shfl_xor_sync(0xffffffffu, lq8, 1);
    lq8 += __shfl_xor_sync(0xffffffffu, lq8, 2);
    float i0 = 1.0f / lq0;
    float i1 = 1.0f / lq8;

    size_t yr0 = (size_t)qrow0 * 512 + h * 64;
    size_t yr1 = yr0 + (size_t)8 * 512;
    #pragma unroll
    for (int nt = 0; nt < 8; ++nt) {
        int ccp = (nt >> 1) * 16 + (nt & 1) * 2 + tig * 4;   // d-permuted
        float v00 = acc[nt][0] * i0, v01 = acc[nt][1] * i0;
        float v10 = acc[nt][2] * i1, v11 = acc[nt][3] * i1;
        __nv_bfloat162 h0 = __floats2bfloat162_rn(v00, v01);
        __nv_bfloat162 h1 = __floats2bfloat162_rn(v10, v11);
        __nv_bfloat162 l0v = __floats2bfloat162_rn(v00 - __bfloat162float(h0.x),
                                                   v01 - __bfloat162float(h0.y));
        __nv_bfloat162 l1v = __floats2bfloat162_rn(v10 - __bfloat162float(h1.x),
                                                   v11 - __bfloat162float(h1.y));
        *(uint32_t*)&yh[yr0 + ccp] = b2u(h0);
        *(uint32_t*)&yh[yr1 + ccp] = b2u(h1);
        *(uint32_t*)&yl[yr0 + ccp] = b2u(l0v);
        *(uint32_t*)&yl[yr1 + ccp] = b2u(l1v);
    }
}

// ---------------------------------------------------------------------------
// Launch.  attn_tc is our launch index 3 -> ncu profiles it next round.
// ---------------------------------------------------------------------------
extern "C" void kernel_launch(void* const* d_in, const int* in_sizes, int n_in,
                              void* d_out, int out_size) {
    (void)in_sizes; (void)n_in; (void)out_size;
    const float* x_ctx     = (const float*)d_in[0];
    const float* x_query   = (const float*)d_in[1];
    const float* pos_ctx   = (const float*)d_in[2];
    const float* pos_query = (const float*)d_in[3];
    const float* Wq = (const float*)d_in[4];
    const float* bq = (const float*)d_in[5];
    const float* Wk = (const float*)d_in[6];
    const float* bk = (const float*)d_in[7];
    const float* Wv = (const float*)d_in[8];
    const float* bv = (const float*)d_in[9];
    const float* Wo = (const float*)d_in[10];
    const float* bo = (const float*)d_in[11];
    float* out = (float*)d_out;

    __half* gh;
    __nv_bfloat16 *gxqh, *gxql, *gxch, *gxcl, *gwh, *gwl;
    __nv_bfloat16 *gqh, *gql, *gkh, *gkl, *gvth, *gvtl, *gyh, *gyl;
    cudaGetSymbolAddress((void**)&gh,   g_heat);
    cudaGetSymbolAddress((void**)&gxqh, g_xqh);
    cudaGetSymbolAddress((void**)&gxql, g_xql);
    cudaGetSymbolAddress((void**)&gxch, g_xch);
    cudaGetSymbolAddress((void**)&gxcl, g_xcl);
    cudaGetSymbolAddress((void**)&gwh,  g_wh);
    cudaGetSymbolAddress((void**)&gwl,  g_wl);
    cudaGetSymbolAddress((void**)&gqh,  g_qh);
    cudaGetSymbolAddress((void**)&gql,  g_ql);
    cudaGetSymbolAddress((void**)&gkh,  g_kh);
    cudaGetSymbolAddress((void**)&gkl,  g_kl);
    cudaGetSymbolAddress((void**)&gvth, g_vth);
    cudaGetSymbolAddress((void**)&gvtl, g_vtl);
    cudaGetSymbolAddress((void**)&gyh,  g_yh);
    cudaGetSymbolAddress((void**)&gyl,  g_yl);

    cudaFuncSetAttribute(attn_tc,
                         cudaFuncAttributeMaxDynamicSharedMemorySize, ATTN_SMEM_B);
    cudaFuncSetAttribute(proj_qkv,
                         cudaFuncAttributeMaxDynamicSharedMemorySize, GEMM_SMEM_B);
    cudaFuncSetAttribute(gemm_o,
                         cudaFuncAttributeMaxDynamicSharedMemorySize, GEMM_SMEM_B);

    // launch 0: all splits
    split_all<<<(B_ * NQ * CE + B_ * NC * CE) / 1024 + 4 * (CE * CE) / 1024, 256>>>(
        x_query, x_ctx, Wq, Wk, Wv, Wo, gxqh, gxql, gxch, gxcl, gwh, gwl);
    // launch 1: heat (fp16)
    heat_precompute<<<dim3(NQ, B_), 256>>>(pos_ctx, pos_query, gh);
    // launch 2: batched Q/K/V projections (V writes transposed+split directly)
    proj_qkv<<<dim3(8, 64, 3), 256, GEMM_SMEM_B>>>(
        gxqh, gxql, gxch, gxcl, gwh, gwl, bq, bk, bv,
        gqh, gql, gkh, gkl, gvth, gvtl);
    // launch 3: attention  <-- ncu profiles this next round
    attn_tc<<<dim3(NQ / 128, H_, B_), 256, ATTN_SMEM_B>>>(
        gqh, gql, gkh, gkl, gvth, gvtl, gh, gyh, gyl);
    // launch 4: O projection
    gemm_o<<<dim3(8, (B_ * NQ) / 128), 256, GEMM_SMEM_B>>>(
        gyh, gyl, gwh + 3 * CE * CE, gwl + 3 * CE * CE, bo, out);
}